// round 1
// baseline (speedup 1.0000x reference)
#include <cuda_runtime.h>

#define M_TOT 65536      // B*N rows
#define DIMW  512        // DIM == INNER
#define WIN   128
#define NHEAD 8
#define DHEAD 64

// ---------------- scratch (__device__ globals; no allocation allowed) -------
__device__ float g_WqT[DIMW * DIMW];
__device__ float g_WkT[DIMW * DIMW];
__device__ float g_WvT[DIMW * DIMW];
__device__ float g_WoT[DIMW * DIMW];
__device__ float g_q[(size_t)M_TOT * DIMW];
__device__ float g_k[(size_t)M_TOT * DIMW];
__device__ float g_v[(size_t)M_TOT * DIMW];
__device__ float g_o[(size_t)M_TOT * DIMW];

// ---------------- weight transpose: WT[d][o] = W[o][d] ----------------------
__global__ void transpose_w(const float* __restrict__ Wq, const float* __restrict__ Wk,
                            const float* __restrict__ Wv, const float* __restrict__ Wo)
{
    __shared__ float t[32][33];
    const float* src; float* dst;
    switch (blockIdx.z) {
        case 0:  src = Wq; dst = g_WqT; break;
        case 1:  src = Wk; dst = g_WkT; break;
        case 2:  src = Wv; dst = g_WvT; break;
        default: src = Wo; dst = g_WoT; break;
    }
    int x  = blockIdx.x * 32 + threadIdx.x;
    int y0 = blockIdx.y * 32;
    #pragma unroll
    for (int j = threadIdx.y; j < 32; j += 8)
        t[j][threadIdx.x] = src[(size_t)(y0 + j) * DIMW + x];
    __syncthreads();
    int x2 = blockIdx.y * 32 + threadIdx.x;
    int y2 = blockIdx.x * 32;
    #pragma unroll
    for (int j = threadIdx.y; j < 32; j += 8)
        dst[(size_t)(y2 + j) * DIMW + x2] = t[threadIdx.x][j];
}

// ---------------- 128x128x8 register-blocked SGEMM body ---------------------
// C[m][n] = sum_k A[m][k] * B[k][n]   (M=65536, N=K=512)
// epi: C += Yadd[m][n] + bias[n]
__device__ __forceinline__ void sgemm_body(
    const float* __restrict__ A, const float* __restrict__ B, float* __restrict__ C,
    const float* __restrict__ Yadd, const float* __restrict__ bias, bool epi)
{
    __shared__ float As[8][128];
    __shared__ float Bs[8][128];
    const int tid  = threadIdx.x;
    const int tx   = tid & 15;
    const int ty   = tid >> 4;
    const int am   = tid >> 1;              // 0..127 A-tile row
    const int acol = (tid & 1) * 4;         // 0 or 4
    const int br   = tid >> 5;              // 0..7   B-tile k-row
    const int bc   = (tid & 31) * 4;        // 0..124
    const size_t arow = (size_t)blockIdx.y * 128 + am;
    const int    ncol = blockIdx.x * 128;

    float acc[8][8];
    #pragma unroll
    for (int i = 0; i < 8; ++i)
        #pragma unroll
        for (int j = 0; j < 8; ++j) acc[i][j] = 0.f;

    for (int k0 = 0; k0 < DIMW; k0 += 8) {
        float4 a4 = *(const float4*)(A + arow * DIMW + k0 + acol);
        As[acol + 0][am] = a4.x;
        As[acol + 1][am] = a4.y;
        As[acol + 2][am] = a4.z;
        As[acol + 3][am] = a4.w;
        *(float4*)(&Bs[br][bc]) =
            *(const float4*)(B + (size_t)(k0 + br) * DIMW + ncol + bc);
        __syncthreads();
        #pragma unroll
        for (int kk = 0; kk < 8; ++kk) {
            float ra[8], rb[8];
            *(float4*)&ra[0] = *(const float4*)&As[kk][ty * 4];
            *(float4*)&ra[4] = *(const float4*)&As[kk][ty * 4 + 64];
            *(float4*)&rb[0] = *(const float4*)&Bs[kk][tx * 4];
            *(float4*)&rb[4] = *(const float4*)&Bs[kk][tx * 4 + 64];
            #pragma unroll
            for (int i = 0; i < 8; ++i)
                #pragma unroll
                for (int j = 0; j < 8; ++j)
                    acc[i][j] += ra[i] * rb[j];
        }
        __syncthreads();
    }

    #pragma unroll
    for (int ih = 0; ih < 2; ++ih)
        #pragma unroll
        for (int i = 0; i < 4; ++i) {
            size_t r = (size_t)blockIdx.y * 128 + ty * 4 + ih * 64 + i;
            #pragma unroll
            for (int jh = 0; jh < 2; ++jh) {
                int c = ncol + tx * 4 + jh * 64;
                float4 o;
                o.x = acc[ih * 4 + i][jh * 4 + 0];
                o.y = acc[ih * 4 + i][jh * 4 + 1];
                o.z = acc[ih * 4 + i][jh * 4 + 2];
                o.w = acc[ih * 4 + i][jh * 4 + 3];
                if (epi) {
                    float4 yv = *(const float4*)(Yadd + r * DIMW + c);
                    float4 bv = *(const float4*)(bias + c);
                    o.x += yv.x + bv.x; o.y += yv.y + bv.y;
                    o.z += yv.z + bv.z; o.w += yv.w + bv.w;
                }
                *(float4*)(C + r * DIMW + c) = o;
            }
        }
}

__global__ __launch_bounds__(256) void qkv_gemm(const float* __restrict__ x,
                                                const float* __restrict__ y)
{
    const float* A; const float* B; float* C;
    if (blockIdx.z == 0)      { A = y; B = g_WqT; C = g_q; }
    else if (blockIdx.z == 1) { A = x; B = g_WkT; C = g_k; }
    else                      { A = x; B = g_WvT; C = g_v; }
    sgemm_body(A, B, C, nullptr, nullptr, false);
}

__global__ __launch_bounds__(256) void out_gemm(const float* __restrict__ y,
                                                const float* __restrict__ bout,
                                                float* __restrict__ ynew)
{
    sgemm_body(g_o, g_WoT, ynew, y, bout, true);
}

// ---------------- LayerNorm over rows of 512 (in place on g_q / g_k) --------
__global__ __launch_bounds__(256) void ln_kernel(const float* __restrict__ gq,
                                                 const float* __restrict__ bq,
                                                 const float* __restrict__ gk,
                                                 const float* __restrict__ bk)
{
    float*       buf = (blockIdx.y == 0) ? g_q : g_k;
    const float* g   = (blockIdx.y == 0) ? gq  : gk;
    const float* b   = (blockIdx.y == 0) ? bq  : bk;
    const size_t row = blockIdx.x;
    const int tid = threadIdx.x;

    float2 v = *(float2*)(buf + row * DIMW + tid * 2);
    float s  = v.x + v.y;
    float sq = v.x * v.x + v.y * v.y;
    #pragma unroll
    for (int o = 16; o > 0; o >>= 1) {
        s  += __shfl_xor_sync(0xffffffffu, s,  o);
        sq += __shfl_xor_sync(0xffffffffu, sq, o);
    }
    __shared__ float ss[8], ssq[8];
    if ((tid & 31) == 0) { ss[tid >> 5] = s; ssq[tid >> 5] = sq; }
    __syncthreads();
    s = 0.f; sq = 0.f;
    #pragma unroll
    for (int i = 0; i < 8; ++i) { s += ss[i]; sq += ssq[i]; }

    float mean = s * (1.f / 512.f);
    float var  = sq * (1.f / 512.f) - mean * mean;
    float rstd = rsqrtf(var + 1e-5f);
    int c = tid * 2;
    float2 o;
    o.x = (v.x - mean) * rstd * g[c]     + b[c];
    o.y = (v.y - mean) * rstd * g[c + 1] + b[c + 1];
    *(float2*)(buf + row * DIMW + c) = o;
}

// ---------------- windowed attention: one block per (window, head) ----------
#define QS  65    // q/k/v smem row stride (conflict-free for our mappings)
#define ATS 136   // attn smem row stride (rg*8 + cg -> distinct banks)
#define ATTN_SMEM ((3 * 128 * QS + 128 * ATS) * 4)

__global__ __launch_bounds__(256) void attn_kernel(float* __restrict__ attn_out)
{
    extern __shared__ float sm[];
    float* qs  = sm;
    float* ks  = qs + 128 * QS;
    float* vs  = ks + 128 * QS;
    float* as_ = vs + 128 * QS;

    const int tid = threadIdx.x;
    const int bwh = blockIdx.x;           // bw*8 + h
    const int bw  = bwh >> 3;
    const int h   = bwh & 7;
    const size_t rowbase = (size_t)bw * WIN;
    const int coloff = h * DHEAD;

    // load q, k, v tiles [128, 64]
    #pragma unroll
    for (int it = 0; it < 8; ++it) {
        int idx = tid + it * 256;         // 0..2047
        int i   = idx >> 4;
        int d4  = (idx & 15) << 2;
        size_t goff = (rowbase + i) * DIMW + coloff + d4;
        float4 qv = *(const float4*)(g_q + goff);
        float4 kv = *(const float4*)(g_k + goff);
        float4 vv = *(const float4*)(g_v + goff);
        float* qd = qs + i * QS + d4;
        qd[0] = qv.x; qd[1] = qv.y; qd[2] = qv.z; qd[3] = qv.w;
        float* kd = ks + i * QS + d4;
        kd[0] = kv.x; kd[1] = kv.y; kd[2] = kv.z; kd[3] = kv.w;
        float* vd = vs + i * QS + d4;
        vd[0] = vv.x; vd[1] = vv.y; vd[2] = vv.z; vd[3] = vv.w;
    }
    __syncthreads();

    const int rg = tid >> 3;   // 0..31 : rows  i = rg + 32*r
    const int cg = tid & 7;    // 0..7  : cols  j = cg + 8*c

    // dots = q @ k^T  (4x16 micro-tile per thread, scattered mapping)
    float acc[4][16];
    #pragma unroll
    for (int r = 0; r < 4; ++r)
        #pragma unroll
        for (int c = 0; c < 16; ++c) acc[r][c] = 0.f;

    #pragma unroll 4
    for (int d = 0; d < 64; ++d) {
        float qv[4], kv[16];
        #pragma unroll
        for (int r = 0; r < 4; ++r)  qv[r] = qs[(rg + 32 * r) * QS + d];
        #pragma unroll
        for (int c = 0; c < 16; ++c) kv[c] = ks[(cg + 8 * c) * QS + d];
        #pragma unroll
        for (int r = 0; r < 4; ++r)
            #pragma unroll
            for (int c = 0; c < 16; ++c)
                acc[r][c] += qv[r] * kv[c];
    }

    // softmax per row (row spread over the 8 contiguous lanes of a cg-group)
    const size_t abase = (size_t)bwh * WIN * WIN;
    #pragma unroll
    for (int r = 0; r < 4; ++r) {
        float mx = -1e30f;
        #pragma unroll
        for (int c = 0; c < 16; ++c) {
            acc[r][c] *= 0.125f;                       // DHEAD^-0.5
            mx = fmaxf(mx, acc[r][c]);
        }
        #pragma unroll
        for (int o = 1; o < 8; o <<= 1)
            mx = fmaxf(mx, __shfl_xor_sync(0xffffffffu, mx, o, 8));
        float sum = 0.f;
        #pragma unroll
        for (int c = 0; c < 16; ++c) {
            acc[r][c] = __expf(acc[r][c] - mx);
            sum += acc[r][c];
        }
        #pragma unroll
        for (int o = 1; o < 8; o <<= 1)
            sum += __shfl_xor_sync(0xffffffffu, sum, o, 8);
        float inv = 1.0f / sum;
        int i = rg + 32 * r;
        #pragma unroll
        for (int c = 0; c < 16; ++c) {
            float p = acc[r][c] * inv;
            int j = cg + 8 * c;
            attn_out[abase + (size_t)i * WIN + j] = p;   // attn output
            as_[i * ATS + j] = p;
        }
    }
    __syncthreads();

    // out = attn @ v  (4x8 micro-tile per thread)
    float oacc[4][8];
    #pragma unroll
    for (int r = 0; r < 4; ++r)
        #pragma unroll
        for (int c = 0; c < 8; ++c) oacc[r][c] = 0.f;

    #pragma unroll 2
    for (int j = 0; j < 128; ++j) {
        float av[4], vv[8];
        #pragma unroll
        for (int r = 0; r < 4; ++r) av[r] = as_[(rg + 32 * r) * ATS + j];
        #pragma unroll
        for (int c = 0; c < 8; ++c) vv[c] = vs[j * QS + cg + 8 * c];
        #pragma unroll
        for (int r = 0; r < 4; ++r)
            #pragma unroll
            for (int c = 0; c < 8; ++c)
                oacc[r][c] += av[r] * vv[c];
    }

    #pragma unroll
    for (int r = 0; r < 4; ++r) {
        int i = rg + 32 * r;
        size_t go = (rowbase + i) * DIMW + coloff;
        #pragma unroll
        for (int c = 0; c < 8; ++c)
            g_o[go + cg + 8 * c] = oacc[r][c];
    }
}

// ---------------- launcher ---------------------------------------------------
extern "C" void kernel_launch(void* const* d_in, const int* in_sizes, int n_in,
                              void* d_out, int out_size)
{
    const float* x  = (const float*)d_in[0];
    const float* y  = (const float*)d_in[1];
    const float* Wq = (const float*)d_in[2];
    const float* gq = (const float*)d_in[3];
    const float* bq = (const float*)d_in[4];
    const float* Wk = (const float*)d_in[5];
    const float* gk = (const float*)d_in[6];
    const float* bk = (const float*)d_in[7];
    const float* Wv = (const float*)d_in[8];
    const float* Wo = (const float*)d_in[9];
    const float* bo = (const float*)d_in[10];

    float* ynew = (float*)d_out;
    float* attn = ynew + (size_t)M_TOT * DIMW;

    cudaFuncSetAttribute(attn_kernel,
                         cudaFuncAttributeMaxDynamicSharedMemorySize, ATTN_SMEM);

    transpose_w<<<dim3(16, 16, 4), dim3(32, 8)>>>(Wq, Wk, Wv, Wo);
    qkv_gemm<<<dim3(4, 512, 3), 256>>>(x, y);
    ln_kernel<<<dim3(65536, 2), 256>>>(gq, bq, gk, bk);
    attn_kernel<<<4096, 256, ATTN_SMEM>>>(attn);
    out_gemm<<<dim3(4, 512), 256>>>(y, bo, ynew);
}

// round 5
// speedup vs baseline: 1.8904x; 1.8904x over previous
#include <cuda_runtime.h>
#include <cuda_bf16.h>
#include <cstdint>

#define M_TOT 65536      // B*N rows
#define DIMW  512        // DIM == INNER
#define WIN   128
#define NHEAD 8
#define DHEAD 64

// GEMM tiling (warp-MMA, mma.sync m16n8k16 bf16)
#define BM 128
#define BN 128
#define BK 64                        // bf16 elems per k-chunk (128 bytes/row)
#define NKC (DIMW / BK)              // 8 chunks
#define TILE_B (BM * 128)            // one operand tile: 16384 bytes
#define STAGE_B (4 * TILE_B)         // Ah, Al, Bh, Bl : 64 KB
#define NSTAGE 3
#define GEMM_SMEM (NSTAGE * STAGE_B) // 192 KB

// ---------------- scratch (__device__ globals; no allocation allowed) -------
__device__ float g_q[(size_t)M_TOT * DIMW];
__device__ float g_k[(size_t)M_TOT * DIMW];
__device__ float g_v[(size_t)M_TOT * DIMW];
__device__ float g_o[(size_t)M_TOT * DIMW];

__device__ __nv_bfloat16 g_xh[(size_t)M_TOT * DIMW];
__device__ __nv_bfloat16 g_xl[(size_t)M_TOT * DIMW];
__device__ __nv_bfloat16 g_yh[(size_t)M_TOT * DIMW];
__device__ __nv_bfloat16 g_yl[(size_t)M_TOT * DIMW];
__device__ __nv_bfloat16 g_oh[(size_t)M_TOT * DIMW];
__device__ __nv_bfloat16 g_ol[(size_t)M_TOT * DIMW];

__device__ __nv_bfloat16 g_Wqh[DIMW * DIMW];
__device__ __nv_bfloat16 g_Wql[DIMW * DIMW];
__device__ __nv_bfloat16 g_Wkh[DIMW * DIMW];
__device__ __nv_bfloat16 g_Wkl[DIMW * DIMW];
__device__ __nv_bfloat16 g_Wvh[DIMW * DIMW];
__device__ __nv_bfloat16 g_Wvl[DIMW * DIMW];
__device__ __nv_bfloat16 g_Woh[DIMW * DIMW];
__device__ __nv_bfloat16 g_Wol[DIMW * DIMW];

// ---------------- small asm helpers ------------------------------------------
__device__ __forceinline__ uint32_t smem_u32(const void* p) {
    uint32_t a;
    asm("{ .reg .u64 t; cvta.to.shared.u64 t, %1; cvt.u32.u64 %0, t; }"
        : "=r"(a) : "l"(p));
    return a;
}
__device__ __forceinline__ void cp16(uint32_t dst, const void* src) {
    asm volatile("cp.async.cg.shared.global [%0], [%1], 16;"
                 :: "r"(dst), "l"(src) : "memory");
}
__device__ __forceinline__ void cp_commit() {
    asm volatile("cp.async.commit_group;" ::: "memory");
}
template <int N>
__device__ __forceinline__ void cp_wait() {
    asm volatile("cp.async.wait_group %0;" :: "n"(N) : "memory");
}
__device__ __forceinline__ void ldsm4(uint32_t* r, uint32_t addr) {
    asm volatile("ldmatrix.sync.aligned.m8n8.x4.shared.b16 {%0,%1,%2,%3}, [%4];"
                 : "=r"(r[0]), "=r"(r[1]), "=r"(r[2]), "=r"(r[3]) : "r"(addr));
}
__device__ __forceinline__ void mma16816(float* d, const uint32_t* a,
                                         uint32_t b0, uint32_t b1) {
    asm volatile(
        "mma.sync.aligned.m16n8k16.row.col.f32.bf16.bf16.f32 "
        "{%0,%1,%2,%3}, {%4,%5,%6,%7}, {%8,%9}, {%0,%1,%2,%3};"
        : "+f"(d[0]), "+f"(d[1]), "+f"(d[2]), "+f"(d[3])
        : "r"(a[0]), "r"(a[1]), "r"(a[2]), "r"(a[3]), "r"(b0), "r"(b1));
}

// ---------------- fp32 -> bf16 hi/lo split ----------------------------------
__global__ __launch_bounds__(256) void split_kernel(const float4* __restrict__ in,
                                                    uint2* __restrict__ hi,
                                                    uint2* __restrict__ lo, int n4)
{
    int i = blockIdx.x * blockDim.x + threadIdx.x;
    if (i >= n4) return;
    float4 v = in[i];
    __nv_bfloat16 h0 = __float2bfloat16(v.x);
    __nv_bfloat16 h1 = __float2bfloat16(v.y);
    __nv_bfloat16 h2 = __float2bfloat16(v.z);
    __nv_bfloat16 h3 = __float2bfloat16(v.w);
    __nv_bfloat16 l0 = __float2bfloat16(v.x - __bfloat162float(h0));
    __nv_bfloat16 l1 = __float2bfloat16(v.y - __bfloat162float(h1));
    __nv_bfloat16 l2 = __float2bfloat16(v.z - __bfloat162float(h2));
    __nv_bfloat16 l3 = __float2bfloat16(v.w - __bfloat162float(h3));
    uint2 H, L;
    H.x = (uint32_t)__bfloat16_as_ushort(h0) | ((uint32_t)__bfloat16_as_ushort(h1) << 16);
    H.y = (uint32_t)__bfloat16_as_ushort(h2) | ((uint32_t)__bfloat16_as_ushort(h3) << 16);
    L.x = (uint32_t)__bfloat16_as_ushort(l0) | ((uint32_t)__bfloat16_as_ushort(l1) << 16);
    L.y = (uint32_t)__bfloat16_as_ushort(l2) | ((uint32_t)__bfloat16_as_ushort(l3) << 16);
    hi[i] = H;
    lo[i] = L;
}

// ---------------- bf16x3 warp-MMA GEMM ---------------------------------------
// C[M,512] = A[M,512] @ W^T.  W[out,in] row-major is exactly the col-major B
// operand (K contiguous per n row).  3 products: AhBh + AhBl + AlBh, fp32 acc.
__device__ __forceinline__ void load_stage(uint32_t sbase,
    const __nv_bfloat16* __restrict__ Ah, const __nv_bfloat16* __restrict__ Al,
    const __nv_bfloat16* __restrict__ Bh, const __nv_bfloat16* __restrict__ Bl,
    int m0, int n0, int kc, int tid)
{
    const int kcol = kc * BK;
    #pragma unroll
    for (int i = 0; i < 4; ++i) {
        int idx = tid + i * 256;          // 0..1023
        int row = idx >> 3;
        int ch  = idx & 7;
        uint32_t soff = row * 128 + (((ch ^ (row & 7)) << 4));
        size_t ga = (size_t)(m0 + row) * DIMW + kcol + ch * 8;
        size_t gb = (size_t)(n0 + row) * DIMW + kcol + ch * 8;
        cp16(sbase + soff,              Ah + ga);
        cp16(sbase + TILE_B + soff,     Al + ga);
        cp16(sbase + 2 * TILE_B + soff, Bh + gb);
        cp16(sbase + 3 * TILE_B + soff, Bl + gb);
    }
    cp_commit();
}

__device__ __forceinline__ void gemm_body(
    const __nv_bfloat16* __restrict__ Ah, const __nv_bfloat16* __restrict__ Al,
    const __nv_bfloat16* __restrict__ Bh, const __nv_bfloat16* __restrict__ Bl,
    float* __restrict__ C, const float* __restrict__ Yadd,
    const float* __restrict__ bias, bool epi)
{
    extern __shared__ char dsm[];
    const uint32_t sb = smem_u32(dsm);

    const int tid  = threadIdx.x;
    const int wid  = tid >> 5;
    const int lane = tid & 31;
    const int warp_m = wid >> 1;      // 0..3 -> 32 rows each
    const int warp_n = wid & 1;       // 0..1 -> 64 cols each
    const int m0 = blockIdx.y * BM;
    const int n0 = blockIdx.x * BN;

    float acc[2][8][4];
    #pragma unroll
    for (int a = 0; a < 2; ++a)
        #pragma unroll
        for (int b = 0; b < 8; ++b)
            #pragma unroll
            for (int c = 0; c < 4; ++c) acc[a][b][c] = 0.f;

    // prologue: fill 3 stages
    #pragma unroll
    for (int s = 0; s < NSTAGE; ++s)
        load_stage(sb + s * STAGE_B, Ah, Al, Bh, Bl, m0, n0, s, tid);

    // ldmatrix row/lane geometry
    const int frag_row = lane & 15;   // row within 16-row ldmatrix block
    const int frag_ch  = lane >> 4;   // 0/1 : which 8-elem k-chunk

    #pragma unroll 1
    for (int kc = 0; kc < NKC; ++kc) {
        cp_wait<NSTAGE - 1>();
        __syncthreads();

        const uint32_t st  = sb + (kc % NSTAGE) * STAGE_B;
        const uint32_t sAh = st;
        const uint32_t sAl = st + TILE_B;
        const uint32_t sBh = st + 2 * TILE_B;
        const uint32_t sBl = st + 3 * TILE_B;

        #pragma unroll
        for (int kk = 0; kk < 4; ++kk) {          // 4 x k16 within 64
            uint32_t ah[2][4], al[2][4];
            #pragma unroll
            for (int mi = 0; mi < 2; ++mi) {
                int row = warp_m * 32 + mi * 16 + frag_row;
                int ch  = kk * 2 + frag_ch;
                uint32_t off = row * 128 + (((ch ^ (row & 7)) << 4));
                ldsm4(ah[mi], sAh + off);
                ldsm4(al[mi], sAl + off);
            }
            uint32_t bh[4][4], bl[4][4];
            #pragma unroll
            for (int ng = 0; ng < 4; ++ng) {      // 4 x n16 = 64 cols
                int row = warp_n * 64 + ng * 16 + frag_row;
                int ch  = kk * 2 + frag_ch;
                uint32_t off = row * 128 + (((ch ^ (row & 7)) << 4));
                ldsm4(bh[ng], sBh + off);
                ldsm4(bl[ng], sBl + off);
            }
            #pragma unroll
            for (int mi = 0; mi < 2; ++mi)
                #pragma unroll
                for (int ng = 0; ng < 4; ++ng) {
                    // n8 tile 0 of this n16: k0-7 -> reg0, k8-15 -> reg2
                    mma16816(acc[mi][ng * 2],     ah[mi], bh[ng][0], bh[ng][2]);
                    mma16816(acc[mi][ng * 2],     ah[mi], bl[ng][0], bl[ng][2]);
                    mma16816(acc[mi][ng * 2],     al[mi], bh[ng][0], bh[ng][2]);
                    // n8 tile 1: regs 1 and 3
                    mma16816(acc[mi][ng * 2 + 1], ah[mi], bh[ng][1], bh[ng][3]);
                    mma16816(acc[mi][ng * 2 + 1], ah[mi], bl[ng][1], bl[ng][3]);
                    mma16816(acc[mi][ng * 2 + 1], al[mi], bh[ng][1], bh[ng][3]);
                }
        }

        __syncthreads();
        if (kc + NSTAGE < NKC)
            load_stage(sb + (kc % NSTAGE) * STAGE_B, Ah, Al, Bh, Bl,
                       m0, n0, kc + NSTAGE, tid);
    }

    // epilogue: write fp32
    const int erow = lane >> 2;       // 0..7
    const int ecol = (lane & 3) * 2;  // 0,2,4,6
    #pragma unroll
    for (int mi = 0; mi < 2; ++mi) {
        #pragma unroll
        for (int ni = 0; ni < 8; ++ni) {
            size_t r0 = (size_t)m0 + warp_m * 32 + mi * 16 + erow;
            int    c  = n0 + warp_n * 64 + ni * 8 + ecol;
            float2 v0 = make_float2(acc[mi][ni][0], acc[mi][ni][1]);
            float2 v1 = make_float2(acc[mi][ni][2], acc[mi][ni][3]);
            if (epi) {
                float2 y0 = *(const float2*)(Yadd + r0 * DIMW + c);
                float2 y1 = *(const float2*)(Yadd + (r0 + 8) * DIMW + c);
                float2 bv = *(const float2*)(bias + c);
                v0.x += y0.x + bv.x; v0.y += y0.y + bv.y;
                v1.x += y1.x + bv.x; v1.y += y1.y + bv.y;
            }
            *(float2*)(C + r0 * DIMW + c)       = v0;
            *(float2*)(C + (r0 + 8) * DIMW + c) = v1;
        }
    }
}

__global__ __launch_bounds__(256, 1) void qkv_gemm()
{
    if (blockIdx.z == 0)
        gemm_body(g_yh, g_yl, g_Wqh, g_Wql, g_q, nullptr, nullptr, false);
    else if (blockIdx.z == 1)
        gemm_body(g_xh, g_xl, g_Wkh, g_Wkl, g_k, nullptr, nullptr, false);
    else
        gemm_body(g_xh, g_xl, g_Wvh, g_Wvl, g_v, nullptr, nullptr, false);
}

__global__ __launch_bounds__(256, 1) void out_gemm(const float* __restrict__ y,
                                                   const float* __restrict__ bout,
                                                   float* __restrict__ ynew)
{
    gemm_body(g_oh, g_ol, g_Woh, g_Wol, ynew, y, bout, true);
}

// ---------------- LayerNorm over rows of 512 (in place on g_q / g_k) --------
__global__ __launch_bounds__(256) void ln_kernel(const float* __restrict__ gq,
                                                 const float* __restrict__ bq,
                                                 const float* __restrict__ gk,
                                                 const float* __restrict__ bk)
{
    float*       buf = (blockIdx.y == 0) ? g_q : g_k;
    const float* g   = (blockIdx.y == 0) ? gq  : gk;
    const float* b   = (blockIdx.y == 0) ? bq  : bk;
    const size_t row = blockIdx.x;
    const int tid = threadIdx.x;

    float2 v = *(float2*)(buf + row * DIMW + tid * 2);
    float s  = v.x + v.y;
    float sq = v.x * v.x + v.y * v.y;
    #pragma unroll
    for (int o = 16; o > 0; o >>= 1) {
        s  += __shfl_xor_sync(0xffffffffu, s,  o);
        sq += __shfl_xor_sync(0xffffffffu, sq, o);
    }
    __shared__ float ss[8], ssq[8];
    if ((tid & 31) == 0) { ss[tid >> 5] = s; ssq[tid >> 5] = sq; }
    __syncthreads();
    s = 0.f; sq = 0.f;
    #pragma unroll
    for (int i = 0; i < 8; ++i) { s += ss[i]; sq += ssq[i]; }

    float mean = s * (1.f / 512.f);
    float var  = sq * (1.f / 512.f) - mean * mean;
    float rstd = rsqrtf(var + 1e-5f);
    int c = tid * 2;
    float2 o;
    o.x = (v.x - mean) * rstd * g[c]     + b[c];
    o.y = (v.y - mean) * rstd * g[c + 1] + b[c + 1];
    *(float2*)(buf + row * DIMW + c) = o;
}

// ---------------- windowed attention: one block per (window, head) ----------
#define QS  65
#define ATS 136
#define ATTN_SMEM ((3 * 128 * QS + 128 * ATS) * 4)

__global__ __launch_bounds__(256) void attn_kernel(float* __restrict__ attn_out)
{
    extern __shared__ float sm[];
    float* qs  = sm;
    float* ks  = qs + 128 * QS;
    float* vs  = ks + 128 * QS;
    float* as_ = vs + 128 * QS;

    const int tid = threadIdx.x;
    const int bwh = blockIdx.x;
    const int bw  = bwh >> 3;
    const int h   = bwh & 7;
    const size_t rowbase = (size_t)bw * WIN;
    const int coloff = h * DHEAD;

    #pragma unroll
    for (int it = 0; it < 8; ++it) {
        int idx = tid + it * 256;
        int i   = idx >> 4;
        int d4  = (idx & 15) << 2;
        size_t goff = (rowbase + i) * DIMW + coloff + d4;
        float4 qv = *(const float4*)(g_q + goff);
        float4 kv = *(const float4*)(g_k + goff);
        float4 vv = *(const float4*)(g_v + goff);
        float* qd = qs + i * QS + d4;
        qd[0] = qv.x; qd[1] = qv.y; qd[2] = qv.z; qd[3] = qv.w;
        float* kd = ks + i * QS + d4;
        kd[0] = kv.x; kd[1] = kv.y; kd[2] = kv.z; kd[3] = kv.w;
        float* vd = vs + i * QS + d4;
        vd[0] = vv.x; vd[1] = vv.y; vd[2] = vv.z; vd[3] = vv.w;
    }
    __syncthreads();

    const int rg = tid >> 3;
    const int cg = tid & 7;

    float acc[4][16];
    #pragma unroll
    for (int r = 0; r < 4; ++r)
        #pragma unroll
        for (int c = 0; c < 16; ++c) acc[r][c] = 0.f;

    #pragma unroll 4
    for (int d = 0; d < 64; ++d) {
        float qv[4], kv[16];
        #pragma unroll
        for (int r = 0; r < 4; ++r)  qv[r] = qs[(rg + 32 * r) * QS + d];
        #pragma unroll
        for (int c = 0; c < 16; ++c) kv[c] = ks[(cg + 8 * c) * QS + d];
        #pragma unroll
        for (int r = 0; r < 4; ++r)
            #pragma unroll
            for (int c = 0; c < 16; ++c)
                acc[r][c] += qv[r] * kv[c];
    }

    const size_t abase = (size_t)bwh * WIN * WIN;
    #pragma unroll
    for (int r = 0; r < 4; ++r) {
        float mx = -1e30f;
        #pragma unroll
        for (int c = 0; c < 16; ++c) {
            acc[r][c] *= 0.125f;
            mx = fmaxf(mx, acc[r][c]);
        }
        #pragma unroll
        for (int o = 1; o < 8; o <<= 1)
            mx = fmaxf(mx, __shfl_xor_sync(0xffffffffu, mx, o, 8));
        float sum = 0.f;
        #pragma unroll
        for (int c = 0; c < 16; ++c) {
            acc[r][c] = __expf(acc[r][c] - mx);
            sum += acc[r][c];
        }
        #pragma unroll
        for (int o = 1; o < 8; o <<= 1)
            sum += __shfl_xor_sync(0xffffffffu, sum, o, 8);
        float inv = 1.0f / sum;
        int i = rg + 32 * r;
        #pragma unroll
        for (int c = 0; c < 16; ++c) {
            float p = acc[r][c] * inv;
            int j = cg + 8 * c;
            attn_out[abase + (size_t)i * WIN + j] = p;
            as_[i * ATS + j] = p;
        }
    }
    __syncthreads();

    float oacc[4][8];
    #pragma unroll
    for (int r = 0; r < 4; ++r)
        #pragma unroll
        for (int c = 0; c < 8; ++c) oacc[r][c] = 0.f;

    #pragma unroll 2
    for (int j = 0; j < 128; ++j) {
        float av[4], vv[8];
        #pragma unroll
        for (int r = 0; r < 4; ++r) av[r] = as_[(rg + 32 * r) * ATS + j];
        #pragma unroll
        for (int c = 0; c < 8; ++c) vv[c] = vs[j * QS + cg + 8 * c];
        #pragma unroll
        for (int r = 0; r < 4; ++r)
            #pragma unroll
            for (int c = 0; c < 8; ++c)
                oacc[r][c] += av[r] * vv[c];
    }

    #pragma unroll
    for (int r = 0; r < 4; ++r) {
        int i = rg + 32 * r;
        size_t go = (rowbase + i) * DIMW + coloff;
        #pragma unroll
        for (int c = 0; c < 8; ++c)
            g_o[go + cg + 8 * c] = oacc[r][c];
    }
}

// ---------------- launcher ---------------------------------------------------
extern "C" void kernel_launch(void* const* d_in, const int* in_sizes, int n_in,
                              void* d_out, int out_size)
{
    const float* x  = (const float*)d_in[0];
    const float* y  = (const float*)d_in[1];
    const float* Wq = (const float*)d_in[2];
    const float* gq = (const float*)d_in[3];
    const float* bq = (const float*)d_in[4];
    const float* Wk = (const float*)d_in[5];
    const float* gk = (const float*)d_in[6];
    const float* bk = (const float*)d_in[7];
    const float* Wv = (const float*)d_in[8];
    const float* Wo = (const float*)d_in[9];
    const float* bo = (const float*)d_in[10];

    float* ynew = (float*)d_out;
    float* attn = ynew + (size_t)M_TOT * DIMW;

    void *p_xh, *p_xl, *p_yh, *p_yl, *p_oh, *p_ol, *p_go;
    void *p_wqh, *p_wql, *p_wkh, *p_wkl, *p_wvh, *p_wvl, *p_woh, *p_wol;
    cudaGetSymbolAddress(&p_xh, g_xh);  cudaGetSymbolAddress(&p_xl, g_xl);
    cudaGetSymbolAddress(&p_yh, g_yh);  cudaGetSymbolAddress(&p_yl, g_yl);
    cudaGetSymbolAddress(&p_oh, g_oh);  cudaGetSymbolAddress(&p_ol, g_ol);
    cudaGetSymbolAddress(&p_go, g_o);
    cudaGetSymbolAddress(&p_wqh, g_Wqh); cudaGetSymbolAddress(&p_wql, g_Wql);
    cudaGetSymbolAddress(&p_wkh, g_Wkh); cudaGetSymbolAddress(&p_wkl, g_Wkl);
    cudaGetSymbolAddress(&p_wvh, g_Wvh); cudaGetSymbolAddress(&p_wvl, g_Wvl);
    cudaGetSymbolAddress(&p_woh, g_Woh); cudaGetSymbolAddress(&p_wol, g_Wol);

    cudaFuncSetAttribute(attn_kernel,
                         cudaFuncAttributeMaxDynamicSharedMemorySize, ATTN_SMEM);
    cudaFuncSetAttribute(qkv_gemm,
                         cudaFuncAttributeMaxDynamicSharedMemorySize, GEMM_SMEM);
    cudaFuncSetAttribute(out_gemm,
                         cudaFuncAttributeMaxDynamicSharedMemorySize, GEMM_SMEM);

    // 1) split inputs / weights into bf16 hi/lo
    const int n4_act = (M_TOT * DIMW) / 4;
    const int n4_w   = (DIMW * DIMW) / 4;
    split_kernel<<<(n4_act + 255) / 256, 256>>>((const float4*)x,
        (uint2*)p_xh, (uint2*)p_xl, n4_act);
    split_kernel<<<(n4_act + 255) / 256, 256>>>((const float4*)y,
        (uint2*)p_yh, (uint2*)p_yl, n4_act);
    split_kernel<<<(n4_w + 255) / 256, 256>>>((const float4*)Wq,
        (uint2*)p_wqh, (uint2*)p_wql, n4_w);
    split_kernel<<<(n4_w + 255) / 256, 256>>>((const float4*)Wk,
        (uint2*)p_wkh, (uint2*)p_wkl, n4_w);
    split_kernel<<<(n4_w + 255) / 256, 256>>>((const float4*)Wv,
        (uint2*)p_wvh, (uint2*)p_wvl, n4_w);
    split_kernel<<<(n4_w + 255) / 256, 256>>>((const float4*)Wo,
        (uint2*)p_woh, (uint2*)p_wol, n4_w);

    // 2) q/k/v projections (warp-MMA bf16x3)
    qkv_gemm<<<dim3(DIMW / BN, M_TOT / BM, 3), 256, GEMM_SMEM>>>();

    // 3) LN on q, k
    ln_kernel<<<dim3(M_TOT, 2), 256>>>(gq, bq, gk, bk);

    // 4) windowed attention (fp32) -> attn out + g_o
    attn_kernel<<<4096, 256, ATTN_SMEM>>>(attn);

    // 5) split attention output, final projection with residual epilogue
    split_kernel<<<(n4_act + 255) / 256, 256>>>((const float4*)p_go,
        (uint2*)p_oh, (uint2*)p_ol, n4_act);
    out_gemm<<<dim3(DIMW / BN, M_TOT / BM), 256, GEMM_SMEM>>>(y, bo, ynew);
}

// round 6
// speedup vs baseline: 2.0866x; 1.1038x over previous
#include <cuda_runtime.h>
#include <cuda_bf16.h>
#include <cstdint>

#define M_TOT 65536      // B*N rows
#define DIMW  512        // DIM == INNER
#define WIN   128
#define NHEAD 8
#define DHEAD 64

// GEMM tiling (warp-MMA, mma.sync m16n8k16 bf16)
#define BM 128
#define BN 256
#define BK 64                        // bf16 elems per k-chunk (128 bytes/row)
#define NKC (DIMW / BK)              // 8 chunks
#define A_TILE_B (BM * 128)          // 16384 bytes
#define B_TILE_B (BN * 128)          // 32768 bytes
#define STAGE_B (2 * A_TILE_B + 2 * B_TILE_B)   // 96 KB
#define NSTAGE 2
#define GEMM_SMEM (NSTAGE * STAGE_B)            // 192 KB

// ---------------- scratch (__device__ globals; no allocation allowed) -------
__device__ float g_q[(size_t)M_TOT * DIMW];
__device__ float g_k[(size_t)M_TOT * DIMW];
__device__ float g_v[(size_t)M_TOT * DIMW];

__device__ __nv_bfloat16 g_xh[(size_t)M_TOT * DIMW];
__device__ __nv_bfloat16 g_xl[(size_t)M_TOT * DIMW];
__device__ __nv_bfloat16 g_yh[(size_t)M_TOT * DIMW];
__device__ __nv_bfloat16 g_yl[(size_t)M_TOT * DIMW];
__device__ __nv_bfloat16 g_oh[(size_t)M_TOT * DIMW];
__device__ __nv_bfloat16 g_ol[(size_t)M_TOT * DIMW];

__device__ __nv_bfloat16 g_Wqh[DIMW * DIMW];
__device__ __nv_bfloat16 g_Wql[DIMW * DIMW];
__device__ __nv_bfloat16 g_Wkh[DIMW * DIMW];
__device__ __nv_bfloat16 g_Wkl[DIMW * DIMW];
__device__ __nv_bfloat16 g_Wvh[DIMW * DIMW];
__device__ __nv_bfloat16 g_Wvl[DIMW * DIMW];
__device__ __nv_bfloat16 g_Woh[DIMW * DIMW];
__device__ __nv_bfloat16 g_Wol[DIMW * DIMW];

// ---------------- small asm helpers ------------------------------------------
__device__ __forceinline__ uint32_t smem_u32(const void* p) {
    uint32_t a;
    asm("{ .reg .u64 t; cvta.to.shared.u64 t, %1; cvt.u32.u64 %0, t; }"
        : "=r"(a) : "l"(p));
    return a;
}
__device__ __forceinline__ void cp16(uint32_t dst, const void* src) {
    asm volatile("cp.async.cg.shared.global [%0], [%1], 16;"
                 :: "r"(dst), "l"(src) : "memory");
}
__device__ __forceinline__ void cp_commit() {
    asm volatile("cp.async.commit_group;" ::: "memory");
}
template <int N>
__device__ __forceinline__ void cp_wait() {
    asm volatile("cp.async.wait_group %0;" :: "n"(N) : "memory");
}
__device__ __forceinline__ void ldsm4(uint32_t* r, uint32_t addr) {
    asm volatile("ldmatrix.sync.aligned.m8n8.x4.shared.b16 {%0,%1,%2,%3}, [%4];"
                 : "=r"(r[0]), "=r"(r[1]), "=r"(r[2]), "=r"(r[3]) : "r"(addr));
}
__device__ __forceinline__ void mma16816(float* d, const uint32_t* a,
                                         uint32_t b0, uint32_t b1) {
    asm volatile(
        "mma.sync.aligned.m16n8k16.row.col.f32.bf16.bf16.f32 "
        "{%0,%1,%2,%3}, {%4,%5,%6,%7}, {%8,%9}, {%0,%1,%2,%3};"
        : "+f"(d[0]), "+f"(d[1]), "+f"(d[2]), "+f"(d[3])
        : "r"(a[0]), "r"(a[1]), "r"(a[2]), "r"(a[3]), "r"(b0), "r"(b1));
}
// packed fp32x2 helpers (Blackwell)
__device__ __forceinline__ unsigned long long pack2(float a, float b) {
    unsigned long long r;
    asm("mov.b64 %0, {%1, %2};" : "=l"(r) : "f"(a), "f"(b));
    return r;
}
__device__ __forceinline__ void unpack2(unsigned long long v, float& a, float& b) {
    asm("mov.b64 {%0, %1}, %2;" : "=f"(a), "=f"(b) : "l"(v));
}
__device__ __forceinline__ void fma2(unsigned long long& d,
                                     unsigned long long a, unsigned long long b) {
    asm("fma.rn.f32x2 %0, %1, %2, %0;" : "+l"(d) : "l"(a), "l"(b));
}

// ---------------- fp32 -> bf16 hi/lo split ----------------------------------
__global__ __launch_bounds__(256) void split_kernel(const float4* __restrict__ in,
                                                    uint2* __restrict__ hi,
                                                    uint2* __restrict__ lo, int n4)
{
    int i = blockIdx.x * blockDim.x + threadIdx.x;
    if (i >= n4) return;
    float4 v = in[i];
    __nv_bfloat16 h0 = __float2bfloat16(v.x);
    __nv_bfloat16 h1 = __float2bfloat16(v.y);
    __nv_bfloat16 h2 = __float2bfloat16(v.z);
    __nv_bfloat16 h3 = __float2bfloat16(v.w);
    __nv_bfloat16 l0 = __float2bfloat16(v.x - __bfloat162float(h0));
    __nv_bfloat16 l1 = __float2bfloat16(v.y - __bfloat162float(h1));
    __nv_bfloat16 l2 = __float2bfloat16(v.z - __bfloat162float(h2));
    __nv_bfloat16 l3 = __float2bfloat16(v.w - __bfloat162float(h3));
    uint2 H, L;
    H.x = (uint32_t)__bfloat16_as_ushort(h0) | ((uint32_t)__bfloat16_as_ushort(h1) << 16);
    H.y = (uint32_t)__bfloat16_as_ushort(h2) | ((uint32_t)__bfloat16_as_ushort(h3) << 16);
    L.x = (uint32_t)__bfloat16_as_ushort(l0) | ((uint32_t)__bfloat16_as_ushort(l1) << 16);
    L.y = (uint32_t)__bfloat16_as_ushort(l2) | ((uint32_t)__bfloat16_as_ushort(l3) << 16);
    hi[i] = H;
    lo[i] = L;
}

// ---------------- bf16x3 warp-MMA GEMM (512 threads, BM128 x BN256) ----------
__device__ __forceinline__ void load_stage(uint32_t sbase,
    const __nv_bfloat16* __restrict__ Ah, const __nv_bfloat16* __restrict__ Al,
    const __nv_bfloat16* __restrict__ Bh, const __nv_bfloat16* __restrict__ Bl,
    int m0, int n0, int kc, int tid)
{
    const int kcol = kc * BK;
    #pragma unroll
    for (int i = 0; i < 2; ++i) {               // A: 128 rows x 8 ch = 1024
        int idx = tid + i * 512;
        int row = idx >> 3;
        int ch  = idx & 7;
        uint32_t soff = row * 128 + (((ch ^ (row & 7)) << 4));
        size_t ga = (size_t)(m0 + row) * DIMW + kcol + ch * 8;
        cp16(sbase + soff,            Ah + ga);
        cp16(sbase + A_TILE_B + soff, Al + ga);
    }
    #pragma unroll
    for (int i = 0; i < 4; ++i) {               // B: 256 rows x 8 ch = 2048
        int idx = tid + i * 512;
        int row = idx >> 3;
        int ch  = idx & 7;
        uint32_t soff = row * 128 + (((ch ^ (row & 7)) << 4));
        size_t gb = (size_t)(n0 + row) * DIMW + kcol + ch * 8;
        cp16(sbase + 2 * A_TILE_B + soff,            Bh + gb);
        cp16(sbase + 2 * A_TILE_B + B_TILE_B + soff, Bl + gb);
    }
    cp_commit();
}

__device__ __forceinline__ void gemm_body(
    const __nv_bfloat16* __restrict__ Ah, const __nv_bfloat16* __restrict__ Al,
    const __nv_bfloat16* __restrict__ Bh, const __nv_bfloat16* __restrict__ Bl,
    float* __restrict__ C, const float* __restrict__ Yadd,
    const float* __restrict__ bias, bool epi)
{
    extern __shared__ char dsm[];
    const uint32_t sb = smem_u32(dsm);

    const int tid  = threadIdx.x;
    const int wid  = tid >> 5;
    const int lane = tid & 31;
    const int warp_m = wid >> 2;      // 0..3 -> 32 rows each
    const int warp_n = wid & 3;       // 0..3 -> 64 cols each
    const int m0 = blockIdx.y * BM;
    const int n0 = blockIdx.x * BN;

    float acc[2][8][4];
    #pragma unroll
    for (int a = 0; a < 2; ++a)
        #pragma unroll
        for (int b = 0; b < 8; ++b)
            #pragma unroll
            for (int c = 0; c < 4; ++c) acc[a][b][c] = 0.f;

    #pragma unroll
    for (int s = 0; s < NSTAGE; ++s)
        load_stage(sb + s * STAGE_B, Ah, Al, Bh, Bl, m0, n0, s, tid);

    const int frag_row = lane & 15;
    const int frag_ch  = lane >> 4;

    #pragma unroll 1
    for (int kc = 0; kc < NKC; ++kc) {
        cp_wait<NSTAGE - 1>();
        __syncthreads();

        const uint32_t st  = sb + (kc % NSTAGE) * STAGE_B;
        const uint32_t sAh = st;
        const uint32_t sAl = st + A_TILE_B;
        const uint32_t sBh = st + 2 * A_TILE_B;
        const uint32_t sBl = st + 2 * A_TILE_B + B_TILE_B;

        #pragma unroll
        for (int kk = 0; kk < 4; ++kk) {
            uint32_t ah[2][4], al[2][4];
            #pragma unroll
            for (int mi = 0; mi < 2; ++mi) {
                int row = warp_m * 32 + mi * 16 + frag_row;
                int ch  = kk * 2 + frag_ch;
                uint32_t off = row * 128 + (((ch ^ (row & 7)) << 4));
                ldsm4(ah[mi], sAh + off);
                ldsm4(al[mi], sAl + off);
            }
            uint32_t bh[4][4], bl[4][4];
            #pragma unroll
            for (int ng = 0; ng < 4; ++ng) {
                int row = warp_n * 64 + ng * 16 + frag_row;
                int ch  = kk * 2 + frag_ch;
                uint32_t off = row * 128 + (((ch ^ (row & 7)) << 4));
                ldsm4(bh[ng], sBh + off);
                ldsm4(bl[ng], sBl + off);
            }
            #pragma unroll
            for (int mi = 0; mi < 2; ++mi)
                #pragma unroll
                for (int ng = 0; ng < 4; ++ng) {
                    mma16816(acc[mi][ng * 2],     ah[mi], bh[ng][0], bh[ng][2]);
                    mma16816(acc[mi][ng * 2],     ah[mi], bl[ng][0], bl[ng][2]);
                    mma16816(acc[mi][ng * 2],     al[mi], bh[ng][0], bh[ng][2]);
                    mma16816(acc[mi][ng * 2 + 1], ah[mi], bh[ng][1], bh[ng][3]);
                    mma16816(acc[mi][ng * 2 + 1], ah[mi], bl[ng][1], bl[ng][3]);
                    mma16816(acc[mi][ng * 2 + 1], al[mi], bh[ng][1], bh[ng][3]);
                }
        }

        __syncthreads();
        if (kc + NSTAGE < NKC)
            load_stage(sb + (kc % NSTAGE) * STAGE_B, Ah, Al, Bh, Bl,
                       m0, n0, kc + NSTAGE, tid);
    }

    const int erow = lane >> 2;
    const int ecol = (lane & 3) * 2;
    #pragma unroll
    for (int mi = 0; mi < 2; ++mi) {
        #pragma unroll
        for (int ni = 0; ni < 8; ++ni) {
            size_t r0 = (size_t)m0 + warp_m * 32 + mi * 16 + erow;
            int    c  = n0 + warp_n * 64 + ni * 8 + ecol;
            float2 v0 = make_float2(acc[mi][ni][0], acc[mi][ni][1]);
            float2 v1 = make_float2(acc[mi][ni][2], acc[mi][ni][3]);
            if (epi) {
                float2 y0 = *(const float2*)(Yadd + r0 * DIMW + c);
                float2 y1 = *(const float2*)(Yadd + (r0 + 8) * DIMW + c);
                float2 bv = *(const float2*)(bias + c);
                v0.x += y0.x + bv.x; v0.y += y0.y + bv.y;
                v1.x += y1.x + bv.x; v1.y += y1.y + bv.y;
            }
            *(float2*)(C + r0 * DIMW + c)       = v0;
            *(float2*)(C + (r0 + 8) * DIMW + c) = v1;
        }
    }
}

__global__ __launch_bounds__(512, 1) void qkv_gemm()
{
    if (blockIdx.z == 0)
        gemm_body(g_yh, g_yl, g_Wqh, g_Wql, g_q, nullptr, nullptr, false);
    else if (blockIdx.z == 1)
        gemm_body(g_xh, g_xl, g_Wkh, g_Wkl, g_k, nullptr, nullptr, false);
    else
        gemm_body(g_xh, g_xl, g_Wvh, g_Wvl, g_v, nullptr, nullptr, false);
}

__global__ __launch_bounds__(512, 1) void out_gemm(const float* __restrict__ y,
                                                   const float* __restrict__ bout,
                                                   float* __restrict__ ynew)
{
    gemm_body(g_oh, g_ol, g_Woh, g_Wol, ynew, y, bout, true);
}

// ---------------- LayerNorm over rows of 512 (in place on g_q / g_k) --------
__global__ __launch_bounds__(256) void ln_kernel(const float* __restrict__ gq,
                                                 const float* __restrict__ bq,
                                                 const float* __restrict__ gk,
                                                 const float* __restrict__ bk)
{
    float*       buf = (blockIdx.y == 0) ? g_q : g_k;
    const float* g   = (blockIdx.y == 0) ? gq  : gk;
    const float* b   = (blockIdx.y == 0) ? bq  : bk;
    const size_t row = blockIdx.x;
    const int tid = threadIdx.x;

    float2 v = *(float2*)(buf + row * DIMW + tid * 2);
    float s  = v.x + v.y;
    float sq = v.x * v.x + v.y * v.y;
    #pragma unroll
    for (int o = 16; o > 0; o >>= 1) {
        s  += __shfl_xor_sync(0xffffffffu, s,  o);
        sq += __shfl_xor_sync(0xffffffffu, sq, o);
    }
    __shared__ float ss[8], ssq[8];
    if ((tid & 31) == 0) { ss[tid >> 5] = s; ssq[tid >> 5] = sq; }
    __syncthreads();
    s = 0.f; sq = 0.f;
    #pragma unroll
    for (int i = 0; i < 8; ++i) { s += ss[i]; sq += ssq[i]; }

    float mean = s * (1.f / 512.f);
    float var  = sq * (1.f / 512.f) - mean * mean;
    float rstd = rsqrtf(var + 1e-5f);
    int c = tid * 2;
    float2 o;
    o.x = (v.x - mean) * rstd * g[c]     + b[c];
    o.y = (v.y - mean) * rstd * g[c + 1] + b[c + 1];
    *(float2*)(buf + row * DIMW + c) = o;
}

// ---------------- windowed attention (FFMA2), 2 blocks/SM --------------------
// layout: qs[128][QS] natural; kt[64][KTS] = K transposed; vs[128][VSS] natural
#define QS  65
#define KTS 130
#define VSS 66
#define ATTN_SMEM ((128 * QS + 64 * KTS + 128 * VSS) * 4)   // 100,352 B

__global__ __launch_bounds__(256, 2) void attn_kernel(float* __restrict__ attn_out)
{
    extern __shared__ float sm[];
    float* qs = sm;                    // [128][QS]
    float* kt = qs + 128 * QS;         // [64][KTS]  (kt[d][j])
    float* vs = kt + 64 * KTS;         // [128][VSS]

    const int tid = threadIdx.x;
    const int bwh = blockIdx.x;        // bw*8 + h
    const int bw  = bwh >> 3;
    const int h   = bwh & 7;
    const size_t rowbase = (size_t)bw * WIN;
    const int coloff = h * DHEAD;

    // load q (natural), k (transposed), v (natural)
    #pragma unroll
    for (int it = 0; it < 8; ++it) {
        int idx = tid + it * 256;      // 0..2047
        int i   = idx >> 4;            // row 0..127
        int d4  = (idx & 15) << 2;     // 0..60
        size_t goff = (rowbase + i) * DIMW + coloff + d4;
        float4 qv = *(const float4*)(g_q + goff);
        float4 kv = *(const float4*)(g_k + goff);
        float4 vv = *(const float4*)(g_v + goff);
        float* qd = qs + i * QS + d4;
        qd[0] = qv.x; qd[1] = qv.y; qd[2] = qv.z; qd[3] = qv.w;
        kt[(d4 + 0) * KTS + i] = kv.x;
        kt[(d4 + 1) * KTS + i] = kv.y;
        kt[(d4 + 2) * KTS + i] = kv.z;
        kt[(d4 + 3) * KTS + i] = kv.w;
        float* vd = vs + i * VSS + d4;
        vd[0] = vv.x; vd[1] = vv.y; vd[2] = vv.z; vd[3] = vv.w;
    }
    __syncthreads();

    const int rg = tid >> 3;           // 0..31 : rows i = rg + 32*r
    const int cg = tid & 7;            // 0..7

    // ---------------- QK^T : acc2[r][c] holds j = 16c + 2cg + {0,1} ---------
    unsigned long long acc2[4][8];
    #pragma unroll
    for (int r = 0; r < 4; ++r)
        #pragma unroll
        for (int c = 0; c < 8; ++c) acc2[r][c] = 0ull;

    #pragma unroll 4
    for (int d = 0; d < 64; ++d) {
        unsigned long long qv2[4];
        #pragma unroll
        for (int r = 0; r < 4; ++r) {
            float q = qs[(rg + 32 * r) * QS + d];
            qv2[r] = pack2(q, q);
        }
        unsigned long long kv2[8];
        #pragma unroll
        for (int c = 0; c < 8; ++c)
            kv2[c] = *reinterpret_cast<const unsigned long long*>(
                         kt + d * KTS + 16 * c + 2 * cg);
        #pragma unroll
        for (int r = 0; r < 4; ++r)
            #pragma unroll
            for (int c = 0; c < 8; ++c)
                fma2(acc2[r][c], qv2[r], kv2[c]);
    }

    // ---------------- softmax per row + write attn ---------------------------
    float pacc[4][16];
    const size_t abase = (size_t)bwh * WIN * WIN;
    #pragma unroll
    for (int r = 0; r < 4; ++r) {
        #pragma unroll
        for (int c = 0; c < 8; ++c) {
            float a, b;
            unpack2(acc2[r][c], a, b);
            pacc[r][2 * c]     = a * 0.125f;
            pacc[r][2 * c + 1] = b * 0.125f;
        }
        float mx = -1e30f;
        #pragma unroll
        for (int c = 0; c < 16; ++c) mx = fmaxf(mx, pacc[r][c]);
        #pragma unroll
        for (int o = 1; o < 8; o <<= 1)
            mx = fmaxf(mx, __shfl_xor_sync(0xffffffffu, mx, o, 8));
        float sum = 0.f;
        #pragma unroll
        for (int c = 0; c < 16; ++c) {
            pacc[r][c] = __expf(pacc[r][c] - mx);
            sum += pacc[r][c];
        }
        #pragma unroll
        for (int o = 1; o < 8; o <<= 1)
            sum += __shfl_xor_sync(0xffffffffu, sum, o, 8);
        float inv = 1.0f / sum;
        int i = rg + 32 * r;
        #pragma unroll
        for (int c = 0; c < 8; ++c) {
            pacc[r][2 * c]     *= inv;
            pacc[r][2 * c + 1] *= inv;
            float2 pw = make_float2(pacc[r][2 * c], pacc[r][2 * c + 1]);
            *reinterpret_cast<float2*>(
                attn_out + abase + (size_t)i * WIN + 16 * c + 2 * cg) = pw;
        }
    }

    // ---------------- P @ V : oacc2[r][c] holds d = 16c + 2cg + {0,1} --------
    unsigned long long oacc2[4][4];
    #pragma unroll
    for (int r = 0; r < 4; ++r)
        #pragma unroll
        for (int c = 0; c < 4; ++c) oacc2[r][c] = 0ull;

    #pragma unroll
    for (int j = 0; j < 128; ++j) {
        const int cg_src = (j >> 1) & 7;
        const int cidx   = ((j >> 4) << 1) | (j & 1);
        unsigned long long vv2[4];
        #pragma unroll
        for (int c = 0; c < 4; ++c)
            vv2[c] = *reinterpret_cast<const unsigned long long*>(
                         vs + j * VSS + 16 * c + 2 * cg);
        #pragma unroll
        for (int r = 0; r < 4; ++r) {
            float p = __shfl_sync(0xffffffffu, pacc[r][cidx], cg_src, 8);
            unsigned long long av2 = pack2(p, p);
            #pragma unroll
            for (int c = 0; c < 4; ++c)
                fma2(oacc2[r][c], av2, vv2[c]);
        }
    }

    // epilogue: split to bf16 hi/lo directly (feeds out_gemm)
    #pragma unroll
    for (int r = 0; r < 4; ++r) {
        int i = rg + 32 * r;
        size_t go = (rowbase + i) * DIMW + coloff;
        #pragma unroll
        for (int c = 0; c < 4; ++c) {
            float o0, o1;
            unpack2(oacc2[r][c], o0, o1);
            __nv_bfloat16 h0 = __float2bfloat16(o0);
            __nv_bfloat16 h1 = __float2bfloat16(o1);
            __nv_bfloat16 l0 = __float2bfloat16(o0 - __bfloat162float(h0));
            __nv_bfloat16 l1 = __float2bfloat16(o1 - __bfloat162float(h1));
            __nv_bfloat162 H; H.x = h0; H.y = h1;
            __nv_bfloat162 L; L.x = l0; L.y = l1;
            *reinterpret_cast<__nv_bfloat162*>(g_oh + go + 16 * c + 2 * cg) = H;
            *reinterpret_cast<__nv_bfloat162*>(g_ol + go + 16 * c + 2 * cg) = L;
        }
    }
}

// ---------------- launcher ---------------------------------------------------
extern "C" void kernel_launch(void* const* d_in, const int* in_sizes, int n_in,
                              void* d_out, int out_size)
{
    const float* x  = (const float*)d_in[0];
    const float* y  = (const float*)d_in[1];
    const float* Wq = (const float*)d_in[2];
    const float* gq = (const float*)d_in[3];
    const float* bq = (const float*)d_in[4];
    const float* Wk = (const float*)d_in[5];
    const float* gk = (const float*)d_in[6];
    const float* bk = (const float*)d_in[7];
    const float* Wv = (const float*)d_in[8];
    const float* Wo = (const float*)d_in[9];
    const float* bo = (const float*)d_in[10];

    float* ynew = (float*)d_out;
    float* attn = ynew + (size_t)M_TOT * DIMW;

    void *p_xh, *p_xl, *p_yh, *p_yl;
    void *p_wqh, *p_wql, *p_wkh, *p_wkl, *p_wvh, *p_wvl, *p_woh, *p_wol;
    cudaGetSymbolAddress(&p_xh, g_xh);  cudaGetSymbolAddress(&p_xl, g_xl);
    cudaGetSymbolAddress(&p_yh, g_yh);  cudaGetSymbolAddress(&p_yl, g_yl);
    cudaGetSymbolAddress(&p_wqh, g_Wqh); cudaGetSymbolAddress(&p_wql, g_Wql);
    cudaGetSymbolAddress(&p_wkh, g_Wkh); cudaGetSymbolAddress(&p_wkl, g_Wkl);
    cudaGetSymbolAddress(&p_wvh, g_Wvh); cudaGetSymbolAddress(&p_wvl, g_Wvl);
    cudaGetSymbolAddress(&p_woh, g_Woh); cudaGetSymbolAddress(&p_wol, g_Wol);

    cudaFuncSetAttribute(attn_kernel,
                         cudaFuncAttributeMaxDynamicSharedMemorySize, ATTN_SMEM);
    cudaFuncSetAttribute(qkv_gemm,
                         cudaFuncAttributeMaxDynamicSharedMemorySize, GEMM_SMEM);
    cudaFuncSetAttribute(out_gemm,
                         cudaFuncAttributeMaxDynamicSharedMemorySize, GEMM_SMEM);

    // 1) split inputs / weights into bf16 hi/lo
    const int n4_act = (M_TOT * DIMW) / 4;
    const int n4_w   = (DIMW * DIMW) / 4;
    split_kernel<<<(n4_act + 255) / 256, 256>>>((const float4*)x,
        (uint2*)p_xh, (uint2*)p_xl, n4_act);
    split_kernel<<<(n4_act + 255) / 256, 256>>>((const float4*)y,
        (uint2*)p_yh, (uint2*)p_yl, n4_act);
    split_kernel<<<(n4_w + 255) / 256, 256>>>((const float4*)Wq,
        (uint2*)p_wqh, (uint2*)p_wql, n4_w);
    split_kernel<<<(n4_w + 255) / 256, 256>>>((const float4*)Wk,
        (uint2*)p_wkh, (uint2*)p_wkl, n4_w);
    split_kernel<<<(n4_w + 255) / 256, 256>>>((const float4*)Wv,
        (uint2*)p_wvh, (uint2*)p_wvl, n4_w);
    split_kernel<<<(n4_w + 255) / 256, 256>>>((const float4*)Wo,
        (uint2*)p_woh, (uint2*)p_wol, n4_w);

    // 2) q/k/v projections (warp-MMA bf16x3, 512 threads)
    qkv_gemm<<<dim3(DIMW / BN, M_TOT / BM, 3), 512, GEMM_SMEM>>>();

    // 3) LN on q, k
    ln_kernel<<<dim3(M_TOT, 2), 256>>>(gq, bq, gk, bk);

    // 4) windowed attention (FFMA2) -> attn out + bf16 hi/lo of o
    attn_kernel<<<4096, 256, ATTN_SMEM>>>(attn);

    // 5) final projection with residual epilogue
    out_gemm<<<dim3(DIMW / BN, M_TOT / BM), 512, GEMM_SMEM>>>(y, bo, ynew);
}

// round 7
// speedup vs baseline: 2.5480x; 1.2211x over previous
#include <cuda_runtime.h>
#include <cuda_fp16.h>
#include <cstdint>

#define M_TOT 65536      // B*N rows
#define DIMW  512        // DIM == INNER
#define WIN   128
#define NHEAD 8
#define DHEAD 64

// GEMM tiling (warp-MMA, mma.sync m16n8k16 fp16, A split hi/lo, B fp16-rounded)
#define BM 128
#define BN 256
#define BK 64                        // fp16 elems per k-chunk (128 bytes/row)
#define NKC (DIMW / BK)              // 8 chunks
#define A_TILE_B (BM * 128)          // 16384 bytes
#define B_TILE_B (BN * 128)          // 32768 bytes
#define STAGE_B (2 * A_TILE_B + B_TILE_B)       // 64 KB
#define NSTAGE 3
#define GEMM_SMEM (NSTAGE * STAGE_B)            // 192 KB

// ---------------- scratch (__device__ globals; no allocation allowed) -------
__device__ float g_q[(size_t)M_TOT * DIMW];
__device__ float g_k[(size_t)M_TOT * DIMW];
__device__ float g_v[(size_t)M_TOT * DIMW];

__device__ __half g_xh[(size_t)M_TOT * DIMW];
__device__ __half g_xl[(size_t)M_TOT * DIMW];
__device__ __half g_yh[(size_t)M_TOT * DIMW];
__device__ __half g_yl[(size_t)M_TOT * DIMW];
__device__ __half g_oh[(size_t)M_TOT * DIMW];
__device__ __half g_ol[(size_t)M_TOT * DIMW];

__device__ __half g_Wq[DIMW * DIMW];
__device__ __half g_Wk[DIMW * DIMW];
__device__ __half g_Wv[DIMW * DIMW];
__device__ __half g_Wo[DIMW * DIMW];

// ---------------- small asm helpers ------------------------------------------
__device__ __forceinline__ uint32_t smem_u32(const void* p) {
    uint32_t a;
    asm("{ .reg .u64 t; cvta.to.shared.u64 t, %1; cvt.u32.u64 %0, t; }"
        : "=r"(a) : "l"(p));
    return a;
}
__device__ __forceinline__ void cp16(uint32_t dst, const void* src) {
    asm volatile("cp.async.cg.shared.global [%0], [%1], 16;"
                 :: "r"(dst), "l"(src) : "memory");
}
__device__ __forceinline__ void cp_commit() {
    asm volatile("cp.async.commit_group;" ::: "memory");
}
template <int N>
__device__ __forceinline__ void cp_wait() {
    asm volatile("cp.async.wait_group %0;" :: "n"(N) : "memory");
}
__device__ __forceinline__ void ldsm4(uint32_t* r, uint32_t addr) {
    asm volatile("ldmatrix.sync.aligned.m8n8.x4.shared.b16 {%0,%1,%2,%3}, [%4];"
                 : "=r"(r[0]), "=r"(r[1]), "=r"(r[2]), "=r"(r[3]) : "r"(addr));
}
__device__ __forceinline__ void mma16816(float* d, const uint32_t* a,
                                         uint32_t b0, uint32_t b1) {
    asm volatile(
        "mma.sync.aligned.m16n8k16.row.col.f32.f16.f16.f32 "
        "{%0,%1,%2,%3}, {%4,%5,%6,%7}, {%8,%9}, {%0,%1,%2,%3};"
        : "+f"(d[0]), "+f"(d[1]), "+f"(d[2]), "+f"(d[3])
        : "r"(a[0]), "r"(a[1]), "r"(a[2]), "r"(a[3]), "r"(b0), "r"(b1));
}
// packed fp32x2 helpers (Blackwell)
__device__ __forceinline__ unsigned long long pack2(float a, float b) {
    unsigned long long r;
    asm("mov.b64 %0, {%1, %2};" : "=l"(r) : "f"(a), "f"(b));
    return r;
}
__device__ __forceinline__ void unpack2(unsigned long long v, float& a, float& b) {
    asm("mov.b64 {%0, %1}, %2;" : "=f"(a), "=f"(b) : "l"(v));
}
__device__ __forceinline__ void fma2(unsigned long long& d,
                                     unsigned long long a, unsigned long long b) {
    asm("fma.rn.f32x2 %0, %1, %2, %0;" : "+l"(d) : "l"(a), "l"(b));
}

// ---------------- fp32 -> fp16 hi/lo split (activations) --------------------
__global__ __launch_bounds__(256) void split_kernel(const float4* __restrict__ in,
                                                    uint2* __restrict__ hi,
                                                    uint2* __restrict__ lo, int n4)
{
    int i = blockIdx.x * blockDim.x + threadIdx.x;
    if (i >= n4) return;
    float4 v = in[i];
    __half h0 = __float2half_rn(v.x);
    __half h1 = __float2half_rn(v.y);
    __half h2 = __float2half_rn(v.z);
    __half h3 = __float2half_rn(v.w);
    __half l0 = __float2half_rn(v.x - __half2float(h0));
    __half l1 = __float2half_rn(v.y - __half2float(h1));
    __half l2 = __float2half_rn(v.z - __half2float(h2));
    __half l3 = __float2half_rn(v.w - __half2float(h3));
    uint2 H, L;
    H.x = (uint32_t)__half_as_ushort(h0) | ((uint32_t)__half_as_ushort(h1) << 16);
    H.y = (uint32_t)__half_as_ushort(h2) | ((uint32_t)__half_as_ushort(h3) << 16);
    L.x = (uint32_t)__half_as_ushort(l0) | ((uint32_t)__half_as_ushort(l1) << 16);
    L.y = (uint32_t)__half_as_ushort(l2) | ((uint32_t)__half_as_ushort(l3) << 16);
    hi[i] = H;
    lo[i] = L;
}

// ---------------- fp32 -> fp16 round (weights, 4 at once) -------------------
__global__ __launch_bounds__(256) void wconv_kernel(const float4* __restrict__ w0,
                                                    const float4* __restrict__ w1,
                                                    const float4* __restrict__ w2,
                                                    const float4* __restrict__ w3,
                                                    uint2* __restrict__ o0,
                                                    uint2* __restrict__ o1,
                                                    uint2* __restrict__ o2,
                                                    uint2* __restrict__ o3, int n4)
{
    int i = blockIdx.x * blockDim.x + threadIdx.x;
    if (i >= n4) return;
    const float4* src = (blockIdx.y == 0) ? w0 : (blockIdx.y == 1) ? w1
                        : (blockIdx.y == 2) ? w2 : w3;
    uint2* dst = (blockIdx.y == 0) ? o0 : (blockIdx.y == 1) ? o1
                 : (blockIdx.y == 2) ? o2 : o3;
    float4 v = src[i];
    uint2 H;
    H.x = (uint32_t)__half_as_ushort(__float2half_rn(v.x)) |
          ((uint32_t)__half_as_ushort(__float2half_rn(v.y)) << 16);
    H.y = (uint32_t)__half_as_ushort(__float2half_rn(v.z)) |
          ((uint32_t)__half_as_ushort(__float2half_rn(v.w)) << 16);
    dst[i] = H;
}

// ---------------- fp16x2 warp-MMA GEMM (512 threads, BM128 x BN256) ----------
__device__ __forceinline__ void load_stage(uint32_t sbase,
    const __half* __restrict__ Ah, const __half* __restrict__ Al,
    const __half* __restrict__ Bh,
    int m0, int n0, int kc, int tid)
{
    const int kcol = kc * BK;
    #pragma unroll
    for (int i = 0; i < 2; ++i) {               // A: 128 rows x 8 ch = 1024
        int idx = tid + i * 512;
        int row = idx >> 3;
        int ch  = idx & 7;
        uint32_t soff = row * 128 + (((ch ^ (row & 7)) << 4));
        size_t ga = (size_t)(m0 + row) * DIMW + kcol + ch * 8;
        cp16(sbase + soff,            Ah + ga);
        cp16(sbase + A_TILE_B + soff, Al + ga);
    }
    #pragma unroll
    for (int i = 0; i < 4; ++i) {               // B: 256 rows x 8 ch = 2048
        int idx = tid + i * 512;
        int row = idx >> 3;
        int ch  = idx & 7;
        uint32_t soff = row * 128 + (((ch ^ (row & 7)) << 4));
        size_t gb = (size_t)(n0 + row) * DIMW + kcol + ch * 8;
        cp16(sbase + 2 * A_TILE_B + soff, Bh + gb);
    }
    cp_commit();
}

__device__ __forceinline__ void gemm_body(
    const __half* __restrict__ Ah, const __half* __restrict__ Al,
    const __half* __restrict__ Bh,
    float* __restrict__ C, const float* __restrict__ Yadd,
    const float* __restrict__ bias, bool epi)
{
    extern __shared__ char dsm[];
    const uint32_t sb = smem_u32(dsm);

    const int tid  = threadIdx.x;
    const int wid  = tid >> 5;
    const int lane = tid & 31;
    const int warp_m = wid >> 2;      // 0..3 -> 32 rows each
    const int warp_n = wid & 3;       // 0..3 -> 64 cols each
    const int m0 = blockIdx.y * BM;
    const int n0 = blockIdx.x * BN;

    float acc[2][8][4];
    #pragma unroll
    for (int a = 0; a < 2; ++a)
        #pragma unroll
        for (int b = 0; b < 8; ++b)
            #pragma unroll
            for (int c = 0; c < 4; ++c) acc[a][b][c] = 0.f;

    #pragma unroll
    for (int s = 0; s < NSTAGE; ++s)
        load_stage(sb + s * STAGE_B, Ah, Al, Bh, m0, n0, s, tid);

    const int frag_row = lane & 15;
    const int frag_ch  = lane >> 4;

    #pragma unroll 1
    for (int kc = 0; kc < NKC; ++kc) {
        cp_wait<NSTAGE - 1>();
        __syncthreads();

        const uint32_t st  = sb + (kc % NSTAGE) * STAGE_B;
        const uint32_t sAh = st;
        const uint32_t sAl = st + A_TILE_B;
        const uint32_t sBh = st + 2 * A_TILE_B;

        #pragma unroll
        for (int kk = 0; kk < 4; ++kk) {
            uint32_t ah[2][4], al[2][4];
            #pragma unroll
            for (int mi = 0; mi < 2; ++mi) {
                int row = warp_m * 32 + mi * 16 + frag_row;
                int ch  = kk * 2 + frag_ch;
                uint32_t off = row * 128 + (((ch ^ (row & 7)) << 4));
                ldsm4(ah[mi], sAh + off);
                ldsm4(al[mi], sAl + off);
            }
            uint32_t bh[4][4];
            #pragma unroll
            for (int ng = 0; ng < 4; ++ng) {
                int row = warp_n * 64 + ng * 16 + frag_row;
                int ch  = kk * 2 + frag_ch;
                uint32_t off = row * 128 + (((ch ^ (row & 7)) << 4));
                ldsm4(bh[ng], sBh + off);
            }
            #pragma unroll
            for (int mi = 0; mi < 2; ++mi)
                #pragma unroll
                for (int ng = 0; ng < 4; ++ng) {
                    mma16816(acc[mi][ng * 2],     ah[mi], bh[ng][0], bh[ng][2]);
                    mma16816(acc[mi][ng * 2],     al[mi], bh[ng][0], bh[ng][2]);
                    mma16816(acc[mi][ng * 2 + 1], ah[mi], bh[ng][1], bh[ng][3]);
                    mma16816(acc[mi][ng * 2 + 1], al[mi], bh[ng][1], bh[ng][3]);
                }
        }

        __syncthreads();
        if (kc + NSTAGE < NKC)
            load_stage(sb + (kc % NSTAGE) * STAGE_B, Ah, Al, Bh,
                       m0, n0, kc + NSTAGE, tid);
    }

    const int erow = lane >> 2;
    const int ecol = (lane & 3) * 2;
    #pragma unroll
    for (int mi = 0; mi < 2; ++mi) {
        #pragma unroll
        for (int ni = 0; ni < 8; ++ni) {
            size_t r0 = (size_t)m0 + warp_m * 32 + mi * 16 + erow;
            int    c  = n0 + warp_n * 64 + ni * 8 + ecol;
            float2 v0 = make_float2(acc[mi][ni][0], acc[mi][ni][1]);
            float2 v1 = make_float2(acc[mi][ni][2], acc[mi][ni][3]);
            if (epi) {
                float2 y0 = *(const float2*)(Yadd + r0 * DIMW + c);
                float2 y1 = *(const float2*)(Yadd + (r0 + 8) * DIMW + c);
                float2 bv = *(const float2*)(bias + c);
                v0.x += y0.x + bv.x; v0.y += y0.y + bv.y;
                v1.x += y1.x + bv.x; v1.y += y1.y + bv.y;
            }
            *(float2*)(C + r0 * DIMW + c)       = v0;
            *(float2*)(C + (r0 + 8) * DIMW + c) = v1;
        }
    }
}

__global__ __launch_bounds__(512, 1) void qkv_gemm()
{
    if (blockIdx.z == 0)
        gemm_body(g_yh, g_yl, g_Wq, g_q, nullptr, nullptr, false);
    else if (blockIdx.z == 1)
        gemm_body(g_xh, g_xl, g_Wk, g_k, nullptr, nullptr, false);
    else
        gemm_body(g_xh, g_xl, g_Wv, g_v, nullptr, nullptr, false);
}

__global__ __launch_bounds__(512, 1) void out_gemm(const float* __restrict__ y,
                                                   const float* __restrict__ bout,
                                                   float* __restrict__ ynew)
{
    gemm_body(g_oh, g_ol, g_Wo, ynew, y, bout, true);
}

// ---------------- LayerNorm over rows of 512 (in place on g_q / g_k) --------
__global__ __launch_bounds__(256) void ln_kernel(const float* __restrict__ gq,
                                                 const float* __restrict__ bq,
                                                 const float* __restrict__ gk,
                                                 const float* __restrict__ bk)
{
    float*       buf = (blockIdx.y == 0) ? g_q : g_k;
    const float* g   = (blockIdx.y == 0) ? gq  : gk;
    const float* b   = (blockIdx.y == 0) ? bq  : bk;
    const size_t row = blockIdx.x;
    const int tid = threadIdx.x;

    float2 v = *(float2*)(buf + row * DIMW + tid * 2);
    float s  = v.x + v.y;
    float sq = v.x * v.x + v.y * v.y;
    #pragma unroll
    for (int o = 16; o > 0; o >>= 1) {
        s  += __shfl_xor_sync(0xffffffffu, s,  o);
        sq += __shfl_xor_sync(0xffffffffu, sq, o);
    }
    __shared__ float ss[8], ssq[8];
    if ((tid & 31) == 0) { ss[tid >> 5] = s; ssq[tid >> 5] = sq; }
    __syncthreads();
    s = 0.f; sq = 0.f;
    #pragma unroll
    for (int i = 0; i < 8; ++i) { s += ss[i]; sq += ssq[i]; }

    float mean = s * (1.f / 512.f);
    float var  = sq * (1.f / 512.f) - mean * mean;
    float rstd = rsqrtf(var + 1e-5f);
    int c = tid * 2;
    float2 o;
    o.x = (v.x - mean) * rstd * g[c]     + b[c];
    o.y = (v.y - mean) * rstd * g[c + 1] + b[c + 1];
    *(float2*)(buf + row * DIMW + c) = o;
}

// ---------------- windowed attention (FFMA2), 2 blocks/SM --------------------
#define QS  65
#define KTS 130
#define VSS 66
#define ATTN_SMEM ((128 * QS + 64 * KTS + 128 * VSS) * 4)   // 100,352 B

__global__ __launch_bounds__(256, 2) void attn_kernel(float* __restrict__ attn_out)
{
    extern __shared__ float sm[];
    float* qs = sm;                    // [128][QS]
    float* kt = qs + 128 * QS;         // [64][KTS]  (kt[d][j])
    float* vs = kt + 64 * KTS;         // [128][VSS]

    const int tid = threadIdx.x;
    const int bwh = blockIdx.x;        // bw*8 + h
    const int bw  = bwh >> 3;
    const int h   = bwh & 7;
    const size_t rowbase = (size_t)bw * WIN;
    const int coloff = h * DHEAD;

    #pragma unroll
    for (int it = 0; it < 8; ++it) {
        int idx = tid + it * 256;
        int i   = idx >> 4;
        int d4  = (idx & 15) << 2;
        size_t goff = (rowbase + i) * DIMW + coloff + d4;
        float4 qv = *(const float4*)(g_q + goff);
        float4 kv = *(const float4*)(g_k + goff);
        float4 vv = *(const float4*)(g_v + goff);
        float* qd = qs + i * QS + d4;
        qd[0] = qv.x; qd[1] = qv.y; qd[2] = qv.z; qd[3] = qv.w;
        kt[(d4 + 0) * KTS + i] = kv.x;
        kt[(d4 + 1) * KTS + i] = kv.y;
        kt[(d4 + 2) * KTS + i] = kv.z;
        kt[(d4 + 3) * KTS + i] = kv.w;
        float* vd = vs + i * VSS + d4;
        vd[0] = vv.x; vd[1] = vv.y; vd[2] = vv.z; vd[3] = vv.w;
    }
    __syncthreads();

    const int rg = tid >> 3;
    const int cg = tid & 7;

    // QK^T : acc2[r][c] holds j = 16c + 2cg + {0,1}
    unsigned long long acc2[4][8];
    #pragma unroll
    for (int r = 0; r < 4; ++r)
        #pragma unroll
        for (int c = 0; c < 8; ++c) acc2[r][c] = 0ull;

    #pragma unroll 4
    for (int d = 0; d < 64; ++d) {
        unsigned long long qv2[4];
        #pragma unroll
        for (int r = 0; r < 4; ++r) {
            float q = qs[(rg + 32 * r) * QS + d];
            qv2[r] = pack2(q, q);
        }
        unsigned long long kv2[8];
        #pragma unroll
        for (int c = 0; c < 8; ++c)
            kv2[c] = *reinterpret_cast<const unsigned long long*>(
                         kt + d * KTS + 16 * c + 2 * cg);
        #pragma unroll
        for (int r = 0; r < 4; ++r)
            #pragma unroll
            for (int c = 0; c < 8; ++c)
                fma2(acc2[r][c], qv2[r], kv2[c]);
    }

    // softmax per row + write attn
    float pacc[4][16];
    const size_t abase = (size_t)bwh * WIN * WIN;
    #pragma unroll
    for (int r = 0; r < 4; ++r) {
        #pragma unroll
        for (int c = 0; c < 8; ++c) {
            float a, b;
            unpack2(acc2[r][c], a, b);
            pacc[r][2 * c]     = a * 0.125f;
            pacc[r][2 * c + 1] = b * 0.125f;
        }
        float mx = -1e30f;
        #pragma unroll
        for (int c = 0; c < 16; ++c) mx = fmaxf(mx, pacc[r][c]);
        #pragma unroll
        for (int o = 1; o < 8; o <<= 1)
            mx = fmaxf(mx, __shfl_xor_sync(0xffffffffu, mx, o, 8));
        float sum = 0.f;
        #pragma unroll
        for (int c = 0; c < 16; ++c) {
            pacc[r][c] = __expf(pacc[r][c] - mx);
            sum += pacc[r][c];
        }
        #pragma unroll
        for (int o = 1; o < 8; o <<= 1)
            sum += __shfl_xor_sync(0xffffffffu, sum, o, 8);
        float inv = 1.0f / sum;
        int i = rg + 32 * r;
        #pragma unroll
        for (int c = 0; c < 8; ++c) {
            pacc[r][2 * c]     *= inv;
            pacc[r][2 * c + 1] *= inv;
            float2 pw = make_float2(pacc[r][2 * c], pacc[r][2 * c + 1]);
            *reinterpret_cast<float2*>(
                attn_out + abase + (size_t)i * WIN + 16 * c + 2 * cg) = pw;
        }
    }

    // P @ V : oacc2[r][c] holds d = 16c + 2cg + {0,1}
    unsigned long long oacc2[4][4];
    #pragma unroll
    for (int r = 0; r < 4; ++r)
        #pragma unroll
        for (int c = 0; c < 4; ++c) oacc2[r][c] = 0ull;

    #pragma unroll
    for (int j = 0; j < 128; ++j) {
        const int cg_src = (j >> 1) & 7;
        const int cidx   = ((j >> 4) << 1) | (j & 1);
        unsigned long long vv2[4];
        #pragma unroll
        for (int c = 0; c < 4; ++c)
            vv2[c] = *reinterpret_cast<const unsigned long long*>(
                         vs + j * VSS + 16 * c + 2 * cg);
        #pragma unroll
        for (int r = 0; r < 4; ++r) {
            float p = __shfl_sync(0xffffffffu, pacc[r][cidx], cg_src, 8);
            unsigned long long av2 = pack2(p, p);
            #pragma unroll
            for (int c = 0; c < 4; ++c)
                fma2(oacc2[r][c], av2, vv2[c]);
        }
    }

    // epilogue: split to fp16 hi/lo directly (feeds out_gemm)
    #pragma unroll
    for (int r = 0; r < 4; ++r) {
        int i = rg + 32 * r;
        size_t go = (rowbase + i) * DIMW + coloff;
        #pragma unroll
        for (int c = 0; c < 4; ++c) {
            float o0, o1;
            unpack2(oacc2[r][c], o0, o1);
            __half h0 = __float2half_rn(o0);
            __half h1 = __float2half_rn(o1);
            __half l0 = __float2half_rn(o0 - __half2float(h0));
            __half l1 = __float2half_rn(o1 - __half2float(h1));
            __half2 H; H.x = h0; H.y = h1;
            __half2 L; L.x = l0; L.y = l1;
            *reinterpret_cast<__half2*>(g_oh + go + 16 * c + 2 * cg) = H;
            *reinterpret_cast<__half2*>(g_ol + go + 16 * c + 2 * cg) = L;
        }
    }
}

// ---------------- launcher ---------------------------------------------------
extern "C" void kernel_launch(void* const* d_in, const int* in_sizes, int n_in,
                              void* d_out, int out_size)
{
    const float* x  = (const float*)d_in[0];
    const float* y  = (const float*)d_in[1];
    const float* Wq = (const float*)d_in[2];
    const float* gq = (const float*)d_in[3];
    const float* bq = (const float*)d_in[4];
    const float* Wk = (const float*)d_in[5];
    const float* gk = (const float*)d_in[6];
    const float* bk = (const float*)d_in[7];
    const float* Wv = (const float*)d_in[8];
    const float* Wo = (const float*)d_in[9];
    const float* bo = (const float*)d_in[10];

    float* ynew = (float*)d_out;
    float* attn = ynew + (size_t)M_TOT * DIMW;

    void *p_xh, *p_xl, *p_yh, *p_yl;
    void *p_wq, *p_wk, *p_wv, *p_wo;
    cudaGetSymbolAddress(&p_xh, g_xh);  cudaGetSymbolAddress(&p_xl, g_xl);
    cudaGetSymbolAddress(&p_yh, g_yh);  cudaGetSymbolAddress(&p_yl, g_yl);
    cudaGetSymbolAddress(&p_wq, g_Wq);  cudaGetSymbolAddress(&p_wk, g_Wk);
    cudaGetSymbolAddress(&p_wv, g_Wv);  cudaGetSymbolAddress(&p_wo, g_Wo);

    cudaFuncSetAttribute(attn_kernel,
                         cudaFuncAttributeMaxDynamicSharedMemorySize, ATTN_SMEM);
    cudaFuncSetAttribute(qkv_gemm,
                         cudaFuncAttributeMaxDynamicSharedMemorySize, GEMM_SMEM);
    cudaFuncSetAttribute(out_gemm,
                         cudaFuncAttributeMaxDynamicSharedMemorySize, GEMM_SMEM);

    // 1) split activations into fp16 hi/lo; round weights to fp16
    const int n4_act = (M_TOT * DIMW) / 4;
    const int n4_w   = (DIMW * DIMW) / 4;
    split_kernel<<<(n4_act + 255) / 256, 256>>>((const float4*)x,
        (uint2*)p_xh, (uint2*)p_xl, n4_act);
    split_kernel<<<(n4_act + 255) / 256, 256>>>((const float4*)y,
        (uint2*)p_yh, (uint2*)p_yl, n4_act);
    wconv_kernel<<<dim3((n4_w + 255) / 256, 4), 256>>>(
        (const float4*)Wq, (const float4*)Wk, (const float4*)Wv, (const float4*)Wo,
        (uint2*)p_wq, (uint2*)p_wk, (uint2*)p_wv, (uint2*)p_wo, n4_w);

    // 2) q/k/v projections (warp-MMA fp16x2)
    qkv_gemm<<<dim3(DIMW / BN, M_TOT / BM, 3), 512, GEMM_SMEM>>>();

    // 3) LN on q, k
    ln_kernel<<<dim3(M_TOT, 2), 256>>>(gq, bq, gk, bk);

    // 4) windowed attention (FFMA2) -> attn out + fp16 hi/lo of o
    attn_kernel<<<4096, 256, ATTN_SMEM>>>(attn);

    // 5) final projection with residual epilogue
    out_gemm<<<dim3(DIMW / BN, M_TOT / BM), 512, GEMM_SMEM>>>(y, bo, ynew);
}

// round 8
// speedup vs baseline: 3.3501x; 1.3148x over previous
#include <cuda_runtime.h>
#include <cuda_fp16.h>
#include <cstdint>

#define M_TOT 65536      // B*N rows
#define DIMW  512        // DIM == INNER
#define WIN   128
#define NHEAD 8
#define DHEAD 64

// GEMM tiling (warp-MMA, mma.sync m16n8k16 fp16, pure fp16 operands)
#define BM 128
#define BN 256
#define BK 64                        // fp16 elems per k-chunk (128 bytes/row)
#define NKC (DIMW / BK)              // 8 chunks
#define A_TILE_B (BM * 128)          // 16384 bytes
#define B_TILE_B (BN * 128)          // 32768 bytes
#define STAGE_B (A_TILE_B + B_TILE_B)           // 48 KB
#define NSTAGE 4
#define GEMM_SMEM (NSTAGE * STAGE_B)            // 192 KB

// ---------------- scratch (__device__ globals; no allocation allowed) -------
__device__ float g_q[(size_t)M_TOT * DIMW];
__device__ float g_k[(size_t)M_TOT * DIMW];
__device__ float g_v[(size_t)M_TOT * DIMW];

__device__ __half g_xh[(size_t)M_TOT * DIMW];
__device__ __half g_yh[(size_t)M_TOT * DIMW];
__device__ __half g_oh[(size_t)M_TOT * DIMW];

__device__ __half g_Wq[DIMW * DIMW];
__device__ __half g_Wk[DIMW * DIMW];
__device__ __half g_Wv[DIMW * DIMW];
__device__ __half g_Wo[DIMW * DIMW];

// ---------------- small asm helpers ------------------------------------------
__device__ __forceinline__ uint32_t smem_u32(const void* p) {
    uint32_t a;
    asm("{ .reg .u64 t; cvta.to.shared.u64 t, %1; cvt.u32.u64 %0, t; }"
        : "=r"(a) : "l"(p));
    return a;
}
__device__ __forceinline__ void cp16(uint32_t dst, const void* src) {
    asm volatile("cp.async.cg.shared.global [%0], [%1], 16;"
                 :: "r"(dst), "l"(src) : "memory");
}
__device__ __forceinline__ void cp_commit() {
    asm volatile("cp.async.commit_group;" ::: "memory");
}
template <int N>
__device__ __forceinline__ void cp_wait() {
    asm volatile("cp.async.wait_group %0;" :: "n"(N) : "memory");
}
__device__ __forceinline__ void ldsm4(uint32_t* r, uint32_t addr) {
    asm volatile("ldmatrix.sync.aligned.m8n8.x4.shared.b16 {%0,%1,%2,%3}, [%4];"
                 : "=r"(r[0]), "=r"(r[1]), "=r"(r[2]), "=r"(r[3]) : "r"(addr));
}
__device__ __forceinline__ void mma16816(float* d, const uint32_t* a,
                                         uint32_t b0, uint32_t b1) {
    asm volatile(
        "mma.sync.aligned.m16n8k16.row.col.f32.f16.f16.f32 "
        "{%0,%1,%2,%3}, {%4,%5,%6,%7}, {%8,%9}, {%0,%1,%2,%3};"
        : "+f"(d[0]), "+f"(d[1]), "+f"(d[2]), "+f"(d[3])
        : "r"(a[0]), "r"(a[1]), "r"(a[2]), "r"(a[3]), "r"(b0), "r"(b1));
}
// packed fp32x2 helpers (Blackwell)
__device__ __forceinline__ unsigned long long pack2(float a, float b) {
    unsigned long long r;
    asm("mov.b64 %0, {%1, %2};" : "=l"(r) : "f"(a), "f"(b));
    return r;
}
__device__ __forceinline__ void unpack2(unsigned long long v, float& a, float& b) {
    asm("mov.b64 {%0, %1}, %2;" : "=f"(a), "=f"(b) : "l"(v));
}
__device__ __forceinline__ void fma2(unsigned long long& d,
                                     unsigned long long a, unsigned long long b) {
    asm("fma.rn.f32x2 %0, %1, %2, %0;" : "+l"(d) : "l"(a), "l"(b));
}

// ---------------- fp32 -> fp16 convert (x, y activations) -------------------
__global__ __launch_bounds__(256) void cvt_kernel(const float4* __restrict__ in0,
                                                  const float4* __restrict__ in1,
                                                  uint2* __restrict__ o0,
                                                  uint2* __restrict__ o1, int n4)
{
    int i = blockIdx.x * blockDim.x + threadIdx.x;
    if (i >= n4) return;
    const float4* src = blockIdx.y ? in1 : in0;
    uint2* dst = blockIdx.y ? o1 : o0;
    float4 v = src[i];
    uint2 H;
    H.x = (uint32_t)__half_as_ushort(__float2half_rn(v.x)) |
          ((uint32_t)__half_as_ushort(__float2half_rn(v.y)) << 16);
    H.y = (uint32_t)__half_as_ushort(__float2half_rn(v.z)) |
          ((uint32_t)__half_as_ushort(__float2half_rn(v.w)) << 16);
    dst[i] = H;
}

// ---------------- fp32 -> fp16 round (weights, 4 at once) -------------------
__global__ __launch_bounds__(256) void wconv_kernel(const float4* __restrict__ w0,
                                                    const float4* __restrict__ w1,
                                                    const float4* __restrict__ w2,
                                                    const float4* __restrict__ w3,
                                                    uint2* __restrict__ o0,
                                                    uint2* __restrict__ o1,
                                                    uint2* __restrict__ o2,
                                                    uint2* __restrict__ o3, int n4)
{
    int i = blockIdx.x * blockDim.x + threadIdx.x;
    if (i >= n4) return;
    const float4* src = (blockIdx.y == 0) ? w0 : (blockIdx.y == 1) ? w1
                        : (blockIdx.y == 2) ? w2 : w3;
    uint2* dst = (blockIdx.y == 0) ? o0 : (blockIdx.y == 1) ? o1
                 : (blockIdx.y == 2) ? o2 : o3;
    float4 v = src[i];
    uint2 H;
    H.x = (uint32_t)__half_as_ushort(__float2half_rn(v.x)) |
          ((uint32_t)__half_as_ushort(__float2half_rn(v.y)) << 16);
    H.y = (uint32_t)__half_as_ushort(__float2half_rn(v.z)) |
          ((uint32_t)__half_as_ushort(__float2half_rn(v.w)) << 16);
    dst[i] = H;
}

// ---------------- fp16 warp-MMA GEMM (512 threads, BM128 x BN256) ------------
__device__ __forceinline__ void load_stage(uint32_t sbase,
    const __half* __restrict__ A, const __half* __restrict__ B,
    int m0, int n0, int kc, int tid)
{
    const int kcol = kc * BK;
    #pragma unroll
    for (int i = 0; i < 2; ++i) {               // A: 128 rows x 8 ch = 1024
        int idx = tid + i * 512;
        int row = idx >> 3;
        int ch  = idx & 7;
        uint32_t soff = row * 128 + (((ch ^ (row & 7)) << 4));
        size_t ga = (size_t)(m0 + row) * DIMW + kcol + ch * 8;
        cp16(sbase + soff, A + ga);
    }
    #pragma unroll
    for (int i = 0; i < 4; ++i) {               // B: 256 rows x 8 ch = 2048
        int idx = tid + i * 512;
        int row = idx >> 3;
        int ch  = idx & 7;
        uint32_t soff = row * 128 + (((ch ^ (row & 7)) << 4));
        size_t gb = (size_t)(n0 + row) * DIMW + kcol + ch * 8;
        cp16(sbase + A_TILE_B + soff, B + gb);
    }
    cp_commit();
}

__device__ __forceinline__ void gemm_body(
    const __half* __restrict__ A, const __half* __restrict__ B,
    float* __restrict__ C, const float* __restrict__ Yadd,
    const float* __restrict__ bias, bool epi)
{
    extern __shared__ char dsm[];
    const uint32_t sb = smem_u32(dsm);

    const int tid  = threadIdx.x;
    const int wid  = tid >> 5;
    const int lane = tid & 31;
    const int warp_m = wid >> 2;      // 0..3 -> 32 rows each
    const int warp_n = wid & 3;       // 0..3 -> 64 cols each
    const int m0 = blockIdx.y * BM;
    const int n0 = blockIdx.x * BN;

    float acc[2][8][4];
    #pragma unroll
    for (int a = 0; a < 2; ++a)
        #pragma unroll
        for (int b = 0; b < 8; ++b)
            #pragma unroll
            for (int c = 0; c < 4; ++c) acc[a][b][c] = 0.f;

    #pragma unroll
    for (int s = 0; s < NSTAGE - 1; ++s)
        load_stage(sb + s * STAGE_B, A, B, m0, n0, s, tid);

    const int frag_row = lane & 15;
    const int frag_ch  = lane >> 4;

    #pragma unroll 1
    for (int kc = 0; kc < NKC; ++kc) {
        cp_wait<NSTAGE - 2>();
        __syncthreads();

        const uint32_t st = sb + (kc % NSTAGE) * STAGE_B;
        const uint32_t sA = st;
        const uint32_t sB = st + A_TILE_B;

        #pragma unroll
        for (int kk = 0; kk < 4; ++kk) {
            uint32_t ah[2][4];
            #pragma unroll
            for (int mi = 0; mi < 2; ++mi) {
                int row = warp_m * 32 + mi * 16 + frag_row;
                int ch  = kk * 2 + frag_ch;
                uint32_t off = row * 128 + (((ch ^ (row & 7)) << 4));
                ldsm4(ah[mi], sA + off);
            }
            uint32_t bh[4][4];
            #pragma unroll
            for (int ng = 0; ng < 4; ++ng) {
                int row = warp_n * 64 + ng * 16 + frag_row;
                int ch  = kk * 2 + frag_ch;
                uint32_t off = row * 128 + (((ch ^ (row & 7)) << 4));
                ldsm4(bh[ng], sB + off);
            }
            #pragma unroll
            for (int mi = 0; mi < 2; ++mi)
                #pragma unroll
                for (int ng = 0; ng < 4; ++ng) {
                    mma16816(acc[mi][ng * 2],     ah[mi], bh[ng][0], bh[ng][2]);
                    mma16816(acc[mi][ng * 2 + 1], ah[mi], bh[ng][1], bh[ng][3]);
                }
        }

        __syncthreads();
        if (kc + NSTAGE - 1 < NKC)
            load_stage(sb + ((kc + NSTAGE - 1) % NSTAGE) * STAGE_B, A, B,
                       m0, n0, kc + NSTAGE - 1, tid);
    }

    const int erow = lane >> 2;
    const int ecol = (lane & 3) * 2;
    #pragma unroll
    for (int mi = 0; mi < 2; ++mi) {
        #pragma unroll
        for (int ni = 0; ni < 8; ++ni) {
            size_t r0 = (size_t)m0 + warp_m * 32 + mi * 16 + erow;
            int    c  = n0 + warp_n * 64 + ni * 8 + ecol;
            float2 v0 = make_float2(acc[mi][ni][0], acc[mi][ni][1]);
            float2 v1 = make_float2(acc[mi][ni][2], acc[mi][ni][3]);
            if (epi) {
                float2 y0 = *(const float2*)(Yadd + r0 * DIMW + c);
                float2 y1 = *(const float2*)(Yadd + (r0 + 8) * DIMW + c);
                float2 bv = *(const float2*)(bias + c);
                v0.x += y0.x + bv.x; v0.y += y0.y + bv.y;
                v1.x += y1.x + bv.x; v1.y += y1.y + bv.y;
            }
            *(float2*)(C + r0 * DIMW + c)       = v0;
            *(float2*)(C + (r0 + 8) * DIMW + c) = v1;
        }
    }
}

__global__ __launch_bounds__(512, 1) void qkv_gemm()
{
    if (blockIdx.z == 0)
        gemm_body(g_yh, g_Wq, g_q, nullptr, nullptr, false);
    else if (blockIdx.z == 1)
        gemm_body(g_xh, g_Wk, g_k, nullptr, nullptr, false);
    else
        gemm_body(g_xh, g_Wv, g_v, nullptr, nullptr, false);
}

__global__ __launch_bounds__(512, 1) void out_gemm(const float* __restrict__ y,
                                                   const float* __restrict__ bout,
                                                   float* __restrict__ ynew)
{
    gemm_body(g_oh, g_Wo, ynew, y, bout, true);
}

// ---------------- LayerNorm over rows of 512 (in place on g_q / g_k) --------
__global__ __launch_bounds__(256) void ln_kernel(const float* __restrict__ gq,
                                                 const float* __restrict__ bq,
                                                 const float* __restrict__ gk,
                                                 const float* __restrict__ bk)
{
    float*       buf = (blockIdx.y == 0) ? g_q : g_k;
    const float* g   = (blockIdx.y == 0) ? gq  : gk;
    const float* b   = (blockIdx.y == 0) ? bq  : bk;
    const size_t row = blockIdx.x;
    const int tid = threadIdx.x;

    float2 v = *(float2*)(buf + row * DIMW + tid * 2);
    float s  = v.x + v.y;
    float sq = v.x * v.x + v.y * v.y;
    #pragma unroll
    for (int o = 16; o > 0; o >>= 1) {
        s  += __shfl_xor_sync(0xffffffffu, s,  o);
        sq += __shfl_xor_sync(0xffffffffu, sq, o);
    }
    __shared__ float ss[8], ssq[8];
    if ((tid & 31) == 0) { ss[tid >> 5] = s; ssq[tid >> 5] = sq; }
    __syncthreads();
    s = 0.f; sq = 0.f;
    #pragma unroll
    for (int i = 0; i < 8; ++i) { s += ss[i]; sq += ssq[i]; }

    float mean = s * (1.f / 512.f);
    float var  = sq * (1.f / 512.f) - mean * mean;
    float rstd = rsqrtf(var + 1e-5f);
    int c = tid * 2;
    float2 o;
    o.x = (v.x - mean) * rstd * g[c]     + b[c];
    o.y = (v.y - mean) * rstd * g[c + 1] + b[c + 1];
    *(float2*)(buf + row * DIMW + c) = o;
}

// ---------------- windowed attention (FFMA2), 2 blocks/SM --------------------
#define QS  65
#define KTS 130
#define VSS 66
#define ATTN_SMEM ((128 * QS + 64 * KTS + 128 * VSS) * 4)   // 100,352 B

__global__ __launch_bounds__(256, 2) void attn_kernel(float* __restrict__ attn_out)
{
    extern __shared__ float sm[];
    float* qs = sm;                    // [128][QS]
    float* kt = qs + 128 * QS;         // [64][KTS]  (kt[d][j])
    float* vs = kt + 64 * KTS;         // [128][VSS]

    const int tid = threadIdx.x;
    const int bwh = blockIdx.x;        // bw*8 + h
    const int bw  = bwh >> 3;
    const int h   = bwh & 7;
    const size_t rowbase = (size_t)bw * WIN;
    const int coloff = h * DHEAD;

    #pragma unroll
    for (int it = 0; it < 8; ++it) {
        int idx = tid + it * 256;
        int i   = idx >> 4;
        int d4  = (idx & 15) << 2;
        size_t goff = (rowbase + i) * DIMW + coloff + d4;
        float4 qv = *(const float4*)(g_q + goff);
        float4 kv = *(const float4*)(g_k + goff);
        float4 vv = *(const float4*)(g_v + goff);
        float* qd = qs + i * QS + d4;
        qd[0] = qv.x; qd[1] = qv.y; qd[2] = qv.z; qd[3] = qv.w;
        kt[(d4 + 0) * KTS + i] = kv.x;
        kt[(d4 + 1) * KTS + i] = kv.y;
        kt[(d4 + 2) * KTS + i] = kv.z;
        kt[(d4 + 3) * KTS + i] = kv.w;
        float* vd = vs + i * VSS + d4;
        vd[0] = vv.x; vd[1] = vv.y; vd[2] = vv.z; vd[3] = vv.w;
    }
    __syncthreads();

    const int rg = tid >> 3;
    const int cg = tid & 7;

    // QK^T : acc2[r][c] holds j = 16c + 2cg + {0,1}
    unsigned long long acc2[4][8];
    #pragma unroll
    for (int r = 0; r < 4; ++r)
        #pragma unroll
        for (int c = 0; c < 8; ++c) acc2[r][c] = 0ull;

    #pragma unroll 4
    for (int d = 0; d < 64; ++d) {
        unsigned long long qv2[4];
        #pragma unroll
        for (int r = 0; r < 4; ++r) {
            float q = qs[(rg + 32 * r) * QS + d];
            qv2[r] = pack2(q, q);
        }
        unsigned long long kv2[8];
        #pragma unroll
        for (int c = 0; c < 8; ++c)
            kv2[c] = *reinterpret_cast<const unsigned long long*>(
                         kt + d * KTS + 16 * c + 2 * cg);
        #pragma unroll
        for (int r = 0; r < 4; ++r)
            #pragma unroll
            for (int c = 0; c < 8; ++c)
                fma2(acc2[r][c], qv2[r], kv2[c]);
    }

    // softmax per row + write attn
    float pacc[4][16];
    const size_t abase = (size_t)bwh * WIN * WIN;
    #pragma unroll
    for (int r = 0; r < 4; ++r) {
        #pragma unroll
        for (int c = 0; c < 8; ++c) {
            float a, b;
            unpack2(acc2[r][c], a, b);
            pacc[r][2 * c]     = a * 0.125f;
            pacc[r][2 * c + 1] = b * 0.125f;
        }
        float mx = -1e30f;
        #pragma unroll
        for (int c = 0; c < 16; ++c) mx = fmaxf(mx, pacc[r][c]);
        #pragma unroll
        for (int o = 1; o < 8; o <<= 1)
            mx = fmaxf(mx, __shfl_xor_sync(0xffffffffu, mx, o, 8));
        float sum = 0.f;
        #pragma unroll
        for (int c = 0; c < 16; ++c) {
            pacc[r][c] = __expf(pacc[r][c] - mx);
            sum += pacc[r][c];
        }
        #pragma unroll
        for (int o = 1; o < 8; o <<= 1)
            sum += __shfl_xor_sync(0xffffffffu, sum, o, 8);
        float inv = 1.0f / sum;
        int i = rg + 32 * r;
        #pragma unroll
        for (int c = 0; c < 8; ++c) {
            pacc[r][2 * c]     *= inv;
            pacc[r][2 * c + 1] *= inv;
            float2 pw = make_float2(pacc[r][2 * c], pacc[r][2 * c + 1]);
            *reinterpret_cast<float2*>(
                attn_out + abase + (size_t)i * WIN + 16 * c + 2 * cg) = pw;
        }
    }

    // P @ V : oacc2[r][c] holds d = 16c + 2cg + {0,1}
    unsigned long long oacc2[4][4];
    #pragma unroll
    for (int r = 0; r < 4; ++r)
        #pragma unroll
        for (int c = 0; c < 4; ++c) oacc2[r][c] = 0ull;

    #pragma unroll
    for (int j = 0; j < 128; ++j) {
        const int cg_src = (j >> 1) & 7;
        const int cidx   = ((j >> 4) << 1) | (j & 1);
        unsigned long long vv2[4];
        #pragma unroll
        for (int c = 0; c < 4; ++c)
            vv2[c] = *reinterpret_cast<const unsigned long long*>(
                         vs + j * VSS + 16 * c + 2 * cg);
        #pragma unroll
        for (int r = 0; r < 4; ++r) {
            float p = __shfl_sync(0xffffffffu, pacc[r][cidx], cg_src, 8);
            unsigned long long av2 = pack2(p, p);
            #pragma unroll
            for (int c = 0; c < 4; ++c)
                fma2(oacc2[r][c], av2, vv2[c]);
        }
    }

    // epilogue: convert o to fp16 directly (feeds out_gemm)
    #pragma unroll
    for (int r = 0; r < 4; ++r) {
        int i = rg + 32 * r;
        size_t go = (rowbase + i) * DIMW + coloff;
        #pragma unroll
        for (int c = 0; c < 4; ++c) {
            float o0, o1;
            unpack2(oacc2[r][c], o0, o1);
            __half2 H; H.x = __float2half_rn(o0); H.y = __float2half_rn(o1);
            *reinterpret_cast<__half2*>(g_oh + go + 16 * c + 2 * cg) = H;
        }
    }
}

// ---------------- launcher ---------------------------------------------------
extern "C" void kernel_launch(void* const* d_in, const int* in_sizes, int n_in,
                              void* d_out, int out_size)
{
    const float* x  = (const float*)d_in[0];
    const float* y  = (const float*)d_in[1];
    const float* Wq = (const float*)d_in[2];
    const float* gq = (const float*)d_in[3];
    const float* bq = (const float*)d_in[4];
    const float* Wk = (const float*)d_in[5];
    const float* gk = (const float*)d_in[6];
    const float* bk = (const float*)d_in[7];
    const float* Wv = (const float*)d_in[8];
    const float* Wo = (const float*)d_in[9];
    const float* bo = (const float*)d_in[10];

    float* ynew = (float*)d_out;
    float* attn = ynew + (size_t)M_TOT * DIMW;

    void *p_xh, *p_yh;
    void *p_wq, *p_wk, *p_wv, *p_wo;
    cudaGetSymbolAddress(&p_xh, g_xh);  cudaGetSymbolAddress(&p_yh, g_yh);
    cudaGetSymbolAddress(&p_wq, g_Wq);  cudaGetSymbolAddress(&p_wk, g_Wk);
    cudaGetSymbolAddress(&p_wv, g_Wv);  cudaGetSymbolAddress(&p_wo, g_Wo);

    cudaFuncSetAttribute(attn_kernel,
                         cudaFuncAttributeMaxDynamicSharedMemorySize, ATTN_SMEM);
    cudaFuncSetAttribute(qkv_gemm,
                         cudaFuncAttributeMaxDynamicSharedMemorySize, GEMM_SMEM);
    cudaFuncSetAttribute(out_gemm,
                         cudaFuncAttributeMaxDynamicSharedMemorySize, GEMM_SMEM);

    // 1) convert activations and weights to fp16
    const int n4_act = (M_TOT * DIMW) / 4;
    const int n4_w   = (DIMW * DIMW) / 4;
    cvt_kernel<<<dim3((n4_act + 255) / 256, 2), 256>>>(
        (const float4*)x, (const float4*)y, (uint2*)p_xh, (uint2*)p_yh, n4_act);
    wconv_kernel<<<dim3((n4_w + 255) / 256, 4), 256>>>(
        (const float4*)Wq, (const float4*)Wk, (const float4*)Wv, (const float4*)Wo,
        (uint2*)p_wq, (uint2*)p_wk, (uint2*)p_wv, (uint2*)p_wo, n4_w);

    // 2) q/k/v projections (warp-MMA fp16)
    qkv_gemm<<<dim3(DIMW / BN, M_TOT / BM, 3), 512, GEMM_SMEM>>>();

    // 3) LN on q, k
    ln_kernel<<<dim3(M_TOT, 2), 256>>>(gq, bq, gk, bk);

    // 4) windowed attention (FFMA2) -> attn out + fp16 o
    attn_kernel<<<4096, 256, ATTN_SMEM>>>(attn);

    // 5) final projection with residual epilogue
    out_gemm<<<dim3(DIMW / BN, M_TOT / BM), 512, GEMM_SMEM>>>(y, bo, ynew);
}

// round 9
// speedup vs baseline: 3.6630x; 1.0934x over previous
#include <cuda_runtime.h>
#include <cuda_fp16.h>
#include <cstdint>

#define M_TOT 65536      // B*N rows
#define DIMW  512        // DIM == INNER
#define WIN   128
#define NHEAD 8
#define DHEAD 64

// GEMM tiling (warp-MMA, mma.sync m16n8k16 fp16)
#define BM 128
#define BN 256
#define BK 64
#define NKC (DIMW / BK)
#define A_TILE_B (BM * 128)
#define B_TILE_B (BN * 128)
#define STAGE_B (A_TILE_B + B_TILE_B)           // 48 KB
#define NSTAGE 4
#define GEMM_SMEM (NSTAGE * STAGE_B)            // 192 KB

// ---------------- scratch (__device__ globals; no allocation allowed) -------
__device__ float g_q[(size_t)M_TOT * DIMW];
__device__ float g_k[(size_t)M_TOT * DIMW];

__device__ __half g_xh[(size_t)M_TOT * DIMW];
__device__ __half g_yh[(size_t)M_TOT * DIMW];
__device__ __half g_vh[(size_t)M_TOT * DIMW];
__device__ __half g_oh[(size_t)M_TOT * DIMW];

__device__ float2 g_stq[M_TOT];   // (mean, rstd) for q rows
__device__ float2 g_stk[M_TOT];   // (mean, rstd) for k rows

__device__ __half g_Wq[DIMW * DIMW];
__device__ __half g_Wk[DIMW * DIMW];
__device__ __half g_Wv[DIMW * DIMW];
__device__ __half g_Wo[DIMW * DIMW];

// ---------------- small asm helpers ------------------------------------------
__device__ __forceinline__ uint32_t smem_u32(const void* p) {
    uint32_t a;
    asm("{ .reg .u64 t; cvta.to.shared.u64 t, %1; cvt.u32.u64 %0, t; }"
        : "=r"(a) : "l"(p));
    return a;
}
__device__ __forceinline__ void cp16(uint32_t dst, const void* src) {
    asm volatile("cp.async.cg.shared.global [%0], [%1], 16;"
                 :: "r"(dst), "l"(src) : "memory");
}
__device__ __forceinline__ void cp_commit() {
    asm volatile("cp.async.commit_group;" ::: "memory");
}
template <int N>
__device__ __forceinline__ void cp_wait() {
    asm volatile("cp.async.wait_group %0;" :: "n"(N) : "memory");
}
__device__ __forceinline__ void ldsm4(uint32_t* r, uint32_t addr) {
    asm volatile("ldmatrix.sync.aligned.m8n8.x4.shared.b16 {%0,%1,%2,%3}, [%4];"
                 : "=r"(r[0]), "=r"(r[1]), "=r"(r[2]), "=r"(r[3]) : "r"(addr));
}
__device__ __forceinline__ void mma16816(float* d, const uint32_t* a,
                                         uint32_t b0, uint32_t b1) {
    asm volatile(
        "mma.sync.aligned.m16n8k16.row.col.f32.f16.f16.f32 "
        "{%0,%1,%2,%3}, {%4,%5,%6,%7}, {%8,%9}, {%0,%1,%2,%3};"
        : "+f"(d[0]), "+f"(d[1]), "+f"(d[2]), "+f"(d[3])
        : "r"(a[0]), "r"(a[1]), "r"(a[2]), "r"(a[3]), "r"(b0), "r"(b1));
}
// packed fp32x2 helpers (Blackwell)
__device__ __forceinline__ unsigned long long pack2(float a, float b) {
    unsigned long long r;
    asm("mov.b64 %0, {%1, %2};" : "=l"(r) : "f"(a), "f"(b));
    return r;
}
__device__ __forceinline__ void unpack2(unsigned long long v, float& a, float& b) {
    asm("mov.b64 {%0, %1}, %2;" : "=f"(a), "=f"(b) : "l"(v));
}
__device__ __forceinline__ void fma2(unsigned long long& d,
                                     unsigned long long a, unsigned long long b) {
    asm("fma.rn.f32x2 %0, %1, %2, %0;" : "+l"(d) : "l"(a), "l"(b));
}

// ---------------- fp32 -> fp16 convert (x, y activations) -------------------
__global__ __launch_bounds__(256) void cvt_kernel(const float4* __restrict__ in0,
                                                  const float4* __restrict__ in1,
                                                  uint2* __restrict__ o0,
                                                  uint2* __restrict__ o1, int n4)
{
    int i = blockIdx.x * blockDim.x + threadIdx.x;
    if (i >= n4) return;
    const float4* src = blockIdx.y ? in1 : in0;
    uint2* dst = blockIdx.y ? o1 : o0;
    float4 v = src[i];
    uint2 H;
    H.x = (uint32_t)__half_as_ushort(__float2half_rn(v.x)) |
          ((uint32_t)__half_as_ushort(__float2half_rn(v.y)) << 16);
    H.y = (uint32_t)__half_as_ushort(__float2half_rn(v.z)) |
          ((uint32_t)__half_as_ushort(__float2half_rn(v.w)) << 16);
    dst[i] = H;
}

// ---------------- fp32 -> fp16 round (weights, 4 at once) -------------------
__global__ __launch_bounds__(256) void wconv_kernel(const float4* __restrict__ w0,
                                                    const float4* __restrict__ w1,
                                                    const float4* __restrict__ w2,
                                                    const float4* __restrict__ w3,
                                                    uint2* __restrict__ o0,
                                                    uint2* __restrict__ o1,
                                                    uint2* __restrict__ o2,
                                                    uint2* __restrict__ o3, int n4)
{
    int i = blockIdx.x * blockDim.x + threadIdx.x;
    if (i >= n4) return;
    const float4* src = (blockIdx.y == 0) ? w0 : (blockIdx.y == 1) ? w1
                        : (blockIdx.y == 2) ? w2 : w3;
    uint2* dst = (blockIdx.y == 0) ? o0 : (blockIdx.y == 1) ? o1
                 : (blockIdx.y == 2) ? o2 : o3;
    float4 v = src[i];
    uint2 H;
    H.x = (uint32_t)__half_as_ushort(__float2half_rn(v.x)) |
          ((uint32_t)__half_as_ushort(__float2half_rn(v.y)) << 16);
    H.y = (uint32_t)__half_as_ushort(__float2half_rn(v.z)) |
          ((uint32_t)__half_as_ushort(__float2half_rn(v.w)) << 16);
    dst[i] = H;
}

// ---------------- fp16 warp-MMA GEMM (512 threads, BM128 x BN256) ------------
__device__ __forceinline__ void load_stage(uint32_t sbase,
    const __half* __restrict__ A, const __half* __restrict__ B,
    int m0, int n0, int kc, int tid)
{
    const int kcol = kc * BK;
    #pragma unroll
    for (int i = 0; i < 2; ++i) {
        int idx = tid + i * 512;
        int row = idx >> 3;
        int ch  = idx & 7;
        uint32_t soff = row * 128 + (((ch ^ (row & 7)) << 4));
        size_t ga = (size_t)(m0 + row) * DIMW + kcol + ch * 8;
        cp16(sbase + soff, A + ga);
    }
    #pragma unroll
    for (int i = 0; i < 4; ++i) {
        int idx = tid + i * 512;
        int row = idx >> 3;
        int ch  = idx & 7;
        uint32_t soff = row * 128 + (((ch ^ (row & 7)) << 4));
        size_t gb = (size_t)(n0 + row) * DIMW + kcol + ch * 8;
        cp16(sbase + A_TILE_B + soff, B + gb);
    }
    cp_commit();
}

// mode: 0 = fp32 plain, 1 = fp32 + resid + bias, 2 = fp16 output
__device__ __forceinline__ void gemm_body(
    const __half* __restrict__ A, const __half* __restrict__ B,
    float* __restrict__ C, __half* __restrict__ C16,
    const float* __restrict__ Yadd, const float* __restrict__ bias, int mode)
{
    extern __shared__ char dsm[];
    const uint32_t sb = smem_u32(dsm);

    const int tid  = threadIdx.x;
    const int wid  = tid >> 5;
    const int lane = tid & 31;
    const int warp_m = wid >> 2;
    const int warp_n = wid & 3;
    const int m0 = blockIdx.y * BM;
    const int n0 = blockIdx.x * BN;

    float acc[2][8][4];
    #pragma unroll
    for (int a = 0; a < 2; ++a)
        #pragma unroll
        for (int b = 0; b < 8; ++b)
            #pragma unroll
            for (int c = 0; c < 4; ++c) acc[a][b][c] = 0.f;

    #pragma unroll
    for (int s = 0; s < NSTAGE - 1; ++s)
        load_stage(sb + s * STAGE_B, A, B, m0, n0, s, tid);

    const int frag_row = lane & 15;
    const int frag_ch  = lane >> 4;

    #pragma unroll 1
    for (int kc = 0; kc < NKC; ++kc) {
        cp_wait<NSTAGE - 2>();
        __syncthreads();

        const uint32_t st = sb + (kc % NSTAGE) * STAGE_B;
        const uint32_t sA = st;
        const uint32_t sB = st + A_TILE_B;

        #pragma unroll
        for (int kk = 0; kk < 4; ++kk) {
            uint32_t ah[2][4];
            #pragma unroll
            for (int mi = 0; mi < 2; ++mi) {
                int row = warp_m * 32 + mi * 16 + frag_row;
                int ch  = kk * 2 + frag_ch;
                uint32_t off = row * 128 + (((ch ^ (row & 7)) << 4));
                ldsm4(ah[mi], sA + off);
            }
            uint32_t bh[4][4];
            #pragma unroll
            for (int ng = 0; ng < 4; ++ng) {
                int row = warp_n * 64 + ng * 16 + frag_row;
                int ch  = kk * 2 + frag_ch;
                uint32_t off = row * 128 + (((ch ^ (row & 7)) << 4));
                ldsm4(bh[ng], sB + off);
            }
            #pragma unroll
            for (int mi = 0; mi < 2; ++mi)
                #pragma unroll
                for (int ng = 0; ng < 4; ++ng) {
                    mma16816(acc[mi][ng * 2],     ah[mi], bh[ng][0], bh[ng][2]);
                    mma16816(acc[mi][ng * 2 + 1], ah[mi], bh[ng][1], bh[ng][3]);
                }
        }

        __syncthreads();
        if (kc + NSTAGE - 1 < NKC)
            load_stage(sb + ((kc + NSTAGE - 1) % NSTAGE) * STAGE_B, A, B,
                       m0, n0, kc + NSTAGE - 1, tid);
    }

    const int erow = lane >> 2;
    const int ecol = (lane & 3) * 2;
    #pragma unroll
    for (int mi = 0; mi < 2; ++mi) {
        #pragma unroll
        for (int ni = 0; ni < 8; ++ni) {
            size_t r0 = (size_t)m0 + warp_m * 32 + mi * 16 + erow;
            int    c  = n0 + warp_n * 64 + ni * 8 + ecol;
            float2 v0 = make_float2(acc[mi][ni][0], acc[mi][ni][1]);
            float2 v1 = make_float2(acc[mi][ni][2], acc[mi][ni][3]);
            if (mode == 2) {
                __half2 h0 = __floats2half2_rn(v0.x, v0.y);
                __half2 h1 = __floats2half2_rn(v1.x, v1.y);
                *reinterpret_cast<__half2*>(C16 + r0 * DIMW + c)       = h0;
                *reinterpret_cast<__half2*>(C16 + (r0 + 8) * DIMW + c) = h1;
            } else {
                if (mode == 1) {
                    float2 y0 = *(const float2*)(Yadd + r0 * DIMW + c);
                    float2 y1 = *(const float2*)(Yadd + (r0 + 8) * DIMW + c);
                    float2 bv = *(const float2*)(bias + c);
                    v0.x += y0.x + bv.x; v0.y += y0.y + bv.y;
                    v1.x += y1.x + bv.x; v1.y += y1.y + bv.y;
                }
                *(float2*)(C + r0 * DIMW + c)       = v0;
                *(float2*)(C + (r0 + 8) * DIMW + c) = v1;
            }
        }
    }
}

__global__ __launch_bounds__(512, 1) void qkv_gemm()
{
    if (blockIdx.z == 0)
        gemm_body(g_yh, g_Wq, g_q, nullptr, nullptr, nullptr, 0);
    else if (blockIdx.z == 1)
        gemm_body(g_xh, g_Wk, g_k, nullptr, nullptr, nullptr, 0);
    else
        gemm_body(g_xh, g_Wv, nullptr, g_vh, nullptr, nullptr, 2);
}

__global__ __launch_bounds__(512, 1) void out_gemm(const float* __restrict__ y,
                                                   const float* __restrict__ bout,
                                                   float* __restrict__ ynew)
{
    gemm_body(g_oh, g_Wo, ynew, nullptr, y, bout, 1);
}

// ---------------- LN row stats: one warp per row, shfl-only ------------------
__global__ __launch_bounds__(256) void stats_kernel()
{
    const float* buf = blockIdx.y ? g_k : g_q;
    float2* st       = blockIdx.y ? g_stk : g_stq;
    const int row  = blockIdx.x * 8 + (threadIdx.x >> 5);
    const int lane = threadIdx.x & 31;
    const float4* p = (const float4*)(buf + (size_t)row * DIMW) + lane;

    float s = 0.f, sq = 0.f;
    #pragma unroll
    for (int i = 0; i < 4; ++i) {
        float4 v = p[i * 32];
        s  += v.x + v.y + v.z + v.w;
        sq += v.x * v.x + v.y * v.y + v.z * v.z + v.w * v.w;
    }
    #pragma unroll
    for (int o = 16; o > 0; o >>= 1) {
        s  += __shfl_xor_sync(0xffffffffu, s,  o);
        sq += __shfl_xor_sync(0xffffffffu, sq, o);
    }
    if (lane == 0) {
        float mean = s * (1.f / 512.f);
        float var  = sq * (1.f / 512.f) - mean * mean;
        st[row] = make_float2(mean, rsqrtf(var + 1e-5f));
    }
}

// ---------------- windowed attention (FFMA2 + fused LN), 2 blocks/SM ---------
#define QS  65
#define KTS 130
#define VSS 66
#define PARAM_F (128 * 2 * 2 + 4 * 64)                       // 768 floats
#define ATTN_SMEM ((128 * QS + 64 * KTS + 128 * VSS + PARAM_F) * 4)

__global__ __launch_bounds__(256, 2) void attn_kernel(
    float* __restrict__ attn_out,
    const float* __restrict__ gq, const float* __restrict__ bq,
    const float* __restrict__ gk, const float* __restrict__ bk)
{
    extern __shared__ float sm[];
    float* qs = sm;                    // [128][QS]
    float* kt = qs + 128 * QS;         // [64][KTS]  (kt[d][j])
    float* vs = kt + 64 * KTS;         // [128][VSS]
    float* ps = vs + 128 * VSS;        // params
    float2* stq = (float2*)ps;         // 128
    float2* stk = (float2*)(ps + 256); // 128
    float* sgq = ps + 512;             // 64 (gamma_q * 0.125)
    float* sbq = ps + 576;             // 64 (beta_q  * 0.125)
    float* sgk = ps + 640;             // 64
    float* sbk = ps + 704;             // 64

    const int tid = threadIdx.x;
    const int bwh = blockIdx.x;        // bw*8 + h
    const int bw  = bwh >> 3;
    const int h   = bwh & 7;
    const size_t rowbase = (size_t)bw * WIN;
    const int coloff = h * DHEAD;

    if (tid < 128) {
        stq[tid] = g_stq[rowbase + tid];
        stk[tid] = g_stk[rowbase + tid];
    } else if (tid < 192) {
        int d = tid - 128;
        sgq[d] = gq[coloff + d] * 0.125f;
        sbq[d] = bq[coloff + d] * 0.125f;
        sgk[d] = gk[coloff + d];
        sbk[d] = bk[coloff + d];
    }
    __syncthreads();

    // load q (LN+scale), k (LN, transposed), v (fp16 -> fp32)
    #pragma unroll
    for (int it = 0; it < 8; ++it) {
        int idx = tid + it * 256;
        int i   = idx >> 4;
        int d4  = (idx & 15) << 2;
        size_t goff = (rowbase + i) * DIMW + coloff + d4;
        float4 qv = *(const float4*)(g_q + goff);
        float4 kv = *(const float4*)(g_k + goff);
        uint2 vraw = *(const uint2*)(g_vh + goff);

        float2 sq_ = stq[i];
        float2 sk_ = stk[i];
        float* qd = qs + i * QS + d4;
        qd[0] = (qv.x - sq_.x) * sq_.y * sgq[d4 + 0] + sbq[d4 + 0];
        qd[1] = (qv.y - sq_.x) * sq_.y * sgq[d4 + 1] + sbq[d4 + 1];
        qd[2] = (qv.z - sq_.x) * sq_.y * sgq[d4 + 2] + sbq[d4 + 2];
        qd[3] = (qv.w - sq_.x) * sq_.y * sgq[d4 + 3] + sbq[d4 + 3];
        kt[(d4 + 0) * KTS + i] = (kv.x - sk_.x) * sk_.y * sgk[d4 + 0] + sbk[d4 + 0];
        kt[(d4 + 1) * KTS + i] = (kv.y - sk_.x) * sk_.y * sgk[d4 + 1] + sbk[d4 + 1];
        kt[(d4 + 2) * KTS + i] = (kv.z - sk_.x) * sk_.y * sgk[d4 + 2] + sbk[d4 + 2];
        kt[(d4 + 3) * KTS + i] = (kv.w - sk_.x) * sk_.y * sgk[d4 + 3] + sbk[d4 + 3];

        __half2 v01 = *reinterpret_cast<__half2*>(&vraw.x);
        __half2 v23 = *reinterpret_cast<__half2*>(&vraw.y);
        float2 f01 = __half22float2(v01);
        float2 f23 = __half22float2(v23);
        float* vd = vs + i * VSS + d4;
        vd[0] = f01.x; vd[1] = f01.y; vd[2] = f23.x; vd[3] = f23.y;
    }
    __syncthreads();

    const int rg = tid >> 3;
    const int cg = tid & 7;

    // QK^T : acc2[r][c] holds j = 16c + 2cg + {0,1}   (scale pre-folded into q)
    unsigned long long acc2[4][8];
    #pragma unroll
    for (int r = 0; r < 4; ++r)
        #pragma unroll
        for (int c = 0; c < 8; ++c) acc2[r][c] = 0ull;

    #pragma unroll 4
    for (int d = 0; d < 64; ++d) {
        unsigned long long qv2[4];
        #pragma unroll
        for (int r = 0; r < 4; ++r) {
            float q = qs[(rg + 32 * r) * QS + d];
            qv2[r] = pack2(q, q);
        }
        unsigned long long kv2[8];
        #pragma unroll
        for (int c = 0; c < 8; ++c)
            kv2[c] = *reinterpret_cast<const unsigned long long*>(
                         kt + d * KTS + 16 * c + 2 * cg);
        #pragma unroll
        for (int r = 0; r < 4; ++r)
            #pragma unroll
            for (int c = 0; c < 8; ++c)
                fma2(acc2[r][c], qv2[r], kv2[c]);
    }

    // softmax per row + write attn
    float pacc[4][16];
    const size_t abase = (size_t)bwh * WIN * WIN;
    #pragma unroll
    for (int r = 0; r < 4; ++r) {
        #pragma unroll
        for (int c = 0; c < 8; ++c)
            unpack2(acc2[r][c], pacc[r][2 * c], pacc[r][2 * c + 1]);
        float mx = -1e30f;
        #pragma unroll
        for (int c = 0; c < 16; ++c) mx = fmaxf(mx, pacc[r][c]);
        #pragma unroll
        for (int o = 1; o < 8; o <<= 1)
            mx = fmaxf(mx, __shfl_xor_sync(0xffffffffu, mx, o, 8));
        float sum = 0.f;
        #pragma unroll
        for (int c = 0; c < 16; ++c) {
            pacc[r][c] = __expf(pacc[r][c] - mx);
            sum += pacc[r][c];
        }
        #pragma unroll
        for (int o = 1; o < 8; o <<= 1)
            sum += __shfl_xor_sync(0xffffffffu, sum, o, 8);
        float inv = 1.0f / sum;
        int i = rg + 32 * r;
        #pragma unroll
        for (int c = 0; c < 8; ++c) {
            pacc[r][2 * c]     *= inv;
            pacc[r][2 * c + 1] *= inv;
            float2 pw = make_float2(pacc[r][2 * c], pacc[r][2 * c + 1]);
            *reinterpret_cast<float2*>(
                attn_out + abase + (size_t)i * WIN + 16 * c + 2 * cg) = pw;
        }
    }

    // P @ V : oacc2[r][c] holds d = 16c + 2cg + {0,1}
    unsigned long long oacc2[4][4];
    #pragma unroll
    for (int r = 0; r < 4; ++r)
        #pragma unroll
        for (int c = 0; c < 4; ++c) oacc2[r][c] = 0ull;

    #pragma unroll
    for (int j = 0; j < 128; ++j) {
        const int cg_src = (j >> 1) & 7;
        const int cidx   = ((j >> 4) << 1) | (j & 1);
        unsigned long long vv2[4];
        #pragma unroll
        for (int c = 0; c < 4; ++c)
            vv2[c] = *reinterpret_cast<const unsigned long long*>(
                         vs + j * VSS + 16 * c + 2 * cg);
        #pragma unroll
        for (int r = 0; r < 4; ++r) {
            float p = __shfl_sync(0xffffffffu, pacc[r][cidx], cg_src, 8);
            unsigned long long av2 = pack2(p, p);
            #pragma unroll
            for (int c = 0; c < 4; ++c)
                fma2(oacc2[r][c], av2, vv2[c]);
        }
    }

    // epilogue: convert o to fp16 directly (feeds out_gemm)
    #pragma unroll
    for (int r = 0; r < 4; ++r) {
        int i = rg + 32 * r;
        size_t go = (rowbase + i) * DIMW + coloff;
        #pragma unroll
        for (int c = 0; c < 4; ++c) {
            float o0, o1;
            unpack2(oacc2[r][c], o0, o1);
            __half2 H; H.x = __float2half_rn(o0); H.y = __float2half_rn(o1);
            *reinterpret_cast<__half2*>(g_oh + go + 16 * c + 2 * cg) = H;
        }
    }
}

// ---------------- launcher ---------------------------------------------------
extern "C" void kernel_launch(void* const* d_in, const int* in_sizes, int n_in,
                              void* d_out, int out_size)
{
    const float* x  = (const float*)d_in[0];
    const float* y  = (const float*)d_in[1];
    const float* Wq = (const float*)d_in[2];
    const float* gq = (const float*)d_in[3];
    const float* bq = (const float*)d_in[4];
    const float* Wk = (const float*)d_in[5];
    const float* gk = (const float*)d_in[6];
    const float* bk = (const float*)d_in[7];
    const float* Wv = (const float*)d_in[8];
    const float* Wo = (const float*)d_in[9];
    const float* bo = (const float*)d_in[10];

    float* ynew = (float*)d_out;
    float* attn = ynew + (size_t)M_TOT * DIMW;

    void *p_xh, *p_yh;
    void *p_wq, *p_wk, *p_wv, *p_wo;
    cudaGetSymbolAddress(&p_xh, g_xh);  cudaGetSymbolAddress(&p_yh, g_yh);
    cudaGetSymbolAddress(&p_wq, g_Wq);  cudaGetSymbolAddress(&p_wk, g_Wk);
    cudaGetSymbolAddress(&p_wv, g_Wv);  cudaGetSymbolAddress(&p_wo, g_Wo);

    cudaFuncSetAttribute(attn_kernel,
                         cudaFuncAttributeMaxDynamicSharedMemorySize, ATTN_SMEM);
    cudaFuncSetAttribute(qkv_gemm,
                         cudaFuncAttributeMaxDynamicSharedMemorySize, GEMM_SMEM);
    cudaFuncSetAttribute(out_gemm,
                         cudaFuncAttributeMaxDynamicSharedMemorySize, GEMM_SMEM);

    // 1) convert activations and weights to fp16
    const int n4_act = (M_TOT * DIMW) / 4;
    const int n4_w   = (DIMW * DIMW) / 4;
    cvt_kernel<<<dim3((n4_act + 255) / 256, 2), 256>>>(
        (const float4*)x, (const float4*)y, (uint2*)p_xh, (uint2*)p_yh, n4_act);
    wconv_kernel<<<dim3((n4_w + 255) / 256, 4), 256>>>(
        (const float4*)Wq, (const float4*)Wk, (const float4*)Wv, (const float4*)Wo,
        (uint2*)p_wq, (uint2*)p_wk, (uint2*)p_wv, (uint2*)p_wo, n4_w);

    // 2) q/k/v projections (warp-MMA fp16; v written fp16)
    qkv_gemm<<<dim3(DIMW / BN, M_TOT / BM, 3), 512, GEMM_SMEM>>>();

    // 3) LN row stats for q, k
    stats_kernel<<<dim3(M_TOT / 8, 2), 256>>>();

    // 4) windowed attention (LN applied on load) -> attn out + fp16 o
    attn_kernel<<<4096, 256, ATTN_SMEM>>>(attn, gq, bq, gk, bk);

    // 5) final projection with residual epilogue
    out_gemm<<<dim3(DIMW / BN, M_TOT / BM), 512, GEMM_SMEM>>>(y, bo, ynew);
}

// round 10
// speedup vs baseline: 3.7747x; 1.0305x over previous
#include <cuda_runtime.h>
#include <cuda_fp16.h>
#include <cstdint>

#define M_TOT 65536      // B*N rows
#define DIMW  512        // DIM == INNER
#define WIN   128
#define NHEAD 8
#define DHEAD 64

// GEMM tiling (warp-MMA, mma.sync m16n8k16 fp16)
#define BM 128
#define BN 256
#define BK 64
#define NKC (DIMW / BK)
#define A_TILE_B (BM * 128)
#define B_TILE_B (BN * 128)
#define STAGE_B (A_TILE_B + B_TILE_B)           // 48 KB
#define NSTAGE 4
#define GEMM_SMEM (NSTAGE * STAGE_B)            // 192 KB

// ---------------- scratch (__device__ globals; no allocation allowed) -------
__device__ __half g_qh[(size_t)M_TOT * DIMW];
__device__ __half g_kh[(size_t)M_TOT * DIMW];
__device__ __half g_vh[(size_t)M_TOT * DIMW];
__device__ __half g_oh[(size_t)M_TOT * DIMW];

__device__ __half g_xh[(size_t)M_TOT * DIMW];
__device__ __half g_yh[(size_t)M_TOT * DIMW];

__device__ float2 g_stq[M_TOT];   // (mean, rstd) for q rows
__device__ float2 g_stk[M_TOT];   // (mean, rstd) for k rows

__device__ __half g_Wq[DIMW * DIMW];
__device__ __half g_Wk[DIMW * DIMW];
__device__ __half g_Wv[DIMW * DIMW];
__device__ __half g_Wo[DIMW * DIMW];

// ---------------- small asm helpers ------------------------------------------
__device__ __forceinline__ uint32_t smem_u32(const void* p) {
    uint32_t a;
    asm("{ .reg .u64 t; cvta.to.shared.u64 t, %1; cvt.u32.u64 %0, t; }"
        : "=r"(a) : "l"(p));
    return a;
}
__device__ __forceinline__ void cp16(uint32_t dst, const void* src) {
    asm volatile("cp.async.cg.shared.global [%0], [%1], 16;"
                 :: "r"(dst), "l"(src) : "memory");
}
__device__ __forceinline__ void cp_commit() {
    asm volatile("cp.async.commit_group;" ::: "memory");
}
template <int N>
__device__ __forceinline__ void cp_wait() {
    asm volatile("cp.async.wait_group %0;" :: "n"(N) : "memory");
}
__device__ __forceinline__ void ldsm4(uint32_t* r, uint32_t addr) {
    asm volatile("ldmatrix.sync.aligned.m8n8.x4.shared.b16 {%0,%1,%2,%3}, [%4];"
                 : "=r"(r[0]), "=r"(r[1]), "=r"(r[2]), "=r"(r[3]) : "r"(addr));
}
__device__ __forceinline__ void mma16816(float* d, const uint32_t* a,
                                         uint32_t b0, uint32_t b1) {
    asm volatile(
        "mma.sync.aligned.m16n8k16.row.col.f32.f16.f16.f32 "
        "{%0,%1,%2,%3}, {%4,%5,%6,%7}, {%8,%9}, {%0,%1,%2,%3};"
        : "+f"(d[0]), "+f"(d[1]), "+f"(d[2]), "+f"(d[3])
        : "r"(a[0]), "r"(a[1]), "r"(a[2]), "r"(a[3]), "r"(b0), "r"(b1));
}
// packed fp32x2 helpers (Blackwell)
__device__ __forceinline__ unsigned long long pack2(float a, float b) {
    unsigned long long r;
    asm("mov.b64 %0, {%1, %2};" : "=l"(r) : "f"(a), "f"(b));
    return r;
}
__device__ __forceinline__ void unpack2(unsigned long long v, float& a, float& b) {
    asm("mov.b64 {%0, %1}, %2;" : "=f"(a), "=f"(b) : "l"(v));
}
__device__ __forceinline__ void fma2(unsigned long long& d,
                                     unsigned long long a, unsigned long long b) {
    asm("fma.rn.f32x2 %0, %1, %2, %0;" : "+l"(d) : "l"(a), "l"(b));
}

// ---------------- fp32 -> fp16 convert (x, y activations) -------------------
__global__ __launch_bounds__(256) void cvt_kernel(const float4* __restrict__ in0,
                                                  const float4* __restrict__ in1,
                                                  uint2* __restrict__ o0,
                                                  uint2* __restrict__ o1, int n4)
{
    int i = blockIdx.x * blockDim.x + threadIdx.x;
    if (i >= n4) return;
    const float4* src = blockIdx.y ? in1 : in0;
    uint2* dst = blockIdx.y ? o1 : o0;
    float4 v = src[i];
    uint2 H;
    H.x = (uint32_t)__half_as_ushort(__float2half_rn(v.x)) |
          ((uint32_t)__half_as_ushort(__float2half_rn(v.y)) << 16);
    H.y = (uint32_t)__half_as_ushort(__float2half_rn(v.z)) |
          ((uint32_t)__half_as_ushort(__float2half_rn(v.w)) << 16);
    dst[i] = H;
}

// ---------------- fp32 -> fp16 round (weights, 4 at once) -------------------
__global__ __launch_bounds__(256) void wconv_kernel(const float4* __restrict__ w0,
                                                    const float4* __restrict__ w1,
                                                    const float4* __restrict__ w2,
                                                    const float4* __restrict__ w3,
                                                    uint2* __restrict__ o0,
                                                    uint2* __restrict__ o1,
                                                    uint2* __restrict__ o2,
                                                    uint2* __restrict__ o3, int n4)
{
    int i = blockIdx.x * blockDim.x + threadIdx.x;
    if (i >= n4) return;
    const float4* src = (blockIdx.y == 0) ? w0 : (blockIdx.y == 1) ? w1
                        : (blockIdx.y == 2) ? w2 : w3;
    uint2* dst = (blockIdx.y == 0) ? o0 : (blockIdx.y == 1) ? o1
                 : (blockIdx.y == 2) ? o2 : o3;
    float4 v = src[i];
    uint2 H;
    H.x = (uint32_t)__half_as_ushort(__float2half_rn(v.x)) |
          ((uint32_t)__half_as_ushort(__float2half_rn(v.y)) << 16);
    H.y = (uint32_t)__half_as_ushort(__float2half_rn(v.z)) |
          ((uint32_t)__half_as_ushort(__float2half_rn(v.w)) << 16);
    dst[i] = H;
}

// ---------------- fp16 warp-MMA GEMM (512 threads, BM128 x BN256) ------------
__device__ __forceinline__ void load_stage(uint32_t sbase,
    const __half* __restrict__ A, const __half* __restrict__ B,
    int m0, int n0, int kc, int tid)
{
    const int kcol = kc * BK;
    #pragma unroll
    for (int i = 0; i < 2; ++i) {
        int idx = tid + i * 512;
        int row = idx >> 3;
        int ch  = idx & 7;
        uint32_t soff = row * 128 + (((ch ^ (row & 7)) << 4));
        size_t ga = (size_t)(m0 + row) * DIMW + kcol + ch * 8;
        cp16(sbase + soff, A + ga);
    }
    #pragma unroll
    for (int i = 0; i < 4; ++i) {
        int idx = tid + i * 512;
        int row = idx >> 3;
        int ch  = idx & 7;
        uint32_t soff = row * 128 + (((ch ^ (row & 7)) << 4));
        size_t gb = (size_t)(n0 + row) * DIMW + kcol + ch * 8;
        cp16(sbase + A_TILE_B + soff, B + gb);
    }
    cp_commit();
}

// mode: 1 = fp32 + resid + bias, 2 = fp16 output
__device__ __forceinline__ void gemm_body(
    const __half* __restrict__ A, const __half* __restrict__ B,
    float* __restrict__ C, __half* __restrict__ C16,
    const float* __restrict__ Yadd, const float* __restrict__ bias, int mode)
{
    extern __shared__ char dsm[];
    const uint32_t sb = smem_u32(dsm);

    const int tid  = threadIdx.x;
    const int wid  = tid >> 5;
    const int lane = tid & 31;
    const int warp_m = wid >> 2;
    const int warp_n = wid & 3;
    const int m0 = blockIdx.y * BM;
    const int n0 = blockIdx.x * BN;

    float acc[2][8][4];
    #pragma unroll
    for (int a = 0; a < 2; ++a)
        #pragma unroll
        for (int b = 0; b < 8; ++b)
            #pragma unroll
            for (int c = 0; c < 4; ++c) acc[a][b][c] = 0.f;

    #pragma unroll
    for (int s = 0; s < NSTAGE - 1; ++s)
        load_stage(sb + s * STAGE_B, A, B, m0, n0, s, tid);

    const int frag_row = lane & 15;
    const int frag_ch  = lane >> 4;

    #pragma unroll 1
    for (int kc = 0; kc < NKC; ++kc) {
        cp_wait<NSTAGE - 2>();
        __syncthreads();

        const uint32_t st = sb + (kc % NSTAGE) * STAGE_B;
        const uint32_t sA = st;
        const uint32_t sB = st + A_TILE_B;

        #pragma unroll
        for (int kk = 0; kk < 4; ++kk) {
            uint32_t ah[2][4];
            #pragma unroll
            for (int mi = 0; mi < 2; ++mi) {
                int row = warp_m * 32 + mi * 16 + frag_row;
                int ch  = kk * 2 + frag_ch;
                uint32_t off = row * 128 + (((ch ^ (row & 7)) << 4));
                ldsm4(ah[mi], sA + off);
            }
            uint32_t bh[4][4];
            #pragma unroll
            for (int ng = 0; ng < 4; ++ng) {
                int row = warp_n * 64 + ng * 16 + frag_row;
                int ch  = kk * 2 + frag_ch;
                uint32_t off = row * 128 + (((ch ^ (row & 7)) << 4));
                ldsm4(bh[ng], sB + off);
            }
            #pragma unroll
            for (int mi = 0; mi < 2; ++mi)
                #pragma unroll
                for (int ng = 0; ng < 4; ++ng) {
                    mma16816(acc[mi][ng * 2],     ah[mi], bh[ng][0], bh[ng][2]);
                    mma16816(acc[mi][ng * 2 + 1], ah[mi], bh[ng][1], bh[ng][3]);
                }
        }

        __syncthreads();
        if (kc + NSTAGE - 1 < NKC)
            load_stage(sb + ((kc + NSTAGE - 1) % NSTAGE) * STAGE_B, A, B,
                       m0, n0, kc + NSTAGE - 1, tid);
    }

    const int erow = lane >> 2;
    const int ecol = (lane & 3) * 2;
    #pragma unroll
    for (int mi = 0; mi < 2; ++mi) {
        #pragma unroll
        for (int ni = 0; ni < 8; ++ni) {
            size_t r0 = (size_t)m0 + warp_m * 32 + mi * 16 + erow;
            int    c  = n0 + warp_n * 64 + ni * 8 + ecol;
            float2 v0 = make_float2(acc[mi][ni][0], acc[mi][ni][1]);
            float2 v1 = make_float2(acc[mi][ni][2], acc[mi][ni][3]);
            if (mode == 2) {
                __half2 h0 = __floats2half2_rn(v0.x, v0.y);
                __half2 h1 = __floats2half2_rn(v1.x, v1.y);
                *reinterpret_cast<__half2*>(C16 + r0 * DIMW + c)       = h0;
                *reinterpret_cast<__half2*>(C16 + (r0 + 8) * DIMW + c) = h1;
            } else {
                float2 y0 = *(const float2*)(Yadd + r0 * DIMW + c);
                float2 y1 = *(const float2*)(Yadd + (r0 + 8) * DIMW + c);
                float2 bv = *(const float2*)(bias + c);
                v0.x += y0.x + bv.x; v0.y += y0.y + bv.y;
                v1.x += y1.x + bv.x; v1.y += y1.y + bv.y;
                *(float2*)(C + r0 * DIMW + c)       = v0;
                *(float2*)(C + (r0 + 8) * DIMW + c) = v1;
            }
        }
    }
}

__global__ __launch_bounds__(512, 1) void qkv_gemm()
{
    if (blockIdx.z == 0)
        gemm_body(g_yh, g_Wq, nullptr, g_qh, nullptr, nullptr, 2);
    else if (blockIdx.z == 1)
        gemm_body(g_xh, g_Wk, nullptr, g_kh, nullptr, nullptr, 2);
    else
        gemm_body(g_xh, g_Wv, nullptr, g_vh, nullptr, nullptr, 2);
}

__global__ __launch_bounds__(512, 1) void out_gemm(const float* __restrict__ y,
                                                   const float* __restrict__ bout,
                                                   float* __restrict__ ynew)
{
    gemm_body(g_oh, g_Wo, ynew, nullptr, y, bout, 1);
}

// ---------------- LN row stats from fp16: one warp per row, shfl-only --------
__global__ __launch_bounds__(256) void stats_kernel()
{
    const __half* buf = blockIdx.y ? g_kh : g_qh;
    float2* st        = blockIdx.y ? g_stk : g_stq;
    const int row  = blockIdx.x * 8 + (threadIdx.x >> 5);
    const int lane = threadIdx.x & 31;
    const uint4* p = (const uint4*)(buf + (size_t)row * DIMW) + lane;

    float s = 0.f, sq = 0.f;
    #pragma unroll
    for (int i = 0; i < 2; ++i) {
        uint4 v = p[i * 32];
        #pragma unroll
        for (int w = 0; w < 4; ++w) {
            uint32_t raw = (&v.x)[w];
            float2 f = __half22float2(*reinterpret_cast<__half2*>(&raw));
            s  += f.x + f.y;
            sq += f.x * f.x + f.y * f.y;
        }
    }
    #pragma unroll
    for (int o = 16; o > 0; o >>= 1) {
        s  += __shfl_xor_sync(0xffffffffu, s,  o);
        sq += __shfl_xor_sync(0xffffffffu, sq, o);
    }
    if (lane == 0) {
        float mean = s * (1.f / 512.f);
        float var  = sq * (1.f / 512.f) - mean * mean;
        st[row] = make_float2(mean, rsqrtf(var + 1e-5f));
    }
}

// ---------------- windowed attention (FFMA2 + fused LN), 2 blocks/SM ---------
#define QS  65
#define KTS 130
#define VSS 66
#define PARAM_F (128 * 2 * 2 + 4 * 64)                       // 768 floats
#define ATTN_SMEM ((128 * QS + 64 * KTS + 128 * VSS + PARAM_F) * 4)

__global__ __launch_bounds__(256, 2) void attn_kernel(
    float* __restrict__ attn_out,
    const float* __restrict__ gq, const float* __restrict__ bq,
    const float* __restrict__ gk, const float* __restrict__ bk)
{
    extern __shared__ float sm[];
    float* qs = sm;                    // [128][QS]
    float* kt = qs + 128 * QS;         // [64][KTS]  (kt[d][j])
    float* vs = kt + 64 * KTS;         // [128][VSS]
    float* ps = vs + 128 * VSS;        // params
    float2* stq = (float2*)ps;         // 128
    float2* stk = (float2*)(ps + 256); // 128
    float* sgq = ps + 512;             // 64 (gamma_q * 0.125)
    float* sbq = ps + 576;             // 64 (beta_q  * 0.125)
    float* sgk = ps + 640;             // 64
    float* sbk = ps + 704;             // 64

    const int tid = threadIdx.x;
    const int bwh = blockIdx.x;        // bw*8 + h
    const int bw  = bwh >> 3;
    const int h   = bwh & 7;
    const size_t rowbase = (size_t)bw * WIN;
    const int coloff = h * DHEAD;

    if (tid < 128) {
        stq[tid] = g_stq[rowbase + tid];
        stk[tid] = g_stk[rowbase + tid];
    } else if (tid < 192) {
        int d = tid - 128;
        sgq[d] = gq[coloff + d] * 0.125f;
        sbq[d] = bq[coloff + d] * 0.125f;
        sgk[d] = gk[coloff + d];
        sbk[d] = bk[coloff + d];
    }
    __syncthreads();

    // load q (fp16 -> LN+scale), k (fp16 -> LN, transposed), v (fp16 -> fp32)
    #pragma unroll
    for (int it = 0; it < 8; ++it) {
        int idx = tid + it * 256;
        int i   = idx >> 4;
        int d4  = (idx & 15) << 2;
        size_t goff = (rowbase + i) * DIMW + coloff + d4;
        uint2 qraw = *(const uint2*)(g_qh + goff);
        uint2 kraw = *(const uint2*)(g_kh + goff);
        uint2 vraw = *(const uint2*)(g_vh + goff);

        float2 q01 = __half22float2(*reinterpret_cast<__half2*>(&qraw.x));
        float2 q23 = __half22float2(*reinterpret_cast<__half2*>(&qraw.y));
        float2 k01 = __half22float2(*reinterpret_cast<__half2*>(&kraw.x));
        float2 k23 = __half22float2(*reinterpret_cast<__half2*>(&kraw.y));
        float2 v01 = __half22float2(*reinterpret_cast<__half2*>(&vraw.x));
        float2 v23 = __half22float2(*reinterpret_cast<__half2*>(&vraw.y));

        float2 sq_ = stq[i];
        float2 sk_ = stk[i];
        float* qd = qs + i * QS + d4;
        qd[0] = (q01.x - sq_.x) * sq_.y * sgq[d4 + 0] + sbq[d4 + 0];
        qd[1] = (q01.y - sq_.x) * sq_.y * sgq[d4 + 1] + sbq[d4 + 1];
        qd[2] = (q23.x - sq_.x) * sq_.y * sgq[d4 + 2] + sbq[d4 + 2];
        qd[3] = (q23.y - sq_.x) * sq_.y * sgq[d4 + 3] + sbq[d4 + 3];
        kt[(d4 + 0) * KTS + i] = (k01.x - sk_.x) * sk_.y * sgk[d4 + 0] + sbk[d4 + 0];
        kt[(d4 + 1) * KTS + i] = (k01.y - sk_.x) * sk_.y * sgk[d4 + 1] + sbk[d4 + 1];
        kt[(d4 + 2) * KTS + i] = (k23.x - sk_.x) * sk_.y * sgk[d4 + 2] + sbk[d4 + 2];
        kt[(d4 + 3) * KTS + i] = (k23.y - sk_.x) * sk_.y * sgk[d4 + 3] + sbk[d4 + 3];

        float* vd = vs + i * VSS + d4;
        vd[0] = v01.x; vd[1] = v01.y; vd[2] = v23.x; vd[3] = v23.y;
    }
    __syncthreads();

    const int rg = tid >> 3;
    const int cg = tid & 7;

    // QK^T : acc2[r][c] holds j = 16c + 2cg + {0,1}   (scale pre-folded into q)
    unsigned long long acc2[4][8];
    #pragma unroll
    for (int r = 0; r < 4; ++r)
        #pragma unroll
        for (int c = 0; c < 8; ++c) acc2[r][c] = 0ull;

    #pragma unroll 4
    for (int d = 0; d < 64; ++d) {
        unsigned long long qv2[4];
        #pragma unroll
        for (int r = 0; r < 4; ++r) {
            float q = qs[(rg + 32 * r) * QS + d];
            qv2[r] = pack2(q, q);
        }
        unsigned long long kv2[8];
        #pragma unroll
        for (int c = 0; c < 8; ++c)
            kv2[c] = *reinterpret_cast<const unsigned long long*>(
                         kt + d * KTS + 16 * c + 2 * cg);
        #pragma unroll
        for (int r = 0; r < 4; ++r)
            #pragma unroll
            for (int c = 0; c < 8; ++c)
                fma2(acc2[r][c], qv2[r], kv2[c]);
    }

    // softmax per row + write attn
    float pacc[4][16];
    const size_t abase = (size_t)bwh * WIN * WIN;
    #pragma unroll
    for (int r = 0; r < 4; ++r) {
        #pragma unroll
        for (int c = 0; c < 8; ++c)
            unpack2(acc2[r][c], pacc[r][2 * c], pacc[r][2 * c + 1]);
        float mx = -1e30f;
        #pragma unroll
        for (int c = 0; c < 16; ++c) mx = fmaxf(mx, pacc[r][c]);
        #pragma unroll
        for (int o = 1; o < 8; o <<= 1)
            mx = fmaxf(mx, __shfl_xor_sync(0xffffffffu, mx, o, 8));
        float sum = 0.f;
        #pragma unroll
        for (int c = 0; c < 16; ++c) {
            pacc[r][c] = __expf(pacc[r][c] - mx);
            sum += pacc[r][c];
        }
        #pragma unroll
        for (int o = 1; o < 8; o <<= 1)
            sum += __shfl_xor_sync(0xffffffffu, sum, o, 8);
        float inv = 1.0f / sum;
        int i = rg + 32 * r;
        #pragma unroll
        for (int c = 0; c < 8; ++c) {
            pacc[r][2 * c]     *= inv;
            pacc[r][2 * c + 1] *= inv;
            float2 pw = make_float2(pacc[r][2 * c], pacc[r][2 * c + 1]);
            *reinterpret_cast<float2*>(
                attn_out + abase + (size_t)i * WIN + 16 * c + 2 * cg) = pw;
        }
    }

    // P @ V : oacc2[r][c] holds d = 16c + 2cg + {0,1}
    unsigned long long oacc2[4][4];
    #pragma unroll
    for (int r = 0; r < 4; ++r)
        #pragma unroll
        for (int c = 0; c < 4; ++c) oacc2[r][c] = 0ull;

    #pragma unroll
    for (int j = 0; j < 128; ++j) {
        const int cg_src = (j >> 1) & 7;
        const int cidx   = ((j >> 4) << 1) | (j & 1);
        unsigned long long vv2[4];
        #pragma unroll
        for (int c = 0; c < 4; ++c)
            vv2[c] = *reinterpret_cast<const unsigned long long*>(
                         vs + j * VSS + 16 * c + 2 * cg);
        #pragma unroll
        for (int r = 0; r < 4; ++r) {
            float p = __shfl_sync(0xffffffffu, pacc[r][cidx], cg_src, 8);
            unsigned long long av2 = pack2(p, p);
            #pragma unroll
            for (int c = 0; c < 4; ++c)
                fma2(oacc2[r][c], av2, vv2[c]);
        }
    }

    // epilogue: convert o to fp16 directly (feeds out_gemm)
    #pragma unroll
    for (int r = 0; r < 4; ++r) {
        int i = rg + 32 * r;
        size_t go = (rowbase + i) * DIMW + coloff;
        #pragma unroll
        for (int c = 0; c < 4; ++c) {
            float o0, o1;
            unpack2(oacc2[r][c], o0, o1);
            __half2 H; H.x = __float2half_rn(o0); H.y = __float2half_rn(o1);
            *reinterpret_cast<__half2*>(g_oh + go + 16 * c + 2 * cg) = H;
        }
    }
}

// ---------------- launcher ---------------------------------------------------
extern "C" void kernel_launch(void* const* d_in, const int* in_sizes, int n_in,
                              void* d_out, int out_size)
{
    const float* x  = (const float*)d_in[0];
    const float* y  = (const float*)d_in[1];
    const float* Wq = (const float*)d_in[2];
    const float* gq = (const float*)d_in[3];
    const float* bq = (const float*)d_in[4];
    const float* Wk = (const float*)d_in[5];
    const float* gk = (const float*)d_in[6];
    const float* bk = (const float*)d_in[7];
    const float* Wv = (const float*)d_in[8];
    const float* Wo = (const float*)d_in[9];
    const float* bo = (const float*)d_in[10];

    float* ynew = (float*)d_out;
    float* attn = ynew + (size_t)M_TOT * DIMW;

    void *p_xh, *p_yh;
    void *p_wq, *p_wk, *p_wv, *p_wo;
    cudaGetSymbolAddress(&p_xh, g_xh);  cudaGetSymbolAddress(&p_yh, g_yh);
    cudaGetSymbolAddress(&p_wq, g_Wq);  cudaGetSymbolAddress(&p_wk, g_Wk);
    cudaGetSymbolAddress(&p_wv, g_Wv);  cudaGetSymbolAddress(&p_wo, g_Wo);

    cudaFuncSetAttribute(attn_kernel,
                         cudaFuncAttributeMaxDynamicSharedMemorySize, ATTN_SMEM);
    cudaFuncSetAttribute(qkv_gemm,
                         cudaFuncAttributeMaxDynamicSharedMemorySize, GEMM_SMEM);
    cudaFuncSetAttribute(out_gemm,
                         cudaFuncAttributeMaxDynamicSharedMemorySize, GEMM_SMEM);

    // 1) convert activations and weights to fp16
    const int n4_act = (M_TOT * DIMW) / 4;
    const int n4_w   = (DIMW * DIMW) / 4;
    cvt_kernel<<<dim3((n4_act + 255) / 256, 2), 256>>>(
        (const float4*)x, (const float4*)y, (uint2*)p_xh, (uint2*)p_yh, n4_act);
    wconv_kernel<<<dim3((n4_w + 255) / 256, 4), 256>>>(
        (const float4*)Wq, (const float4*)Wk, (const float4*)Wv, (const float4*)Wo,
        (uint2*)p_wq, (uint2*)p_wk, (uint2*)p_wv, (uint2*)p_wo, n4_w);

    // 2) q/k/v projections (warp-MMA fp16; q,k,v all written fp16)
    qkv_gemm<<<dim3(DIMW / BN, M_TOT / BM, 3), 512, GEMM_SMEM>>>();

    // 3) LN row stats for q, k (fp16 input)
    stats_kernel<<<dim3(M_TOT / 8, 2), 256>>>();

    // 4) windowed attention (LN applied on load) -> attn out + fp16 o
    attn_kernel<<<4096, 256, ATTN_SMEM>>>(attn, gq, bq, gk, bk);

    // 5) final projection with residual epilogue
    out_gemm<<<dim3(DIMW / BN, M_TOT / BM), 512, GEMM_SMEM>>>(y, bo, ynew);
}

// round 12
// speedup vs baseline: 5.1709x; 1.3699x over previous
#include <cuda_runtime.h>
#include <cuda_fp16.h>
#include <cstdint>

#define M_TOT 65536      // B*N rows
#define DIMW  512        // DIM == INNER
#define WIN   128
#define NHEAD 8
#define DHEAD 64

// GEMM tiling (warp-MMA, mma.sync m16n8k16 fp16)
#define BM 128
#define BN 256
#define BK 64
#define NKC (DIMW / BK)
#define A_TILE_B (BM * 128)
#define B_TILE_B (BN * 128)
#define STAGE_B (A_TILE_B + B_TILE_B)           // 48 KB
#define NSTAGE 4
#define GEMM_SMEM (NSTAGE * STAGE_B)            // 192 KB

// ---------------- scratch (__device__ globals; no allocation allowed) -------
__device__ __half g_qh[(size_t)M_TOT * DIMW];
__device__ __half g_kh[(size_t)M_TOT * DIMW];
__device__ __half g_vh[(size_t)M_TOT * DIMW];
__device__ __half g_oh[(size_t)M_TOT * DIMW];

__device__ __half g_xh[(size_t)M_TOT * DIMW];
__device__ __half g_yh[(size_t)M_TOT * DIMW];

__device__ float2 g_stq[M_TOT];   // (mean, rstd) for q rows
__device__ float2 g_stk[M_TOT];   // (mean, rstd) for k rows

__device__ __half g_Wq[DIMW * DIMW];
__device__ __half g_Wk[DIMW * DIMW];
__device__ __half g_Wv[DIMW * DIMW];
__device__ __half g_Wo[DIMW * DIMW];

// ---------------- small asm helpers ------------------------------------------
__device__ __forceinline__ uint32_t smem_u32(const void* p) {
    uint32_t a;
    asm("{ .reg .u64 t; cvta.to.shared.u64 t, %1; cvt.u32.u64 %0, t; }"
        : "=r"(a) : "l"(p));
    return a;
}
__device__ __forceinline__ void cp16(uint32_t dst, const void* src) {
    asm volatile("cp.async.cg.shared.global [%0], [%1], 16;"
                 :: "r"(dst), "l"(src) : "memory");
}
__device__ __forceinline__ void cp_commit() {
    asm volatile("cp.async.commit_group;" ::: "memory");
}
template <int N>
__device__ __forceinline__ void cp_wait() {
    asm volatile("cp.async.wait_group %0;" :: "n"(N) : "memory");
}
__device__ __forceinline__ void ldsm4(uint32_t* r, uint32_t addr) {
    asm volatile("ldmatrix.sync.aligned.m8n8.x4.shared.b16 {%0,%1,%2,%3}, [%4];"
                 : "=r"(r[0]), "=r"(r[1]), "=r"(r[2]), "=r"(r[3]) : "r"(addr));
}
__device__ __forceinline__ void mma16816(float* d, const uint32_t* a,
                                         uint32_t b0, uint32_t b1) {
    asm volatile(
        "mma.sync.aligned.m16n8k16.row.col.f32.f16.f16.f32 "
        "{%0,%1,%2,%3}, {%4,%5,%6,%7}, {%8,%9}, {%0,%1,%2,%3};"
        : "+f"(d[0]), "+f"(d[1]), "+f"(d[2]), "+f"(d[3])
        : "r"(a[0]), "r"(a[1]), "r"(a[2]), "r"(a[3]), "r"(b0), "r"(b1));
}

// ---------------- fp32 -> fp16 convert (x, y activations) -------------------
__global__ __launch_bounds__(256) void cvt_kernel(const float4* __restrict__ in0,
                                                  const float4* __restrict__ in1,
                                                  uint2* __restrict__ o0,
                                                  uint2* __restrict__ o1, int n4)
{
    int i = blockIdx.x * blockDim.x + threadIdx.x;
    if (i >= n4) return;
    const float4* src = blockIdx.y ? in1 : in0;
    uint2* dst = blockIdx.y ? o1 : o0;
    float4 v = src[i];
    uint2 H;
    H.x = (uint32_t)__half_as_ushort(__float2half_rn(v.x)) |
          ((uint32_t)__half_as_ushort(__float2half_rn(v.y)) << 16);
    H.y = (uint32_t)__half_as_ushort(__float2half_rn(v.z)) |
          ((uint32_t)__half_as_ushort(__float2half_rn(v.w)) << 16);
    dst[i] = H;
}

// ---------------- fp32 -> fp16 round (weights, 4 at once) -------------------
__global__ __launch_bounds__(256) void wconv_kernel(const float4* __restrict__ w0,
                                                    const float4* __restrict__ w1,
                                                    const float4* __restrict__ w2,
                                                    const float4* __restrict__ w3,
                                                    uint2* __restrict__ o0,
                                                    uint2* __restrict__ o1,
                                                    uint2* __restrict__ o2,
                                                    uint2* __restrict__ o3, int n4)
{
    int i = blockIdx.x * blockDim.x + threadIdx.x;
    if (i >= n4) return;
    const float4* src = (blockIdx.y == 0) ? w0 : (blockIdx.y == 1) ? w1
                        : (blockIdx.y == 2) ? w2 : w3;
    uint2* dst = (blockIdx.y == 0) ? o0 : (blockIdx.y == 1) ? o1
                 : (blockIdx.y == 2) ? o2 : o3;
    float4 v = src[i];
    uint2 H;
    H.x = (uint32_t)__half_as_ushort(__float2half_rn(v.x)) |
          ((uint32_t)__half_as_ushort(__float2half_rn(v.y)) << 16);
    H.y = (uint32_t)__half_as_ushort(__float2half_rn(v.z)) |
          ((uint32_t)__half_as_ushort(__float2half_rn(v.w)) << 16);
    dst[i] = H;
}

// ---------------- fp16 warp-MMA GEMM (512 threads, BM128 x BN256) ------------
__device__ __forceinline__ void load_stage(uint32_t sbase,
    const __half* __restrict__ A, const __half* __restrict__ B,
    int m0, int n0, int kc, int tid)
{
    const int kcol = kc * BK;
    #pragma unroll
    for (int i = 0; i < 2; ++i) {
        int idx = tid + i * 512;
        int row = idx >> 3;
        int ch  = idx & 7;
        uint32_t soff = row * 128 + (((ch ^ (row & 7)) << 4));
        size_t ga = (size_t)(m0 + row) * DIMW + kcol + ch * 8;
        cp16(sbase + soff, A + ga);
    }
    #pragma unroll
    for (int i = 0; i < 4; ++i) {
        int idx = tid + i * 512;
        int row = idx >> 3;
        int ch  = idx & 7;
        uint32_t soff = row * 128 + (((ch ^ (row & 7)) << 4));
        size_t gb = (size_t)(n0 + row) * DIMW + kcol + ch * 8;
        cp16(sbase + A_TILE_B + soff, B + gb);
    }
    cp_commit();
}

// mode: 1 = fp32 + resid + bias, 2 = fp16 output
__device__ __forceinline__ void gemm_body(
    const __half* __restrict__ A, const __half* __restrict__ B,
    float* __restrict__ C, __half* __restrict__ C16,
    const float* __restrict__ Yadd, const float* __restrict__ bias, int mode)
{
    extern __shared__ char dsm[];
    const uint32_t sb = smem_u32(dsm);

    const int tid  = threadIdx.x;
    const int wid  = tid >> 5;
    const int lane = tid & 31;
    const int warp_m = wid >> 2;
    const int warp_n = wid & 3;
    const int m0 = blockIdx.y * BM;
    const int n0 = blockIdx.x * BN;

    float acc[2][8][4];
    #pragma unroll
    for (int a = 0; a < 2; ++a)
        #pragma unroll
        for (int b = 0; b < 8; ++b)
            #pragma unroll
            for (int c = 0; c < 4; ++c) acc[a][b][c] = 0.f;

    #pragma unroll
    for (int s = 0; s < NSTAGE - 1; ++s)
        load_stage(sb + s * STAGE_B, A, B, m0, n0, s, tid);

    const int frag_row = lane & 15;
    const int frag_ch  = lane >> 4;

    #pragma unroll 1
    for (int kc = 0; kc < NKC; ++kc) {
        cp_wait<NSTAGE - 2>();
        __syncthreads();

        const uint32_t st = sb + (kc % NSTAGE) * STAGE_B;
        const uint32_t sA = st;
        const uint32_t sB = st + A_TILE_B;

        #pragma unroll
        for (int kk = 0; kk < 4; ++kk) {
            uint32_t ah[2][4];
            #pragma unroll
            for (int mi = 0; mi < 2; ++mi) {
                int row = warp_m * 32 + mi * 16 + frag_row;
                int ch  = kk * 2 + frag_ch;
                uint32_t off = row * 128 + (((ch ^ (row & 7)) << 4));
                ldsm4(ah[mi], sA + off);
            }
            uint32_t bh[4][4];
            #pragma unroll
            for (int ng = 0; ng < 4; ++ng) {
                int row = warp_n * 64 + ng * 16 + frag_row;
                int ch  = kk * 2 + frag_ch;
                uint32_t off = row * 128 + (((ch ^ (row & 7)) << 4));
                ldsm4(bh[ng], sB + off);
            }
            #pragma unroll
            for (int mi = 0; mi < 2; ++mi)
                #pragma unroll
                for (int ng = 0; ng < 4; ++ng) {
                    mma16816(acc[mi][ng * 2],     ah[mi], bh[ng][0], bh[ng][2]);
                    mma16816(acc[mi][ng * 2 + 1], ah[mi], bh[ng][1], bh[ng][3]);
                }
        }

        __syncthreads();
        if (kc + NSTAGE - 1 < NKC)
            load_stage(sb + ((kc + NSTAGE - 1) % NSTAGE) * STAGE_B, A, B,
                       m0, n0, kc + NSTAGE - 1, tid);
    }

    const int erow = lane >> 2;
    const int ecol = (lane & 3) * 2;
    #pragma unroll
    for (int mi = 0; mi < 2; ++mi) {
        #pragma unroll
        for (int ni = 0; ni < 8; ++ni) {
            size_t r0 = (size_t)m0 + warp_m * 32 + mi * 16 + erow;
            int    c  = n0 + warp_n * 64 + ni * 8 + ecol;
            float2 v0 = make_float2(acc[mi][ni][0], acc[mi][ni][1]);
            float2 v1 = make_float2(acc[mi][ni][2], acc[mi][ni][3]);
            if (mode == 2) {
                __half2 h0 = __floats2half2_rn(v0.x, v0.y);
                __half2 h1 = __floats2half2_rn(v1.x, v1.y);
                *reinterpret_cast<__half2*>(C16 + r0 * DIMW + c)       = h0;
                *reinterpret_cast<__half2*>(C16 + (r0 + 8) * DIMW + c) = h1;
            } else {
                float2 y0 = *(const float2*)(Yadd + r0 * DIMW + c);
                float2 y1 = *(const float2*)(Yadd + (r0 + 8) * DIMW + c);
                float2 bv = *(const float2*)(bias + c);
                v0.x += y0.x + bv.x; v0.y += y0.y + bv.y;
                v1.x += y1.x + bv.x; v1.y += y1.y + bv.y;
                *(float2*)(C + r0 * DIMW + c)       = v0;
                *(float2*)(C + (r0 + 8) * DIMW + c) = v1;
            }
        }
    }
}

__global__ __launch_bounds__(512, 1) void qkv_gemm()
{
    if (blockIdx.z == 0)
        gemm_body(g_yh, g_Wq, nullptr, g_qh, nullptr, nullptr, 2);
    else if (blockIdx.z == 1)
        gemm_body(g_xh, g_Wk, nullptr, g_kh, nullptr, nullptr, 2);
    else
        gemm_body(g_xh, g_Wv, nullptr, g_vh, nullptr, nullptr, 2);
}

__global__ __launch_bounds__(512, 1) void out_gemm(const float* __restrict__ y,
                                                   const float* __restrict__ bout,
                                                   float* __restrict__ ynew)
{
    gemm_body(g_oh, g_Wo, ynew, nullptr, y, bout, 1);
}

// ---------------- LN row stats from fp16: one warp per row, shfl-only --------
__global__ __launch_bounds__(256) void stats_kernel()
{
    const __half* buf = blockIdx.y ? g_kh : g_qh;
    float2* st        = blockIdx.y ? g_stk : g_stq;
    const int row  = blockIdx.x * 8 + (threadIdx.x >> 5);
    const int lane = threadIdx.x & 31;
    const uint4* p = (const uint4*)(buf + (size_t)row * DIMW) + lane;

    float s = 0.f, sq = 0.f;
    #pragma unroll
    for (int i = 0; i < 2; ++i) {
        uint4 v = p[i * 32];
        #pragma unroll
        for (int w = 0; w < 4; ++w) {
            uint32_t raw = (&v.x)[w];
            float2 f = __half22float2(*reinterpret_cast<__half2*>(&raw));
            s  += f.x + f.y;
            sq += f.x * f.x + f.y * f.y;
        }
    }
    #pragma unroll
    for (int o = 16; o > 0; o >>= 1) {
        s  += __shfl_xor_sync(0xffffffffu, s,  o);
        sq += __shfl_xor_sync(0xffffffffu, sq, o);
    }
    if (lane == 0) {
        float mean = s * (1.f / 512.f);
        float var  = sq * (1.f / 512.f) - mean * mean;
        st[row] = make_float2(mean, rsqrtf(var + 1e-5f));
    }
}

// ---------------- tensor-core windowed attention, 2 blocks/SM ----------------
// smem layout (bytes), all tiles 256B row stride (16B-aligned for ldmatrix):
//   Qh  [128][64] fp16 swizzled 128B rows        @ 0       (16384)
//   Kh  [128][64] fp16 swizzled                  @ 16384   (16384)
//   Vt  [64][128] fp16, 256B stride, swizzled    @ 32768   (16384)
//   P   [128][128] fp16, 256B stride, swizzled   @ 49152   (32768)
//   mx  float[128][2]                            @ 81920   (1024)
//   sm  float[128][2]                            @ 82944   (1024)
//   stq float2[128]                              @ 83968   (1024)
//   stk float2[128]                              @ 84992   (1024)
//   sgq/sbq/sgk/sbk float[64] each               @ 86016   (1024)
#define AQ_OFF   0
#define AK_OFF   16384
#define AVT_OFF  32768
#define AP_OFF   49152
#define AMX_OFF  81920
#define ASM_OFF  82944
#define ASTQ_OFF 83968
#define ASTK_OFF 84992
#define ASG_OFF  86016
#define ATTN_SMEM 87040
#define TSTRIDE  256

__global__ __launch_bounds__(256, 2) void attn_kernel(
    float* __restrict__ attn_out,
    const float* __restrict__ gq, const float* __restrict__ bq,
    const float* __restrict__ gk, const float* __restrict__ bk)
{
    extern __shared__ char asm_[];
    const uint32_t sb = smem_u32(asm_);
    float2* stq = (float2*)(asm_ + ASTQ_OFF);
    float2* stk = (float2*)(asm_ + ASTK_OFF);
    float*  sgq = (float*)(asm_ + ASG_OFF);
    float*  sbq = sgq + 64;
    float*  sgk = sgq + 128;
    float*  sbk = sgq + 192;
    float*  mxb = (float*)(asm_ + AMX_OFF);
    float*  smb = (float*)(asm_ + ASM_OFF);

    const int tid = threadIdx.x;
    const int bwh = blockIdx.x;        // bw*8 + h
    const int bw  = bwh >> 3;
    const int h   = bwh & 7;
    const size_t rowbase = (size_t)bw * WIN;
    const int coloff = h * DHEAD;

    if (tid < 128) {
        stq[tid] = g_stq[rowbase + tid];
        stk[tid] = g_stk[rowbase + tid];
    } else if (tid < 192) {
        int d = tid - 128;
        sgq[d] = gq[coloff + d] * 0.125f;
        sbq[d] = bq[coloff + d] * 0.125f;
        sgk[d] = gk[coloff + d];
        sbk[d] = bk[coloff + d];
    }
    __syncthreads();

    // ---- load: q,k (fp16 -> LN fp32 -> fp16, swizzled), v -> Vt transposed --
    #pragma unroll
    for (int it = 0; it < 8; ++it) {
        int idx = tid + it * 256;      // 0..2047
        int i   = idx >> 4;            // row 0..127
        int d4  = (idx & 15) << 2;     // 0..60
        size_t goff = (rowbase + i) * DIMW + coloff + d4;
        uint2 qraw = *(const uint2*)(g_qh + goff);
        uint2 kraw = *(const uint2*)(g_kh + goff);
        uint2 vraw = *(const uint2*)(g_vh + goff);

        float2 q01 = __half22float2(*reinterpret_cast<__half2*>(&qraw.x));
        float2 q23 = __half22float2(*reinterpret_cast<__half2*>(&qraw.y));
        float2 k01 = __half22float2(*reinterpret_cast<__half2*>(&kraw.x));
        float2 k23 = __half22float2(*reinterpret_cast<__half2*>(&kraw.y));

        float2 sq_ = stq[i];
        float2 sk_ = stk[i];
        __half2 qh0 = __floats2half2_rn(
            (q01.x - sq_.x) * sq_.y * sgq[d4 + 0] + sbq[d4 + 0],
            (q01.y - sq_.x) * sq_.y * sgq[d4 + 1] + sbq[d4 + 1]);
        __half2 qh1 = __floats2half2_rn(
            (q23.x - sq_.x) * sq_.y * sgq[d4 + 2] + sbq[d4 + 2],
            (q23.y - sq_.x) * sq_.y * sgq[d4 + 3] + sbq[d4 + 3]);
        __half2 kh0 = __floats2half2_rn(
            (k01.x - sk_.x) * sk_.y * sgk[d4 + 0] + sbk[d4 + 0],
            (k01.y - sk_.x) * sk_.y * sgk[d4 + 1] + sbk[d4 + 1]);
        __half2 kh1 = __floats2half2_rn(
            (k23.x - sk_.x) * sk_.y * sgk[d4 + 2] + sbk[d4 + 2],
            (k23.y - sk_.x) * sk_.y * sgk[d4 + 3] + sbk[d4 + 3]);

        uint32_t qkoff = i * 128 + (((d4 >> 3) ^ (i & 7)) << 4) + (d4 & 7) * 2;
        *(__half2*)(asm_ + AQ_OFF + qkoff)     = qh0;
        *(__half2*)(asm_ + AQ_OFF + qkoff + 4) = qh1;
        *(__half2*)(asm_ + AK_OFF + qkoff)     = kh0;
        *(__half2*)(asm_ + AK_OFF + qkoff + 4) = kh1;

        // Vt[d][j=i], scalar half stores
        const __half* vh = reinterpret_cast<const __half*>(&vraw);
        #pragma unroll
        for (int w = 0; w < 4; ++w) {
            int d = d4 + w;
            uint32_t off = d * TSTRIDE + (((i >> 3) ^ (d & 7)) << 4) + (i & 7) * 2;
            *(__half*)(asm_ + AVT_OFF + off) = vh[w];
        }
    }
    __syncthreads();

    const int wid  = tid >> 5;
    const int lane = tid & 31;
    const int warp_m = wid >> 1;       // 0..3 -> 32 rows
    const int warp_n = wid & 1;        // 0..1 -> 64 cols (j or d)
    const int frag_row = lane & 15;
    const int frag_ch  = lane >> 4;
    const int erow = lane >> 2;
    const int equad = lane & 3;

    // ---- QK^T via HMMA: acc[mi][ni][4], rows warp_m*32+mi*16, cols warp_n*64+ni*8
    float acc[2][8][4];
    #pragma unroll
    for (int a = 0; a < 2; ++a)
        #pragma unroll
        for (int b = 0; b < 8; ++b)
            #pragma unroll
            for (int c = 0; c < 4; ++c) acc[a][b][c] = 0.f;

    #pragma unroll
    for (int kk = 0; kk < 4; ++kk) {
        uint32_t ah[2][4];
        #pragma unroll
        for (int mi = 0; mi < 2; ++mi) {
            int row = warp_m * 32 + mi * 16 + frag_row;
            int ch  = kk * 2 + frag_ch;
            ldsm4(ah[mi], sb + AQ_OFF + row * 128 + (((ch ^ (row & 7)) << 4)));
        }
        uint32_t bh[4][4];
        #pragma unroll
        for (int ng = 0; ng < 4; ++ng) {
            int row = warp_n * 64 + ng * 16 + frag_row;
            int ch  = kk * 2 + frag_ch;
            ldsm4(bh[ng], sb + AK_OFF + row * 128 + (((ch ^ (row & 7)) << 4)));
        }
        #pragma unroll
        for (int mi = 0; mi < 2; ++mi)
            #pragma unroll
            for (int ng = 0; ng < 4; ++ng) {
                mma16816(acc[mi][ng * 2],     ah[mi], bh[ng][0], bh[ng][2]);
                mma16816(acc[mi][ng * 2 + 1], ah[mi], bh[ng][1], bh[ng][3]);
            }
    }

    // ---- softmax on fragments (fp32 exact), cross-warp-pair via smem --------
    #pragma unroll
    for (int mi = 0; mi < 2; ++mi)
        #pragma unroll
        for (int hh = 0; hh < 2; ++hh) {
            float m = -1e30f;
            #pragma unroll
            for (int ni = 0; ni < 8; ++ni) {
                m = fmaxf(m, acc[mi][ni][hh * 2]);
                m = fmaxf(m, acc[mi][ni][hh * 2 + 1]);
            }
            m = fmaxf(m, __shfl_xor_sync(0xffffffffu, m, 1));
            m = fmaxf(m, __shfl_xor_sync(0xffffffffu, m, 2));
            if (equad == 0) {
                int row = warp_m * 32 + mi * 16 + hh * 8 + erow;
                mxb[row * 2 + warp_n] = m;
            }
        }
    __syncthreads();

    #pragma unroll
    for (int mi = 0; mi < 2; ++mi)
        #pragma unroll
        for (int hh = 0; hh < 2; ++hh) {
            int row = warp_m * 32 + mi * 16 + hh * 8 + erow;
            float m = fmaxf(mxb[row * 2], mxb[row * 2 + 1]);
            float s = 0.f;
            #pragma unroll
            for (int ni = 0; ni < 8; ++ni) {
                float e0 = __expf(acc[mi][ni][hh * 2]     - m);
                float e1 = __expf(acc[mi][ni][hh * 2 + 1] - m);
                acc[mi][ni][hh * 2]     = e0;
                acc[mi][ni][hh * 2 + 1] = e1;
                s += e0 + e1;
            }
            s += __shfl_xor_sync(0xffffffffu, s, 1);
            s += __shfl_xor_sync(0xffffffffu, s, 2);
            if (equad == 0)
                smb[row * 2 + warp_n] = s;
        }
    __syncthreads();

    // ---- scale, write attn (fp32) + P (fp16 smem) ---------------------------
    const size_t abase = (size_t)bwh * WIN * WIN;
    #pragma unroll
    for (int mi = 0; mi < 2; ++mi)
        #pragma unroll
        for (int hh = 0; hh < 2; ++hh) {
            int row = warp_m * 32 + mi * 16 + hh * 8 + erow;
            float inv = 1.0f / (smb[row * 2] + smb[row * 2 + 1]);
            #pragma unroll
            for (int ni = 0; ni < 8; ++ni) {
                float p0 = acc[mi][ni][hh * 2]     * inv;
                float p1 = acc[mi][ni][hh * 2 + 1] * inv;
                int col = warp_n * 64 + ni * 8 + equad * 2;
                *(float2*)(attn_out + abase + (size_t)row * WIN + col) =
                    make_float2(p0, p1);
                uint32_t off = row * TSTRIDE +
                               (((col >> 3) ^ (row & 7)) << 4) + (col & 7) * 2;
                *(__half2*)(asm_ + AP_OFF + off) = __floats2half2_rn(p0, p1);
            }
        }
    __syncthreads();

    // ---- P @ V via HMMA: out rows = warp_m*32, d cols = warp_n*32 -----------
    float oac[2][4][4];
    #pragma unroll
    for (int a = 0; a < 2; ++a)
        #pragma unroll
        for (int b = 0; b < 4; ++b)
            #pragma unroll
            for (int c = 0; c < 4; ++c) oac[a][b][c] = 0.f;

    #pragma unroll
    for (int kk = 0; kk < 8; ++kk) {
        uint32_t ap[2][4];
        #pragma unroll
        for (int mi = 0; mi < 2; ++mi) {
            int row = warp_m * 32 + mi * 16 + frag_row;
            int ch  = kk * 2 + frag_ch;
            ldsm4(ap[mi], sb + AP_OFF + row * TSTRIDE +
                           (((ch ^ (row & 7)) << 4)));
        }
        uint32_t bv[2][4];
        #pragma unroll
        for (int ng = 0; ng < 2; ++ng) {
            int d  = warp_n * 32 + ng * 16 + frag_row;
            int ch = kk * 2 + frag_ch;
            ldsm4(bv[ng], sb + AVT_OFF + d * TSTRIDE +
                           (((ch ^ (d & 7)) << 4)));
        }
        #pragma unroll
        for (int mi = 0; mi < 2; ++mi)
            #pragma unroll
            for (int ng = 0; ng < 2; ++ng) {
                mma16816(oac[mi][ng * 2],     ap[mi], bv[ng][0], bv[ng][2]);
                mma16816(oac[mi][ng * 2 + 1], ap[mi], bv[ng][1], bv[ng][3]);
            }
    }

    // ---- write o (fp16) -----------------------------------------------------
    #pragma unroll
    for (int mi = 0; mi < 2; ++mi)
        #pragma unroll
        for (int ni = 0; ni < 4; ++ni) {
            int r0 = warp_m * 32 + mi * 16 + erow;
            int c  = coloff + warp_n * 32 + ni * 8 + equad * 2;
            size_t go0 = (rowbase + r0) * DIMW + c;
            size_t go1 = (rowbase + r0 + 8) * DIMW + c;
            *(__half2*)(g_oh + go0) = __floats2half2_rn(oac[mi][ni][0], oac[mi][ni][1]);
            *(__half2*)(g_oh + go1) = __floats2half2_rn(oac[mi][ni][2], oac[mi][ni][3]);
        }
}

// ---------------- launcher ---------------------------------------------------
extern "C" void kernel_launch(void* const* d_in, const int* in_sizes, int n_in,
                              void* d_out, int out_size)
{
    const float* x  = (const float*)d_in[0];
    const float* y  = (const float*)d_in[1];
    const float* Wq = (const float*)d_in[2];
    const float* gq = (const float*)d_in[3];
    const float* bq = (const float*)d_in[4];
    const float* Wk = (const float*)d_in[5];
    const float* gk = (const float*)d_in[6];
    const float* bk = (const float*)d_in[7];
    const float* Wv = (const float*)d_in[8];
    const float* Wo = (const float*)d_in[9];
    const float* bo = (const float*)d_in[10];

    float* ynew = (float*)d_out;
    float* attn = ynew + (size_t)M_TOT * DIMW;

    void *p_xh, *p_yh;
    void *p_wq, *p_wk, *p_wv, *p_wo;
    cudaGetSymbolAddress(&p_xh, g_xh);  cudaGetSymbolAddress(&p_yh, g_yh);
    cudaGetSymbolAddress(&p_wq, g_Wq);  cudaGetSymbolAddress(&p_wk, g_Wk);
    cudaGetSymbolAddress(&p_wv, g_Wv);  cudaGetSymbolAddress(&p_wo, g_Wo);

    cudaFuncSetAttribute(attn_kernel,
                         cudaFuncAttributeMaxDynamicSharedMemorySize, ATTN_SMEM);
    cudaFuncSetAttribute(qkv_gemm,
                         cudaFuncAttributeMaxDynamicSharedMemorySize, GEMM_SMEM);
    cudaFuncSetAttribute(out_gemm,
                         cudaFuncAttributeMaxDynamicSharedMemorySize, GEMM_SMEM);

    // 1) convert activations and weights to fp16
    const int n4_act = (M_TOT * DIMW) / 4;
    const int n4_w   = (DIMW * DIMW) / 4;
    cvt_kernel<<<dim3((n4_act + 255) / 256, 2), 256>>>(
        (const float4*)x, (const float4*)y, (uint2*)p_xh, (uint2*)p_yh, n4_act);
    wconv_kernel<<<dim3((n4_w + 255) / 256, 4), 256>>>(
        (const float4*)Wq, (const float4*)Wk, (const float4*)Wv, (const float4*)Wo,
        (uint2*)p_wq, (uint2*)p_wk, (uint2*)p_wv, (uint2*)p_wo, n4_w);

    // 2) q/k/v projections (warp-MMA fp16; q,k,v all written fp16)
    qkv_gemm<<<dim3(DIMW / BN, M_TOT / BM, 3), 512, GEMM_SMEM>>>();

    // 3) LN row stats for q, k (fp16 input)
    stats_kernel<<<dim3(M_TOT / 8, 2), 256>>>();

    // 4) tensor-core windowed attention -> attn (fp32) + fp16 o
    attn_kernel<<<4096, 256, ATTN_SMEM>>>(attn, gq, bq, gk, bk);

    // 5) final projection with residual epilogue
    out_gemm<<<dim3(DIMW / BN, M_TOT / BM), 512, GEMM_SMEM>>>(y, bo, ynew);
}

// round 13
// speedup vs baseline: 5.6040x; 1.0837x over previous
#include <cuda_runtime.h>
#include <cuda_fp16.h>
#include <cstdint>

#define M_TOT 65536      // B*N rows
#define DIMW  512        // DIM == INNER
#define WIN   128
#define NHEAD 8
#define DHEAD 64

// GEMM tiling (warp-MMA, mma.sync m16n8k16 fp16), 256 thr, 2 CTA/SM
#define BM 128
#define BN 128
#define BK 64
#define NKC (DIMW / BK)
#define A_TILE_B (BM * 128)                     // 16 KB
#define B_TILE_B (BN * 128)                     // 16 KB
#define STAGE_B (A_TILE_B + B_TILE_B)           // 32 KB
#define NSTAGE 3
#define GEMM_SMEM (NSTAGE * STAGE_B)            // 96 KB

// ---------------- scratch (__device__ globals; no allocation allowed) -------
__device__ __half g_qh[(size_t)M_TOT * DIMW];
__device__ __half g_kh[(size_t)M_TOT * DIMW];
__device__ __half g_vh[(size_t)M_TOT * DIMW];
__device__ __half g_oh[(size_t)M_TOT * DIMW];

__device__ __half g_xh[(size_t)M_TOT * DIMW];
__device__ __half g_yh[(size_t)M_TOT * DIMW];

__device__ float2 g_stq[M_TOT];   // (mean, rstd) for q rows
__device__ float2 g_stk[M_TOT];   // (mean, rstd) for k rows

__device__ __half g_Wq[DIMW * DIMW];
__device__ __half g_Wk[DIMW * DIMW];
__device__ __half g_Wv[DIMW * DIMW];
__device__ __half g_Wo[DIMW * DIMW];

// ---------------- small asm helpers ------------------------------------------
__device__ __forceinline__ uint32_t smem_u32(const void* p) {
    uint32_t a;
    asm("{ .reg .u64 t; cvta.to.shared.u64 t, %1; cvt.u32.u64 %0, t; }"
        : "=r"(a) : "l"(p));
    return a;
}
__device__ __forceinline__ void cp16(uint32_t dst, const void* src) {
    asm volatile("cp.async.cg.shared.global [%0], [%1], 16;"
                 :: "r"(dst), "l"(src) : "memory");
}
__device__ __forceinline__ void cp_commit() {
    asm volatile("cp.async.commit_group;" ::: "memory");
}
template <int N>
__device__ __forceinline__ void cp_wait() {
    asm volatile("cp.async.wait_group %0;" :: "n"(N) : "memory");
}
__device__ __forceinline__ void ldsm4(uint32_t* r, uint32_t addr) {
    asm volatile("ldmatrix.sync.aligned.m8n8.x4.shared.b16 {%0,%1,%2,%3}, [%4];"
                 : "=r"(r[0]), "=r"(r[1]), "=r"(r[2]), "=r"(r[3]) : "r"(addr));
}
__device__ __forceinline__ void mma16816(float* d, const uint32_t* a,
                                         uint32_t b0, uint32_t b1) {
    asm volatile(
        "mma.sync.aligned.m16n8k16.row.col.f32.f16.f16.f32 "
        "{%0,%1,%2,%3}, {%4,%5,%6,%7}, {%8,%9}, {%0,%1,%2,%3};"
        : "+f"(d[0]), "+f"(d[1]), "+f"(d[2]), "+f"(d[3])
        : "r"(a[0]), "r"(a[1]), "r"(a[2]), "r"(a[3]), "r"(b0), "r"(b1));
}

// ---------------- fp32 -> fp16 convert (x, y activations) -------------------
__global__ __launch_bounds__(256) void cvt_kernel(const float4* __restrict__ in0,
                                                  const float4* __restrict__ in1,
                                                  uint2* __restrict__ o0,
                                                  uint2* __restrict__ o1, int n4)
{
    int i = blockIdx.x * blockDim.x + threadIdx.x;
    if (i >= n4) return;
    const float4* src = blockIdx.y ? in1 : in0;
    uint2* dst = blockIdx.y ? o1 : o0;
    float4 v = src[i];
    uint2 H;
    H.x = (uint32_t)__half_as_ushort(__float2half_rn(v.x)) |
          ((uint32_t)__half_as_ushort(__float2half_rn(v.y)) << 16);
    H.y = (uint32_t)__half_as_ushort(__float2half_rn(v.z)) |
          ((uint32_t)__half_as_ushort(__float2half_rn(v.w)) << 16);
    dst[i] = H;
}

// ---------------- fp32 -> fp16 round (weights, 4 at once) -------------------
__global__ __launch_bounds__(256) void wconv_kernel(const float4* __restrict__ w0,
                                                    const float4* __restrict__ w1,
                                                    const float4* __restrict__ w2,
                                                    const float4* __restrict__ w3,
                                                    uint2* __restrict__ o0,
                                                    uint2* __restrict__ o1,
                                                    uint2* __restrict__ o2,
                                                    uint2* __restrict__ o3, int n4)
{
    int i = blockIdx.x * blockDim.x + threadIdx.x;
    if (i >= n4) return;
    const float4* src = (blockIdx.y == 0) ? w0 : (blockIdx.y == 1) ? w1
                        : (blockIdx.y == 2) ? w2 : w3;
    uint2* dst = (blockIdx.y == 0) ? o0 : (blockIdx.y == 1) ? o1
                 : (blockIdx.y == 2) ? o2 : o3;
    float4 v = src[i];
    uint2 H;
    H.x = (uint32_t)__half_as_ushort(__float2half_rn(v.x)) |
          ((uint32_t)__half_as_ushort(__float2half_rn(v.y)) << 16);
    H.y = (uint32_t)__half_as_ushort(__float2half_rn(v.z)) |
          ((uint32_t)__half_as_ushort(__float2half_rn(v.w)) << 16);
    dst[i] = H;
}

// ---------------- fp16 warp-MMA GEMM (256 threads, BM128 x BN128) ------------
__device__ __forceinline__ void load_stage(uint32_t sbase,
    const __half* __restrict__ A, const __half* __restrict__ B,
    int m0, int n0, int kc, int tid)
{
    const int kcol = kc * BK;
    #pragma unroll
    for (int i = 0; i < 4; ++i) {               // A: 128 rows x 8 ch = 1024
        int idx = tid + i * 256;
        int row = idx >> 3;
        int ch  = idx & 7;
        uint32_t soff = row * 128 + (((ch ^ (row & 7)) << 4));
        size_t ga = (size_t)(m0 + row) * DIMW + kcol + ch * 8;
        size_t gb = (size_t)(n0 + row) * DIMW + kcol + ch * 8;
        cp16(sbase + soff,            A + ga);
        cp16(sbase + A_TILE_B + soff, B + gb);
    }
    cp_commit();
}

// mode: 1 = fp32 + resid + bias, 2 = fp16 output
__device__ __forceinline__ void gemm_body(
    const __half* __restrict__ A, const __half* __restrict__ B,
    float* __restrict__ C, __half* __restrict__ C16,
    const float* __restrict__ Yadd, const float* __restrict__ bias, int mode)
{
    extern __shared__ char dsm[];
    const uint32_t sb = smem_u32(dsm);

    const int tid  = threadIdx.x;
    const int wid  = tid >> 5;
    const int lane = tid & 31;
    const int warp_m = wid >> 1;      // 0..3 -> 32 rows each
    const int warp_n = wid & 1;       // 0..1 -> 64 cols each
    const int m0 = blockIdx.y * BM;
    const int n0 = blockIdx.x * BN;

    float acc[2][8][4];
    #pragma unroll
    for (int a = 0; a < 2; ++a)
        #pragma unroll
        for (int b = 0; b < 8; ++b)
            #pragma unroll
            for (int c = 0; c < 4; ++c) acc[a][b][c] = 0.f;

    #pragma unroll
    for (int s = 0; s < NSTAGE - 1; ++s)
        load_stage(sb + s * STAGE_B, A, B, m0, n0, s, tid);

    const int frag_row = lane & 15;
    const int frag_ch  = lane >> 4;

    #pragma unroll 1
    for (int kc = 0; kc < NKC; ++kc) {
        cp_wait<NSTAGE - 2>();
        __syncthreads();

        const uint32_t st = sb + (kc % NSTAGE) * STAGE_B;
        const uint32_t sA = st;
        const uint32_t sB = st + A_TILE_B;

        // issue next-stage loads first (overlap with this chunk's MMAs);
        // target stage (kc+NSTAGE-1)%NSTAGE was last read at iter kc-1, and the
        // barrier above guarantees all threads finished that iteration.
        if (kc + NSTAGE - 1 < NKC)
            load_stage(sb + ((kc + NSTAGE - 1) % NSTAGE) * STAGE_B, A, B,
                       m0, n0, kc + NSTAGE - 1, tid);

        #pragma unroll
        for (int kk = 0; kk < 4; ++kk) {
            uint32_t ah[2][4];
            #pragma unroll
            for (int mi = 0; mi < 2; ++mi) {
                int row = warp_m * 32 + mi * 16 + frag_row;
                int ch  = kk * 2 + frag_ch;
                uint32_t off = row * 128 + (((ch ^ (row & 7)) << 4));
                ldsm4(ah[mi], sA + off);
            }
            uint32_t bh[4][4];
            #pragma unroll
            for (int ng = 0; ng < 4; ++ng) {
                int row = warp_n * 64 + ng * 16 + frag_row;
                int ch  = kk * 2 + frag_ch;
                uint32_t off = row * 128 + (((ch ^ (row & 7)) << 4));
                ldsm4(bh[ng], sB + off);
            }
            #pragma unroll
            for (int mi = 0; mi < 2; ++mi)
                #pragma unroll
                for (int ng = 0; ng < 4; ++ng) {
                    mma16816(acc[mi][ng * 2],     ah[mi], bh[ng][0], bh[ng][2]);
                    mma16816(acc[mi][ng * 2 + 1], ah[mi], bh[ng][1], bh[ng][3]);
                }
        }
    }

    const int erow = lane >> 2;
    const int ecol = (lane & 3) * 2;
    #pragma unroll
    for (int mi = 0; mi < 2; ++mi) {
        #pragma unroll
        for (int ni = 0; ni < 8; ++ni) {
            size_t r0 = (size_t)m0 + warp_m * 32 + mi * 16 + erow;
            int    c  = n0 + warp_n * 64 + ni * 8 + ecol;
            float2 v0 = make_float2(acc[mi][ni][0], acc[mi][ni][1]);
            float2 v1 = make_float2(acc[mi][ni][2], acc[mi][ni][3]);
            if (mode == 2) {
                __half2 h0 = __floats2half2_rn(v0.x, v0.y);
                __half2 h1 = __floats2half2_rn(v1.x, v1.y);
                *reinterpret_cast<__half2*>(C16 + r0 * DIMW + c)       = h0;
                *reinterpret_cast<__half2*>(C16 + (r0 + 8) * DIMW + c) = h1;
            } else {
                float2 y0 = *(const float2*)(Yadd + r0 * DIMW + c);
                float2 y1 = *(const float2*)(Yadd + (r0 + 8) * DIMW + c);
                float2 bv = *(const float2*)(bias + c);
                v0.x += y0.x + bv.x; v0.y += y0.y + bv.y;
                v1.x += y1.x + bv.x; v1.y += y1.y + bv.y;
                *(float2*)(C + r0 * DIMW + c)       = v0;
                *(float2*)(C + (r0 + 8) * DIMW + c) = v1;
            }
        }
    }
}

__global__ __launch_bounds__(256, 2) void qkv_gemm()
{
    if (blockIdx.z == 0)
        gemm_body(g_yh, g_Wq, nullptr, g_qh, nullptr, nullptr, 2);
    else if (blockIdx.z == 1)
        gemm_body(g_xh, g_Wk, nullptr, g_kh, nullptr, nullptr, 2);
    else
        gemm_body(g_xh, g_Wv, nullptr, g_vh, nullptr, nullptr, 2);
}

__global__ __launch_bounds__(256, 2) void out_gemm(const float* __restrict__ y,
                                                   const float* __restrict__ bout,
                                                   float* __restrict__ ynew)
{
    gemm_body(g_oh, g_Wo, ynew, nullptr, y, bout, 1);
}

// ---------------- LN row stats from fp16: one warp per row, shfl-only --------
__global__ __launch_bounds__(256) void stats_kernel()
{
    const __half* buf = blockIdx.y ? g_kh : g_qh;
    float2* st        = blockIdx.y ? g_stk : g_stq;
    const int row  = blockIdx.x * 8 + (threadIdx.x >> 5);
    const int lane = threadIdx.x & 31;
    const uint4* p = (const uint4*)(buf + (size_t)row * DIMW) + lane;

    float s = 0.f, sq = 0.f;
    #pragma unroll
    for (int i = 0; i < 2; ++i) {
        uint4 v = p[i * 32];
        #pragma unroll
        for (int w = 0; w < 4; ++w) {
            uint32_t raw = (&v.x)[w];
            float2 f = __half22float2(*reinterpret_cast<__half2*>(&raw));
            s  += f.x + f.y;
            sq += f.x * f.x + f.y * f.y;
        }
    }
    #pragma unroll
    for (int o = 16; o > 0; o >>= 1) {
        s  += __shfl_xor_sync(0xffffffffu, s,  o);
        sq += __shfl_xor_sync(0xffffffffu, sq, o);
    }
    if (lane == 0) {
        float mean = s * (1.f / 512.f);
        float var  = sq * (1.f / 512.f) - mean * mean;
        st[row] = make_float2(mean, rsqrtf(var + 1e-5f));
    }
}

// ---------------- tensor-core windowed attention, 2 blocks/SM ----------------
// smem layout (bytes), all tiles 256B-friendly, 16B-aligned ldmatrix rows:
#define AQ_OFF   0
#define AK_OFF   16384
#define AVT_OFF  32768
#define AP_OFF   49152
#define AMX_OFF  81920
#define ASM_OFF  82944
#define ASTQ_OFF 83968
#define ASTK_OFF 84992
#define ASG_OFF  86016
#define ATTN_SMEM 87040
#define TSTRIDE  256

__global__ __launch_bounds__(256, 2) void attn_kernel(
    float* __restrict__ attn_out,
    const float* __restrict__ gq, const float* __restrict__ bq,
    const float* __restrict__ gk, const float* __restrict__ bk)
{
    extern __shared__ char asm_[];
    const uint32_t sb = smem_u32(asm_);
    float2* stq = (float2*)(asm_ + ASTQ_OFF);
    float2* stk = (float2*)(asm_ + ASTK_OFF);
    float*  sgq = (float*)(asm_ + ASG_OFF);
    float*  sbq = sgq + 64;
    float*  sgk = sgq + 128;
    float*  sbk = sgq + 192;
    float*  mxb = (float*)(asm_ + AMX_OFF);
    float*  smb = (float*)(asm_ + ASM_OFF);

    const int tid = threadIdx.x;
    const int bwh = blockIdx.x;        // bw*8 + h
    const int bw  = bwh >> 3;
    const int h   = bwh & 7;
    const size_t rowbase = (size_t)bw * WIN;
    const int coloff = h * DHEAD;

    if (tid < 128) {
        stq[tid] = g_stq[rowbase + tid];
        stk[tid] = g_stk[rowbase + tid];
    } else if (tid < 192) {
        int d = tid - 128;
        sgq[d] = gq[coloff + d] * 0.125f;
        sbq[d] = bq[coloff + d] * 0.125f;
        sgk[d] = gk[coloff + d];
        sbk[d] = bk[coloff + d];
    }
    __syncthreads();

    // ---- load: q,k (fp16 -> LN fp32 -> fp16, swizzled), v -> Vt transposed --
    #pragma unroll
    for (int it = 0; it < 8; ++it) {
        int idx = tid + it * 256;      // 0..2047
        int i   = idx >> 4;            // row 0..127
        int d4  = (idx & 15) << 2;     // 0..60
        size_t goff = (rowbase + i) * DIMW + coloff + d4;
        uint2 qraw = *(const uint2*)(g_qh + goff);
        uint2 kraw = *(const uint2*)(g_kh + goff);
        uint2 vraw = *(const uint2*)(g_vh + goff);

        float2 q01 = __half22float2(*reinterpret_cast<__half2*>(&qraw.x));
        float2 q23 = __half22float2(*reinterpret_cast<__half2*>(&qraw.y));
        float2 k01 = __half22float2(*reinterpret_cast<__half2*>(&kraw.x));
        float2 k23 = __half22float2(*reinterpret_cast<__half2*>(&kraw.y));

        float2 sq_ = stq[i];
        float2 sk_ = stk[i];
        __half2 qh0 = __floats2half2_rn(
            (q01.x - sq_.x) * sq_.y * sgq[d4 + 0] + sbq[d4 + 0],
            (q01.y - sq_.x) * sq_.y * sgq[d4 + 1] + sbq[d4 + 1]);
        __half2 qh1 = __floats2half2_rn(
            (q23.x - sq_.x) * sq_.y * sgq[d4 + 2] + sbq[d4 + 2],
            (q23.y - sq_.x) * sq_.y * sgq[d4 + 3] + sbq[d4 + 3]);
        __half2 kh0 = __floats2half2_rn(
            (k01.x - sk_.x) * sk_.y * sgk[d4 + 0] + sbk[d4 + 0],
            (k01.y - sk_.x) * sk_.y * sgk[d4 + 1] + sbk[d4 + 1]);
        __half2 kh1 = __floats2half2_rn(
            (k23.x - sk_.x) * sk_.y * sgk[d4 + 2] + sbk[d4 + 2],
            (k23.y - sk_.x) * sk_.y * sgk[d4 + 3] + sbk[d4 + 3]);

        uint32_t qkoff = i * 128 + (((d4 >> 3) ^ (i & 7)) << 4) + (d4 & 7) * 2;
        *(__half2*)(asm_ + AQ_OFF + qkoff)     = qh0;
        *(__half2*)(asm_ + AQ_OFF + qkoff + 4) = qh1;
        *(__half2*)(asm_ + AK_OFF + qkoff)     = kh0;
        *(__half2*)(asm_ + AK_OFF + qkoff + 4) = kh1;

        // Vt[d][j=i], scalar half stores
        const __half* vh = reinterpret_cast<const __half*>(&vraw);
        #pragma unroll
        for (int w = 0; w < 4; ++w) {
            int d = d4 + w;
            uint32_t off = d * TSTRIDE + (((i >> 3) ^ (d & 7)) << 4) + (i & 7) * 2;
            *(__half*)(asm_ + AVT_OFF + off) = vh[w];
        }
    }
    __syncthreads();

    const int wid  = tid >> 5;
    const int lane = tid & 31;
    const int warp_m = wid >> 1;       // 0..3 -> 32 rows
    const int warp_n = wid & 1;        // 0..1 -> 64 cols (j or d)
    const int frag_row = lane & 15;
    const int frag_ch  = lane >> 4;
    const int erow = lane >> 2;
    const int equad = lane & 3;

    // ---- QK^T via HMMA ------------------------------------------------------
    float acc[2][8][4];
    #pragma unroll
    for (int a = 0; a < 2; ++a)
        #pragma unroll
        for (int b = 0; b < 8; ++b)
            #pragma unroll
            for (int c = 0; c < 4; ++c) acc[a][b][c] = 0.f;

    #pragma unroll
    for (int kk = 0; kk < 4; ++kk) {
        uint32_t ah[2][4];
        #pragma unroll
        for (int mi = 0; mi < 2; ++mi) {
            int row = warp_m * 32 + mi * 16 + frag_row;
            int ch  = kk * 2 + frag_ch;
            ldsm4(ah[mi], sb + AQ_OFF + row * 128 + (((ch ^ (row & 7)) << 4)));
        }
        uint32_t bh[4][4];
        #pragma unroll
        for (int ng = 0; ng < 4; ++ng) {
            int row = warp_n * 64 + ng * 16 + frag_row;
            int ch  = kk * 2 + frag_ch;
            ldsm4(bh[ng], sb + AK_OFF + row * 128 + (((ch ^ (row & 7)) << 4)));
        }
        #pragma unroll
        for (int mi = 0; mi < 2; ++mi)
            #pragma unroll
            for (int ng = 0; ng < 4; ++ng) {
                mma16816(acc[mi][ng * 2],     ah[mi], bh[ng][0], bh[ng][2]);
                mma16816(acc[mi][ng * 2 + 1], ah[mi], bh[ng][1], bh[ng][3]);
            }
    }

    // ---- softmax on fragments (fp32), cross-warp-pair via smem --------------
    #pragma unroll
    for (int mi = 0; mi < 2; ++mi)
        #pragma unroll
        for (int hh = 0; hh < 2; ++hh) {
            float m = -1e30f;
            #pragma unroll
            for (int ni = 0; ni < 8; ++ni) {
                m = fmaxf(m, acc[mi][ni][hh * 2]);
                m = fmaxf(m, acc[mi][ni][hh * 2 + 1]);
            }
            m = fmaxf(m, __shfl_xor_sync(0xffffffffu, m, 1));
            m = fmaxf(m, __shfl_xor_sync(0xffffffffu, m, 2));
            if (equad == 0) {
                int row = warp_m * 32 + mi * 16 + hh * 8 + erow;
                mxb[row * 2 + warp_n] = m;
            }
        }
    __syncthreads();

    #pragma unroll
    for (int mi = 0; mi < 2; ++mi)
        #pragma unroll
        for (int hh = 0; hh < 2; ++hh) {
            int row = warp_m * 32 + mi * 16 + hh * 8 + erow;
            float m = fmaxf(mxb[row * 2], mxb[row * 2 + 1]);
            float s = 0.f;
            #pragma unroll
            for (int ni = 0; ni < 8; ++ni) {
                float e0 = __expf(acc[mi][ni][hh * 2]     - m);
                float e1 = __expf(acc[mi][ni][hh * 2 + 1] - m);
                acc[mi][ni][hh * 2]     = e0;
                acc[mi][ni][hh * 2 + 1] = e1;
                s += e0 + e1;
            }
            s += __shfl_xor_sync(0xffffffffu, s, 1);
            s += __shfl_xor_sync(0xffffffffu, s, 2);
            if (equad == 0)
                smb[row * 2 + warp_n] = s;
        }
    __syncthreads();

    // ---- scale, write attn (fp32) + P (fp16 smem) ---------------------------
    const size_t abase = (size_t)bwh * WIN * WIN;
    #pragma unroll
    for (int mi = 0; mi < 2; ++mi)
        #pragma unroll
        for (int hh = 0; hh < 2; ++hh) {
            int row = warp_m * 32 + mi * 16 + hh * 8 + erow;
            float inv = 1.0f / (smb[row * 2] + smb[row * 2 + 1]);
            #pragma unroll
            for (int ni = 0; ni < 8; ++ni) {
                float p0 = acc[mi][ni][hh * 2]     * inv;
                float p1 = acc[mi][ni][hh * 2 + 1] * inv;
                int col = warp_n * 64 + ni * 8 + equad * 2;
                *(float2*)(attn_out + abase + (size_t)row * WIN + col) =
                    make_float2(p0, p1);
                uint32_t off = row * TSTRIDE +
                               (((col >> 3) ^ (row & 7)) << 4) + (col & 7) * 2;
                *(__half2*)(asm_ + AP_OFF + off) = __floats2half2_rn(p0, p1);
            }
        }
    __syncthreads();

    // ---- P @ V via HMMA ------------------------------------------------------
    float oac[2][4][4];
    #pragma unroll
    for (int a = 0; a < 2; ++a)
        #pragma unroll
        for (int b = 0; b < 4; ++b)
            #pragma unroll
            for (int c = 0; c < 4; ++c) oac[a][b][c] = 0.f;

    #pragma unroll
    for (int kk = 0; kk < 8; ++kk) {
        uint32_t ap[2][4];
        #pragma unroll
        for (int mi = 0; mi < 2; ++mi) {
            int row = warp_m * 32 + mi * 16 + frag_row;
            int ch  = kk * 2 + frag_ch;
            ldsm4(ap[mi], sb + AP_OFF + row * TSTRIDE +
                           (((ch ^ (row & 7)) << 4)));
        }
        uint32_t bv[2][4];
        #pragma unroll
        for (int ng = 0; ng < 2; ++ng) {
            int d  = warp_n * 32 + ng * 16 + frag_row;
            int ch = kk * 2 + frag_ch;
            ldsm4(bv[ng], sb + AVT_OFF + d * TSTRIDE +
                           (((ch ^ (d & 7)) << 4)));
        }
        #pragma unroll
        for (int mi = 0; mi < 2; ++mi)
            #pragma unroll
            for (int ng = 0; ng < 2; ++ng) {
                mma16816(oac[mi][ng * 2],     ap[mi], bv[ng][0], bv[ng][2]);
                mma16816(oac[mi][ng * 2 + 1], ap[mi], bv[ng][1], bv[ng][3]);
            }
    }

    // ---- write o (fp16) -----------------------------------------------------
    #pragma unroll
    for (int mi = 0; mi < 2; ++mi)
        #pragma unroll
        for (int ni = 0; ni < 4; ++ni) {
            int r0 = warp_m * 32 + mi * 16 + erow;
            int c  = coloff + warp_n * 32 + ni * 8 + equad * 2;
            size_t go0 = (rowbase + r0) * DIMW + c;
            size_t go1 = (rowbase + r0 + 8) * DIMW + c;
            *(__half2*)(g_oh + go0) = __floats2half2_rn(oac[mi][ni][0], oac[mi][ni][1]);
            *(__half2*)(g_oh + go1) = __floats2half2_rn(oac[mi][ni][2], oac[mi][ni][3]);
        }
}

// ---------------- launcher ---------------------------------------------------
extern "C" void kernel_launch(void* const* d_in, const int* in_sizes, int n_in,
                              void* d_out, int out_size)
{
    const float* x  = (const float*)d_in[0];
    const float* y  = (const float*)d_in[1];
    const float* Wq = (const float*)d_in[2];
    const float* gq = (const float*)d_in[3];
    const float* bq = (const float*)d_in[4];
    const float* Wk = (const float*)d_in[5];
    const float* gk = (const float*)d_in[6];
    const float* bk = (const float*)d_in[7];
    const float* Wv = (const float*)d_in[8];
    const float* Wo = (const float*)d_in[9];
    const float* bo = (const float*)d_in[10];

    float* ynew = (float*)d_out;
    float* attn = ynew + (size_t)M_TOT * DIMW;

    void *p_xh, *p_yh;
    void *p_wq, *p_wk, *p_wv, *p_wo;
    cudaGetSymbolAddress(&p_xh, g_xh);  cudaGetSymbolAddress(&p_yh, g_yh);
    cudaGetSymbolAddress(&p_wq, g_Wq);  cudaGetSymbolAddress(&p_wk, g_Wk);
    cudaGetSymbolAddress(&p_wv, g_Wv);  cudaGetSymbolAddress(&p_wo, g_Wo);

    cudaFuncSetAttribute(attn_kernel,
                         cudaFuncAttributeMaxDynamicSharedMemorySize, ATTN_SMEM);
    cudaFuncSetAttribute(qkv_gemm,
                         cudaFuncAttributeMaxDynamicSharedMemorySize, GEMM_SMEM);
    cudaFuncSetAttribute(out_gemm,
                         cudaFuncAttributeMaxDynamicSharedMemorySize, GEMM_SMEM);

    // 1) convert activations and weights to fp16
    const int n4_act = (M_TOT * DIMW) / 4;
    const int n4_w   = (DIMW * DIMW) / 4;
    cvt_kernel<<<dim3((n4_act + 255) / 256, 2), 256>>>(
        (const float4*)x, (const float4*)y, (uint2*)p_xh, (uint2*)p_yh, n4_act);
    wconv_kernel<<<dim3((n4_w + 255) / 256, 4), 256>>>(
        (const float4*)Wq, (const float4*)Wk, (const float4*)Wv, (const float4*)Wo,
        (uint2*)p_wq, (uint2*)p_wk, (uint2*)p_wv, (uint2*)p_wo, n4_w);

    // 2) q/k/v projections (warp-MMA fp16; q,k,v all written fp16)
    qkv_gemm<<<dim3(DIMW / BN, M_TOT / BM, 3), 256, GEMM_SMEM>>>();

    // 3) LN row stats for q, k (fp16 input)
    stats_kernel<<<dim3(M_TOT / 8, 2), 256>>>();

    // 4) tensor-core windowed attention -> attn (fp32) + fp16 o
    attn_kernel<<<4096, 256, ATTN_SMEM>>>(attn, gq, bq, gk, bk);

    // 5) final projection with residual epilogue
    out_gemm<<<dim3(DIMW / BN, M_TOT / BM), 256, GEMM_SMEM>>>(y, bo, ynew);
}